// round 1
// baseline (speedup 1.0000x reference)
#include <cuda_runtime.h>
#include <math.h>

#define BB 4
#define TT 2048
#define HH 16
#define DD 64
#define CC (HH*DD)      // 1024
#define MM (BB*TT)      // 8192

// ---------------- scratch (device globals; no allocation allowed) ----------
__device__ float g_q[(size_t)MM * CC];        // 32 MB
__device__ float g_kv[(size_t)MM * 2 * CC];   // 64 MB
__device__ float g_y[(size_t)MM * CC];        // 32 MB
__device__ float g_cos[TT * 32];
__device__ float g_sin[TT * 32];

// ---------------- SGEMM: C[M,N] = A[M,K] @ B[K,N], 128x128x8 tiles --------
__global__ void __launch_bounds__(256)
sgemm_kernel(const float* __restrict__ A, const float* __restrict__ Bm,
             float* __restrict__ Cm, int Mdim, int Ndim, int Kdim)
{
    __shared__ float As[8][128];
    __shared__ float Bs[8][128];

    const int tid = threadIdx.x;
    const int tx  = tid & 15;        // 0..15 -> 8 cols each
    const int ty  = tid >> 4;        // 0..15 -> 8 rows each
    const int rowBase = blockIdx.y * 128;
    const int colBase = blockIdx.x * 128;

    const int aRow = tid >> 1;           // 0..127
    const int aCol = (tid & 1) << 2;     // 0 or 4
    const int bRow = tid >> 5;           // 0..7
    const int bCol = (tid & 31) << 2;    // 0..124

    float acc[8][8];
    #pragma unroll
    for (int i = 0; i < 8; i++)
        #pragma unroll
        for (int j = 0; j < 8; j++) acc[i][j] = 0.f;

    const float* Ap = A + (size_t)rowBase * Kdim;
    const float* Bp = Bm + colBase;

    for (int k0 = 0; k0 < Kdim; k0 += 8) {
        float4 av = *reinterpret_cast<const float4*>(Ap + (size_t)aRow * Kdim + k0 + aCol);
        As[aCol + 0][aRow] = av.x;
        As[aCol + 1][aRow] = av.y;
        As[aCol + 2][aRow] = av.z;
        As[aCol + 3][aRow] = av.w;
        *reinterpret_cast<float4*>(&Bs[bRow][bCol]) =
            *reinterpret_cast<const float4*>(Bp + (size_t)(k0 + bRow) * Ndim + bCol);
        __syncthreads();

        #pragma unroll
        for (int kk = 0; kk < 8; kk++) {
            float ra[8], rb[8];
            #pragma unroll
            for (int i = 0; i < 8; i++) ra[i] = As[kk][ty * 8 + i];
            #pragma unroll
            for (int j = 0; j < 8; j++) rb[j] = Bs[kk][tx * 8 + j];
            #pragma unroll
            for (int i = 0; i < 8; i++)
                #pragma unroll
                for (int j = 0; j < 8; j++)
                    acc[i][j] += ra[i] * rb[j];
        }
        __syncthreads();
    }

    #pragma unroll
    for (int i = 0; i < 8; i++) {
        float* crow = Cm + (size_t)(rowBase + ty * 8 + i) * Ndim + colBase + tx * 8;
        float4 v0 = make_float4(acc[i][0], acc[i][1], acc[i][2], acc[i][3]);
        float4 v1 = make_float4(acc[i][4], acc[i][5], acc[i][6], acc[i][7]);
        *reinterpret_cast<float4*>(crow + 0) = v0;
        *reinterpret_cast<float4*>(crow + 4) = v1;
    }
}

// ---------------- RoPE table: double-accurate inv_freq, fp32 angle --------
__global__ void rope_table_kernel(float* __restrict__ gcos, float* __restrict__ gsin)
{
    int i = blockIdx.x * blockDim.x + threadIdx.x;
    if (i >= TT * 32) return;
    int t = i >> 5;
    int d = i & 31;
    // inv_freq = 10000^(-2d/64); compute in double, round to fp32 (matches jnp fp32 pow)
    float inv = (float)exp(-((double)(2 * d) / 64.0) * log(10000.0));
    float ang = (float)t * inv;   // fp32 multiply, same as reference einsum
    gcos[i] = cosf(ang);
    gsin[i] = sinf(ang);
}

// ---------------- RoPE apply (in-place on q and k-half of kv) -------------
__global__ void rope_kernel(float* __restrict__ q, float* __restrict__ kv,
                            const float* __restrict__ gcos, const float* __restrict__ gsin)
{
    int idx = blockIdx.x * blockDim.x + threadIdx.x;   // over B*T*H*32
    int d = idx & 31;
    int h = (idx >> 5) & 15;
    int t = (idx >> 9) & (TT - 1);
    int b = idx >> 20;

    float c = gcos[(t << 5) + d];
    float s = gsin[(t << 5) + d];

    size_t qoff = ((size_t)(b * TT + t)) * CC + h * DD;
    float x1 = q[qoff + d], x2 = q[qoff + d + 32];
    q[qoff + d]      = x1 * c - x2 * s;
    q[qoff + d + 32] = x2 * c + x1 * s;

    size_t koff = ((size_t)(b * TT + t)) * (2 * CC) + h * DD;
    float k1 = kv[koff + d], k2 = kv[koff + d + 32];
    kv[koff + d]      = k1 * c - k2 * s;
    kv[koff + d + 32] = k2 * c + k1 * s;
}

// ---------------- Flash attention (fp32, online softmax) ------------------
// Block: 256 threads = 8 warps; 64 q-rows per block (8 rows/warp);
// KV tiles of 32 rows. Layouts: Q rows in g_q [B,T,H*D]; K at kv[.. +h*D],
// V at kv[.. + C + h*D]. Output y in [B,T,H*D].
__global__ void __launch_bounds__(256)
flash_kernel(const float* __restrict__ qg, const float* __restrict__ kvg,
             float* __restrict__ yg)
{
    __shared__ float Qs[64][64];
    __shared__ float Ks[32][68];   // pad 4: 16B-aligned rows, conflict-free LDS.128
    __shared__ float Vs[32][68];

    const int tid  = threadIdx.x;
    const int lane = tid & 31;
    const int warp = tid >> 5;
    const int h  = blockIdx.y;
    const int b  = blockIdx.z;
    const int t0 = blockIdx.x * 64;
    const float scale = 0.125f;   // 1/sqrt(64)

    // Load Q tile: 64 rows x 16 float4 = 1024 float4, 4 per thread
    #pragma unroll
    for (int i = 0; i < 4; i++) {
        int idx = tid + i * 256;
        int r  = idx >> 4;
        int c4 = (idx & 15) << 2;
        const float* src = qg + ((size_t)(b * TT + t0 + r)) * CC + h * DD + c4;
        *reinterpret_cast<float4*>(&Qs[r][c4]) = *reinterpret_cast<const float4*>(src);
    }

    float m[8], l[8], o0[8], o1[8];
    #pragma unroll
    for (int r = 0; r < 8; r++) { m[r] = -1e30f; l[r] = 0.f; o0[r] = 0.f; o1[r] = 0.f; }

    const int r0 = warp * 8;
    const int qimax = t0 + r0 + 7;

    for (int j0 = 0; j0 < t0 + 64; j0 += 32) {
        __syncthreads();   // protect Qs (first iter) / Ks,Vs reuse (later iters)
        #pragma unroll
        for (int i = 0; i < 2; i++) {
            int idx = tid + i * 256;
            int r  = idx >> 4;
            int c4 = (idx & 15) << 2;
            size_t base = ((size_t)(b * TT + j0 + r)) * (2 * CC) + h * DD + c4;
            *reinterpret_cast<float4*>(&Ks[r][c4]) = *reinterpret_cast<const float4*>(kvg + base);
            *reinterpret_cast<float4*>(&Vs[r][c4]) = *reinterpret_cast<const float4*>(kvg + base + CC);
        }
        __syncthreads();

        if (j0 > qimax) continue;   // uniform per warp

        // S = Q K^T for this warp's 8 rows; lane owns one K column
        float s[8] = {0.f, 0.f, 0.f, 0.f, 0.f, 0.f, 0.f, 0.f};
        #pragma unroll
        for (int d4 = 0; d4 < 64; d4 += 4) {
            float4 kd = *reinterpret_cast<const float4*>(&Ks[lane][d4]);
            #pragma unroll
            for (int r = 0; r < 8; r++) {
                float4 qd = *reinterpret_cast<const float4*>(&Qs[r0 + r][d4]);
                s[r] += qd.x * kd.x;
                s[r] += qd.y * kd.y;
                s[r] += qd.z * kd.z;
                s[r] += qd.w * kd.w;
            }
        }

        const int kj = j0 + lane;
        const bool interior = (j0 + 31) <= (t0 + r0);   // no masking needed
        float p[8];
        #pragma unroll
        for (int r = 0; r < 8; r++) {
            float sv = s[r] * scale;
            if (!interior && kj > t0 + r0 + r) sv = -1e30f;
            float mt = sv;
            #pragma unroll
            for (int off = 16; off > 0; off >>= 1)
                mt = fmaxf(mt, __shfl_xor_sync(0xffffffffu, mt, off));
            float mnew  = fmaxf(m[r], mt);
            float alpha = __expf(m[r] - mnew);
            float pv    = __expf(sv - mnew);
            float ps = pv;
            #pragma unroll
            for (int off = 16; off > 0; off >>= 1)
                ps += __shfl_xor_sync(0xffffffffu, ps, off);
            l[r]  = l[r] * alpha + ps;
            m[r]  = mnew;
            o0[r] *= alpha;
            o1[r] *= alpha;
            p[r]  = pv;
        }

        // O += P @ V  (lane owns output dims lane and lane+32)
        #pragma unroll
        for (int j = 0; j < 32; j++) {
            float v0 = Vs[j][lane];
            float v1 = Vs[j][lane + 32];
            #pragma unroll
            for (int r = 0; r < 8; r++) {
                float pj = __shfl_sync(0xffffffffu, p[r], j);
                o0[r] += pj * v0;
                o1[r] += pj * v1;
            }
        }
    }

    #pragma unroll
    for (int r = 0; r < 8; r++) {
        float inv = 1.0f / l[r];
        size_t base = ((size_t)(b * TT + t0 + r0 + r)) * CC + h * DD;
        yg[base + lane]      = o0[r] * inv;
        yg[base + lane + 32] = o1[r] * inv;
    }
}

// ---------------- launch ---------------------------------------------------
extern "C" void kernel_launch(void* const* d_in, const int* in_sizes, int n_in,
                              void* d_out, int out_size)
{
    const float* x   = (const float*)d_in[0];
    const float* Wq  = (const float*)d_in[1];
    const float* Wkv = (const float*)d_in[2];
    const float* Wc  = (const float*)d_in[3];
    float* out = (float*)d_out;

    float *q, *kv, *y, *gc, *gs;
    cudaGetSymbolAddress((void**)&q,  g_q);
    cudaGetSymbolAddress((void**)&kv, g_kv);
    cudaGetSymbolAddress((void**)&y,  g_y);
    cudaGetSymbolAddress((void**)&gc, g_cos);
    cudaGetSymbolAddress((void**)&gs, g_sin);

    rope_table_kernel<<<(TT * 32 + 255) / 256, 256>>>(gc, gs);

    // q = x @ Wq    [8192,1024] x [1024,1024]
    sgemm_kernel<<<dim3(CC / 128, MM / 128), 256>>>(x, Wq, q, MM, CC, CC);
    // kv = x @ Wkv  [8192,1024] x [1024,2048]
    sgemm_kernel<<<dim3(2 * CC / 128, MM / 128), 256>>>(x, Wkv, kv, MM, 2 * CC, CC);
    // RoPE on q and k
    rope_kernel<<<(BB * TT * HH * 32) / 256, 256>>>(q, kv, gc, gs);
    // attention
    flash_kernel<<<dim3(TT / 64, HH, BB), 256>>>(q, kv, y);
    // out = y @ Wc
    sgemm_kernel<<<dim3(CC / 128, MM / 128), 256>>>(y, Wc, out, MM, CC, CC);
}

// round 3
// speedup vs baseline: 1.4541x; 1.4541x over previous
#include <cuda_runtime.h>
#include <cuda_bf16.h>
#include <math.h>
#include <stdint.h>

#define BB 4
#define TT 2048
#define HH 16
#define DD 64
#define CC (HH*DD)      // 1024
#define MM (BB*TT)      // 8192
#define GK 1024         // K of all GEMMs

// ---------------- scratch (device globals; no allocation allowed) ----------
__device__ __align__(256) float g_q[(size_t)MM * CC];
__device__ __align__(256) float g_kv[(size_t)MM * 2 * CC];
__device__ __align__(256) float g_y[(size_t)MM * CC];
__device__ __align__(256) float g_cos[TT * 32];
__device__ __align__(256) float g_sin[TT * 32];

// bf16 split operands
__device__ __align__(256) __nv_bfloat16 g_xh[(size_t)MM * GK];
__device__ __align__(256) __nv_bfloat16 g_xl[(size_t)MM * GK];
__device__ __align__(256) __nv_bfloat16 g_yh[(size_t)MM * GK];
__device__ __align__(256) __nv_bfloat16 g_yl[(size_t)MM * GK];
// transposed weights [N, K]
__device__ __align__(256) __nv_bfloat16 g_wqh[(size_t)CC * GK];
__device__ __align__(256) __nv_bfloat16 g_wql[(size_t)CC * GK];
__device__ __align__(256) __nv_bfloat16 g_wkvh[(size_t)2 * CC * GK];
__device__ __align__(256) __nv_bfloat16 g_wkvl[(size_t)2 * CC * GK];
__device__ __align__(256) __nv_bfloat16 g_wch[(size_t)CC * GK];
__device__ __align__(256) __nv_bfloat16 g_wcl[(size_t)CC * GK];

// ---------------- helpers ----------------------------------------------------
__device__ __forceinline__ uint32_t smem_u32(const void* p) {
    return (uint32_t)__cvta_generic_to_shared(p);
}

__device__ __forceinline__ void cp_async16(uint32_t saddr, const void* gaddr) {
    asm volatile("cp.async.cg.shared.global [%0], [%1], 16;" :: "r"(saddr), "l"(gaddr) : "memory");
}

__device__ __forceinline__ void ldsm_x4(uint32_t& r0, uint32_t& r1, uint32_t& r2, uint32_t& r3,
                                        uint32_t addr) {
    asm volatile("ldmatrix.sync.aligned.m8n8.x4.shared.b16 {%0,%1,%2,%3}, [%4];"
                 : "=r"(r0), "=r"(r1), "=r"(r2), "=r"(r3) : "r"(addr));
}

__device__ __forceinline__ void mma16816(float& c0, float& c1, float& c2, float& c3,
                                         uint32_t a0, uint32_t a1, uint32_t a2, uint32_t a3,
                                         uint32_t b0, uint32_t b1) {
    asm volatile(
        "mma.sync.aligned.m16n8k16.row.col.f32.bf16.bf16.f32 "
        "{%0,%1,%2,%3}, {%4,%5,%6,%7}, {%8,%9}, {%0,%1,%2,%3};"
        : "+f"(c0), "+f"(c1), "+f"(c2), "+f"(c3)
        : "r"(a0), "r"(a1), "r"(a2), "r"(a3), "r"(b0), "r"(b1));
}

// ---------------- HMMA GEMM: C[M,Ndim] = (Ah+Al) @ (Bh+Bl)^T ---------------
// A*: [M,K] bf16 row-major; B*: [Ndim,K] bf16 row-major (pre-transposed W).
// CTA tile 128x128, K-chunk 32, 3-stage cp.async pipeline, 8 warps (2Mx4N),
// warp tile 64x32. smem rows padded to 80B -> conflict-free ldmatrix.
#define BK 32
#define NUMK (GK / BK)          // 32
#define ROWB 80                 // 64B data + 16B pad
#define TILE_B (128 * ROWB)     // 10240
#define STAGE_B (4 * TILE_B)    // 40960
#define NSTAGE 3
#define SMEM_DYN (NSTAGE * STAGE_B)   // 122880

__global__ void __launch_bounds__(256, 1)
gemm_kernel_mma(const __nv_bfloat16* __restrict__ Ah, const __nv_bfloat16* __restrict__ Al,
                const __nv_bfloat16* __restrict__ Bh, const __nv_bfloat16* __restrict__ Bl,
                float* __restrict__ Cm, int Ndim)
{
    extern __shared__ char smem_raw[];
    const uint32_t sbase = smem_u32(smem_raw);

    const int tid  = threadIdx.x;
    const int lane = tid & 31;
    const int warp = tid >> 5;
    const int mw   = warp & 1;        // 0..1 -> 64 rows each
    const int nw   = warp >> 1;       // 0..3 -> 32 cols each
    const int m0 = blockIdx.y * 128;
    const int n0 = blockIdx.x * 128;

    // cp.async plan: 8 chunks of 16B per thread per stage
    const __nv_bfloat16* tp[4] = { Ah, Al, Bh, Bl };

    auto prefetch = [&](int kc) {
        const uint32_t sstage = sbase + (uint32_t)(kc % NSTAGE) * STAGE_B;
        #pragma unroll
        for (int i = 0; i < 8; i++) {
            const int c = i * 256 + tid;
            const int tile = c >> 9;            // 0..3
            const int r = (c >> 2) & 127;
            const int j = c & 3;
            const int row0 = (tile < 2) ? m0 : n0;
            const __nv_bfloat16* g = tp[tile] + (size_t)(row0 + r) * GK + kc * BK + j * 8;
            cp_async16(sstage + tile * TILE_B + r * ROWB + j * 16, g);
        }
    };

    prefetch(0);
    asm volatile("cp.async.commit_group;" ::: "memory");
    prefetch(1);
    asm volatile("cp.async.commit_group;" ::: "memory");

    // lane-dependent ldmatrix base offsets (within a tile)
    // A: rows mw*64 + mt*16 + (lane&15); k-byte = (lane>>4)*16 + ks*32
    const uint32_t aBase = (uint32_t)((mw * 64 + (lane & 15)) * ROWB + ((lane >> 4) << 4));
    // B: rows nw*32 + np*16 + (lane&7) + ((lane>>4)<<3); k-byte = ((lane>>3)&1)*16 + ks*32
    const uint32_t bBase = (uint32_t)((nw * 32 + (lane & 7) + ((lane >> 4) << 3)) * ROWB
                                      + (((lane >> 3) & 1) << 4));

    float acc[4][4][4];
    #pragma unroll
    for (int mt = 0; mt < 4; mt++)
        #pragma unroll
        for (int nt = 0; nt < 4; nt++)
            #pragma unroll
            for (int e = 0; e < 4; e++) acc[mt][nt][e] = 0.f;

    for (int kc = 0; kc < NUMK; kc++) {
        asm volatile("cp.async.wait_group 1;" ::: "memory");
        __syncthreads();

        if (kc + 2 < NUMK) prefetch(kc + 2);
        asm volatile("cp.async.commit_group;" ::: "memory");

        const uint32_t sstage = sbase + (uint32_t)(kc % NSTAGE) * STAGE_B;
        const uint32_t aTile = sstage;                 // Ah
        const uint32_t bTile = sstage + 2 * TILE_B;    // Bh

        #pragma unroll
        for (int ks = 0; ks < 2; ks++) {
            const uint32_t kb = ks * 32;
            // load A fragments (hi, lo) for 4 m-tiles
            uint32_t ah[4][4], al[4][4];
            #pragma unroll
            for (int mt = 0; mt < 4; mt++) {
                const uint32_t off = aBase + mt * (16 * ROWB) + kb;
                ldsm_x4(ah[mt][0], ah[mt][1], ah[mt][2], ah[mt][3], aTile + off);
                ldsm_x4(al[mt][0], al[mt][1], al[mt][2], al[mt][3], aTile + TILE_B + off);
            }
            // load B fragments (hi, lo): x4 covers 2 n-tiles
            uint32_t bh[4][2], bl[4][2];
            #pragma unroll
            for (int np = 0; np < 2; np++) {
                const uint32_t off = bBase + np * (16 * ROWB) + kb;
                ldsm_x4(bh[np*2][0], bh[np*2][1], bh[np*2+1][0], bh[np*2+1][1], bTile + off);
                ldsm_x4(bl[np*2][0], bl[np*2][1], bl[np*2+1][0], bl[np*2+1][1],
                        bTile + TILE_B + off);
            }
            #pragma unroll
            for (int mt = 0; mt < 4; mt++) {
                #pragma unroll
                for (int nt = 0; nt < 4; nt++) {
                    float* c = acc[mt][nt];
                    mma16816(c[0], c[1], c[2], c[3],
                             ah[mt][0], ah[mt][1], ah[mt][2], ah[mt][3],
                             bh[nt][0], bh[nt][1]);
                    mma16816(c[0], c[1], c[2], c[3],
                             ah[mt][0], ah[mt][1], ah[mt][2], ah[mt][3],
                             bl[nt][0], bl[nt][1]);
                    mma16816(c[0], c[1], c[2], c[3],
                             al[mt][0], al[mt][1], al[mt][2], al[mt][3],
                             bh[nt][0], bh[nt][1]);
                }
            }
        }
        __syncthreads();
    }

    // epilogue: lane l of m16n8 tile holds rows l/4, l/4+8; cols (l%4)*2, +1
    const int rbase = m0 + mw * 64 + (lane >> 2);
    const int cbase = n0 + nw * 32 + ((lane & 3) << 1);
    #pragma unroll
    for (int mt = 0; mt < 4; mt++) {
        #pragma unroll
        for (int nt = 0; nt < 4; nt++) {
            float* c = acc[mt][nt];
            float* p0 = Cm + (size_t)(rbase + mt * 16) * Ndim + cbase + nt * 8;
            float* p1 = p0 + (size_t)8 * Ndim;
            *reinterpret_cast<float2*>(p0) = make_float2(c[0], c[1]);
            *reinterpret_cast<float2*>(p1) = make_float2(c[2], c[3]);
        }
    }
}

// ---------------- fp32 -> bf16 hi/lo split ---------------------------------
__global__ void split_kernel(const float4* __restrict__ in,
                             uint2* __restrict__ hi, uint2* __restrict__ lo, int n4)
{
    int i = blockIdx.x * blockDim.x + threadIdx.x;
    if (i >= n4) return;
    float4 v = in[i];
    float vv[4] = { v.x, v.y, v.z, v.w };
    unsigned short h[4], l[4];
    #pragma unroll
    for (int k = 0; k < 4; k++) {
        __nv_bfloat16 hb = __float2bfloat16(vv[k]);
        __nv_bfloat16 lb = __float2bfloat16(vv[k] - __bfloat162float(hb));
        h[k] = __bfloat16_as_ushort(hb);
        l[k] = __bfloat16_as_ushort(lb);
    }
    uint2 ho, lo_;
    ho.x = (uint32_t)h[0] | ((uint32_t)h[1] << 16);
    ho.y = (uint32_t)h[2] | ((uint32_t)h[3] << 16);
    lo_.x = (uint32_t)l[0] | ((uint32_t)l[1] << 16);
    lo_.y = (uint32_t)l[2] | ((uint32_t)l[3] << 16);
    hi[i] = ho;
    lo[i] = lo_;
}

// ---------------- W[K,N] -> Wt[N,K] bf16 hi/lo transpose-split -------------
__global__ void transpose_split_kernel(const float* __restrict__ W,
                                       __nv_bfloat16* __restrict__ Th,
                                       __nv_bfloat16* __restrict__ Tl, int N)
{
    __shared__ float t[32][33];
    const int n0 = blockIdx.x * 32, k0 = blockIdx.y * 32;
    const int tx = threadIdx.x, ty = threadIdx.y;   // 32 x 8
    #pragma unroll
    for (int i = 0; i < 32; i += 8)
        t[ty + i][tx] = W[(size_t)(k0 + ty + i) * N + n0 + tx];
    __syncthreads();
    #pragma unroll
    for (int i = 0; i < 32; i += 8) {
        float v = t[tx][ty + i];
        __nv_bfloat16 hb = __float2bfloat16(v);
        size_t o = (size_t)(n0 + ty + i) * GK + k0 + tx;
        Th[o] = hb;
        Tl[o] = __float2bfloat16(v - __bfloat162float(hb));
    }
}

// ---------------- RoPE table: double-accurate inv_freq, fp32 angle --------
__global__ void rope_table_kernel(float* __restrict__ gcos, float* __restrict__ gsin)
{
    int i = blockIdx.x * blockDim.x + threadIdx.x;
    if (i >= TT * 32) return;
    int t = i >> 5;
    int d = i & 31;
    float inv = (float)exp(-((double)(2 * d) / 64.0) * log(10000.0));
    float ang = (float)t * inv;
    gcos[i] = cosf(ang);
    gsin[i] = sinf(ang);
}

// ---------------- RoPE apply (in-place on q and k-half of kv) -------------
__global__ void rope_kernel(float* __restrict__ q, float* __restrict__ kv,
                            const float* __restrict__ gcos, const float* __restrict__ gsin)
{
    int idx = blockIdx.x * blockDim.x + threadIdx.x;   // over B*T*H*32
    int d = idx & 31;
    int h = (idx >> 5) & 15;
    int t = (idx >> 9) & (TT - 1);
    int b = idx >> 20;

    float c = gcos[(t << 5) + d];
    float s = gsin[(t << 5) + d];

    size_t qoff = ((size_t)(b * TT + t)) * CC + h * DD;
    float x1 = q[qoff + d], x2 = q[qoff + d + 32];
    q[qoff + d]      = x1 * c - x2 * s;
    q[qoff + d + 32] = x2 * c + x1 * s;

    size_t koff = ((size_t)(b * TT + t)) * (2 * CC) + h * DD;
    float k1 = kv[koff + d], k2 = kv[koff + d + 32];
    kv[koff + d]      = k1 * c - k2 * s;
    kv[koff + d + 32] = k2 * c + k1 * s;
}

// ---------------- Flash attention (fp32, online softmax) ------------------
__global__ void __launch_bounds__(256)
flash_kernel(const float* __restrict__ qg, const float* __restrict__ kvg,
             float* __restrict__ yg)
{
    __shared__ float Qs[64][64];
    __shared__ float Ks[32][68];
    __shared__ float Vs[32][68];

    const int tid  = threadIdx.x;
    const int lane = tid & 31;
    const int warp = tid >> 5;
    const int h  = blockIdx.y;
    const int b  = blockIdx.z;
    const int t0 = blockIdx.x * 64;
    const float scale = 0.125f;

    #pragma unroll
    for (int i = 0; i < 4; i++) {
        int idx = tid + i * 256;
        int r  = idx >> 4;
        int c4 = (idx & 15) << 2;
        const float* src = qg + ((size_t)(b * TT + t0 + r)) * CC + h * DD + c4;
        *reinterpret_cast<float4*>(&Qs[r][c4]) = *reinterpret_cast<const float4*>(src);
    }

    float m[8], l[8], o0[8], o1[8];
    #pragma unroll
    for (int r = 0; r < 8; r++) { m[r] = -1e30f; l[r] = 0.f; o0[r] = 0.f; o1[r] = 0.f; }

    const int r0 = warp * 8;
    const int qimax = t0 + r0 + 7;

    for (int j0 = 0; j0 < t0 + 64; j0 += 32) {
        __syncthreads();
        #pragma unroll
        for (int i = 0; i < 2; i++) {
            int idx = tid + i * 256;
            int r  = idx >> 4;
            int c4 = (idx & 15) << 2;
            size_t base = ((size_t)(b * TT + j0 + r)) * (2 * CC) + h * DD + c4;
            *reinterpret_cast<float4*>(&Ks[r][c4]) = *reinterpret_cast<const float4*>(kvg + base);
            *reinterpret_cast<float4*>(&Vs[r][c4]) = *reinterpret_cast<const float4*>(kvg + base + CC);
        }
        __syncthreads();

        if (j0 > qimax) continue;

        float s[8] = {0.f, 0.f, 0.f, 0.f, 0.f, 0.f, 0.f, 0.f};
        #pragma unroll
        for (int d4 = 0; d4 < 64; d4 += 4) {
            float4 kd = *reinterpret_cast<const float4*>(&Ks[lane][d4]);
            #pragma unroll
            for (int r = 0; r < 8; r++) {
                float4 qd = *reinterpret_cast<const float4*>(&Qs[r0 + r][d4]);
                s[r] += qd.x * kd.x;
                s[r] += qd.y * kd.y;
                s[r] += qd.z * kd.z;
                s[r] += qd.w * kd.w;
            }
        }

        const int kj = j0 + lane;
        const bool interior = (j0 + 31) <= (t0 + r0);
        float p[8];
        #pragma unroll
        for (int r = 0; r < 8; r++) {
            float sv = s[r] * scale;
            if (!interior && kj > t0 + r0 + r) sv = -1e30f;
            float mt = sv;
            #pragma unroll
            for (int off = 16; off > 0; off >>= 1)
                mt = fmaxf(mt, __shfl_xor_sync(0xffffffffu, mt, off));
            float mnew  = fmaxf(m[r], mt);
            float alpha = __expf(m[r] - mnew);
            float pv    = __expf(sv - mnew);
            float ps = pv;
            #pragma unroll
            for (int off = 16; off > 0; off >>= 1)
                ps += __shfl_xor_sync(0xffffffffu, ps, off);
            l[r]  = l[r] * alpha + ps;
            m[r]  = mnew;
            o0[r] *= alpha;
            o1[r] *= alpha;
            p[r]  = pv;
        }

        #pragma unroll
        for (int j = 0; j < 32; j++) {
            float v0 = Vs[j][lane];
            float v1 = Vs[j][lane + 32];
            #pragma unroll
            for (int r = 0; r < 8; r++) {
                float pj = __shfl_sync(0xffffffffu, p[r], j);
                o0[r] += pj * v0;
                o1[r] += pj * v1;
            }
        }
    }

    #pragma unroll
    for (int r = 0; r < 8; r++) {
        float inv = 1.0f / l[r];
        size_t base = ((size_t)(b * TT + t0 + r0 + r)) * CC + h * DD;
        yg[base + lane]      = o0[r] * inv;
        yg[base + lane + 32] = o1[r] * inv;
    }
}

// ---------------- launch ---------------------------------------------------
extern "C" void kernel_launch(void* const* d_in, const int* in_sizes, int n_in,
                              void* d_out, int out_size)
{
    const float* x   = (const float*)d_in[0];
    const float* Wq  = (const float*)d_in[1];
    const float* Wkv = (const float*)d_in[2];
    const float* Wc  = (const float*)d_in[3];
    float* out = (float*)d_out;

    float *q, *kv, *y, *gc, *gs;
    __nv_bfloat16 *xh, *xl, *yh, *yl, *wqh, *wql, *wkvh, *wkvl, *wch, *wcl;
    cudaGetSymbolAddress((void**)&q,  g_q);
    cudaGetSymbolAddress((void**)&kv, g_kv);
    cudaGetSymbolAddress((void**)&y,  g_y);
    cudaGetSymbolAddress((void**)&gc, g_cos);
    cudaGetSymbolAddress((void**)&gs, g_sin);
    cudaGetSymbolAddress((void**)&xh, g_xh);
    cudaGetSymbolAddress((void**)&xl, g_xl);
    cudaGetSymbolAddress((void**)&yh, g_yh);
    cudaGetSymbolAddress((void**)&yl, g_yl);
    cudaGetSymbolAddress((void**)&wqh, g_wqh);
    cudaGetSymbolAddress((void**)&wql, g_wql);
    cudaGetSymbolAddress((void**)&wkvh, g_wkvh);
    cudaGetSymbolAddress((void**)&wkvl, g_wkvl);
    cudaGetSymbolAddress((void**)&wch, g_wch);
    cudaGetSymbolAddress((void**)&wcl, g_wcl);

    cudaFuncSetAttribute(gemm_kernel_mma, cudaFuncAttributeMaxDynamicSharedMemorySize, SMEM_DYN);

    rope_table_kernel<<<(TT * 32 + 255) / 256, 256>>>(gc, gs);

    // split x
    {
        int n4 = MM * GK / 4;
        split_kernel<<<(n4 + 255) / 256, 256>>>((const float4*)x, (uint2*)xh, (uint2*)xl, n4);
    }
    // transpose-split weights
    transpose_split_kernel<<<dim3(CC / 32, GK / 32), dim3(32, 8)>>>(Wq, wqh, wql, CC);
    transpose_split_kernel<<<dim3(2 * CC / 32, GK / 32), dim3(32, 8)>>>(Wkv, wkvh, wkvl, 2 * CC);
    transpose_split_kernel<<<dim3(CC / 32, GK / 32), dim3(32, 8)>>>(Wc, wch, wcl, CC);

    // q = x @ Wq
    gemm_kernel_mma<<<dim3(CC / 128, MM / 128), 256, SMEM_DYN>>>(xh, xl, wqh, wql, q, CC);
    // kv = x @ Wkv
    gemm_kernel_mma<<<dim3(2 * CC / 128, MM / 128), 256, SMEM_DYN>>>(xh, xl, wkvh, wkvl, kv, 2 * CC);
    // RoPE
    rope_kernel<<<(BB * TT * HH * 32) / 256, 256>>>(q, kv, gc, gs);
    // attention
    flash_kernel<<<dim3(TT / 64, HH, BB), 256>>>(q, kv, y);
    // split y, then out = y @ Wc
    {
        int n4 = MM * GK / 4;
        split_kernel<<<(n4 + 255) / 256, 256>>>((const float4*)y, (uint2*)yh, (uint2*)yl, n4);
    }
    gemm_kernel_mma<<<dim3(CC / 128, MM / 128), 256, SMEM_DYN>>>(yh, yl, wch, wcl, out, CC);
}

// round 4
// speedup vs baseline: 3.1418x; 2.1607x over previous
#include <cuda_runtime.h>
#include <cuda_bf16.h>
#include <math.h>
#include <stdint.h>

#define BB 4
#define TT 2048
#define HH 16
#define DD 64
#define CC (HH*DD)      // 1024
#define MM (BB*TT)      // 8192
#define GK 1024         // K of all GEMMs

// ---------------- scratch (device globals; no allocation allowed) ----------
__device__ __align__(256) float g_q[(size_t)MM * CC];
__device__ __align__(256) float g_kv[(size_t)MM * 2 * CC];
__device__ __align__(256) float g_cos[TT * 32];
__device__ __align__(256) float g_sin[TT * 32];

// bf16 split operands
__device__ __align__(256) __nv_bfloat16 g_xh[(size_t)MM * GK];
__device__ __align__(256) __nv_bfloat16 g_xl[(size_t)MM * GK];
__device__ __align__(256) __nv_bfloat16 g_yh[(size_t)MM * GK];
__device__ __align__(256) __nv_bfloat16 g_yl[(size_t)MM * GK];
// attention operands [B,H,T,D] (q,k) and [B,H,D,T] (v transposed)
__device__ __align__(256) __nv_bfloat16 g_qh[(size_t)BB*HH*TT*DD];
__device__ __align__(256) __nv_bfloat16 g_ql[(size_t)BB*HH*TT*DD];
__device__ __align__(256) __nv_bfloat16 g_kh[(size_t)BB*HH*TT*DD];
__device__ __align__(256) __nv_bfloat16 g_kl[(size_t)BB*HH*TT*DD];
__device__ __align__(256) __nv_bfloat16 g_vth[(size_t)BB*HH*TT*DD];
__device__ __align__(256) __nv_bfloat16 g_vtl[(size_t)BB*HH*TT*DD];
// transposed weights [N, K]
__device__ __align__(256) __nv_bfloat16 g_wqh[(size_t)CC * GK];
__device__ __align__(256) __nv_bfloat16 g_wql[(size_t)CC * GK];
__device__ __align__(256) __nv_bfloat16 g_wkvh[(size_t)2 * CC * GK];
__device__ __align__(256) __nv_bfloat16 g_wkvl[(size_t)2 * CC * GK];
__device__ __align__(256) __nv_bfloat16 g_wch[(size_t)CC * GK];
__device__ __align__(256) __nv_bfloat16 g_wcl[(size_t)CC * GK];

// ---------------- helpers ----------------------------------------------------
__device__ __forceinline__ uint32_t smem_u32(const void* p) {
    return (uint32_t)__cvta_generic_to_shared(p);
}

__device__ __forceinline__ void cp_async16(uint32_t saddr, const void* gaddr) {
    asm volatile("cp.async.cg.shared.global [%0], [%1], 16;" :: "r"(saddr), "l"(gaddr) : "memory");
}

__device__ __forceinline__ void ldsm_x4(uint32_t& r0, uint32_t& r1, uint32_t& r2, uint32_t& r3,
                                        uint32_t addr) {
    asm volatile("ldmatrix.sync.aligned.m8n8.x4.shared.b16 {%0,%1,%2,%3}, [%4];"
                 : "=r"(r0), "=r"(r1), "=r"(r2), "=r"(r3) : "r"(addr));
}

__device__ __forceinline__ void mma16816(float& c0, float& c1, float& c2, float& c3,
                                         uint32_t a0, uint32_t a1, uint32_t a2, uint32_t a3,
                                         uint32_t b0, uint32_t b1) {
    asm volatile(
        "mma.sync.aligned.m16n8k16.row.col.f32.bf16.bf16.f32 "
        "{%0,%1,%2,%3}, {%4,%5,%6,%7}, {%8,%9}, {%0,%1,%2,%3};"
        : "+f"(c0), "+f"(c1), "+f"(c2), "+f"(c3)
        : "r"(a0), "r"(a1), "r"(a2), "r"(a3), "r"(b0), "r"(b1));
}

__device__ __forceinline__ uint32_t pack_bf16(float a, float b) {
    __nv_bfloat162 t = __float22bfloat162_rn(make_float2(a, b));
    return *reinterpret_cast<uint32_t*>(&t);
}

__device__ __forceinline__ void store_hl(__nv_bfloat16* hi, __nv_bfloat16* lo,
                                         size_t off, float a, float b) {
    __nv_bfloat162 h = __float22bfloat162_rn(make_float2(a, b));
    float ra = a - __bfloat162float(h.x);
    float rb = b - __bfloat162float(h.y);
    __nv_bfloat162 l = __float22bfloat162_rn(make_float2(ra, rb));
    *reinterpret_cast<__nv_bfloat162*>(hi + off) = h;
    *reinterpret_cast<__nv_bfloat162*>(lo + off) = l;
}

// ---------------- HMMA GEMM: C[M,Ndim] = (Ah+Al) @ (Bh+Bl)^T ---------------
#define BK 32
#define NUMK (GK / BK)          // 32
#define ROWB 80                 // 64B data + 16B pad
#define TILE_B (128 * ROWB)     // 10240
#define STAGE_B (4 * TILE_B)    // 40960
#define NSTAGE 3
#define SMEM_DYN (NSTAGE * STAGE_B)   // 122880

__global__ void __launch_bounds__(256, 1)
gemm_kernel_mma(const __nv_bfloat16* __restrict__ Ah, const __nv_bfloat16* __restrict__ Al,
                const __nv_bfloat16* __restrict__ Bh, const __nv_bfloat16* __restrict__ Bl,
                float* __restrict__ Cm, int Ndim)
{
    extern __shared__ char smem_raw[];
    const uint32_t sbase = smem_u32(smem_raw);

    const int tid  = threadIdx.x;
    const int lane = tid & 31;
    const int warp = tid >> 5;
    const int mw   = warp & 1;
    const int nw   = warp >> 1;
    const int m0 = blockIdx.y * 128;
    const int n0 = blockIdx.x * 128;

    const __nv_bfloat16* tp[4] = { Ah, Al, Bh, Bl };

    auto prefetch = [&](int kc) {
        const uint32_t sstage = sbase + (uint32_t)(kc % NSTAGE) * STAGE_B;
        #pragma unroll
        for (int i = 0; i < 8; i++) {
            const int c = i * 256 + tid;
            const int tile = c >> 9;
            const int r = (c >> 2) & 127;
            const int j = c & 3;
            const int row0 = (tile < 2) ? m0 : n0;
            const __nv_bfloat16* g = tp[tile] + (size_t)(row0 + r) * GK + kc * BK + j * 8;
            cp_async16(sstage + tile * TILE_B + r * ROWB + j * 16, g);
        }
    };

    prefetch(0);
    asm volatile("cp.async.commit_group;" ::: "memory");
    prefetch(1);
    asm volatile("cp.async.commit_group;" ::: "memory");

    const uint32_t aBase = (uint32_t)((mw * 64 + (lane & 15)) * ROWB + ((lane >> 4) << 4));
    const uint32_t bBase = (uint32_t)((nw * 32 + (lane & 7) + ((lane >> 4) << 3)) * ROWB
                                      + (((lane >> 3) & 1) << 4));

    float acc[4][4][4];
    #pragma unroll
    for (int mt = 0; mt < 4; mt++)
        #pragma unroll
        for (int nt = 0; nt < 4; nt++)
            #pragma unroll
            for (int e = 0; e < 4; e++) acc[mt][nt][e] = 0.f;

    for (int kc = 0; kc < NUMK; kc++) {
        asm volatile("cp.async.wait_group 1;" ::: "memory");
        __syncthreads();

        if (kc + 2 < NUMK) prefetch(kc + 2);
        asm volatile("cp.async.commit_group;" ::: "memory");

        const uint32_t sstage = sbase + (uint32_t)(kc % NSTAGE) * STAGE_B;
        const uint32_t aTile = sstage;
        const uint32_t bTile = sstage + 2 * TILE_B;

        #pragma unroll
        for (int ks = 0; ks < 2; ks++) {
            const uint32_t kb = ks * 32;
            uint32_t ah[4][4], al[4][4];
            #pragma unroll
            for (int mt = 0; mt < 4; mt++) {
                const uint32_t off = aBase + mt * (16 * ROWB) + kb;
                ldsm_x4(ah[mt][0], ah[mt][1], ah[mt][2], ah[mt][3], aTile + off);
                ldsm_x4(al[mt][0], al[mt][1], al[mt][2], al[mt][3], aTile + TILE_B + off);
            }
            uint32_t bh[4][2], bl[4][2];
            #pragma unroll
            for (int np = 0; np < 2; np++) {
                const uint32_t off = bBase + np * (16 * ROWB) + kb;
                ldsm_x4(bh[np*2][0], bh[np*2][1], bh[np*2+1][0], bh[np*2+1][1], bTile + off);
                ldsm_x4(bl[np*2][0], bl[np*2][1], bl[np*2+1][0], bl[np*2+1][1],
                        bTile + TILE_B + off);
            }
            #pragma unroll
            for (int mt = 0; mt < 4; mt++) {
                #pragma unroll
                for (int nt = 0; nt < 4; nt++) {
                    float* c = acc[mt][nt];
                    mma16816(c[0], c[1], c[2], c[3],
                             ah[mt][0], ah[mt][1], ah[mt][2], ah[mt][3],
                             bh[nt][0], bh[nt][1]);
                    mma16816(c[0], c[1], c[2], c[3],
                             ah[mt][0], ah[mt][1], ah[mt][2], ah[mt][3],
                             bl[nt][0], bl[nt][1]);
                    mma16816(c[0], c[1], c[2], c[3],
                             al[mt][0], al[mt][1], al[mt][2], al[mt][3],
                             bh[nt][0], bh[nt][1]);
                }
            }
        }
        __syncthreads();
    }

    const int rbase = m0 + mw * 64 + (lane >> 2);
    const int cbase = n0 + nw * 32 + ((lane & 3) << 1);
    #pragma unroll
    for (int mt = 0; mt < 4; mt++) {
        #pragma unroll
        for (int nt = 0; nt < 4; nt++) {
            float* c = acc[mt][nt];
            float* p0 = Cm + (size_t)(rbase + mt * 16) * Ndim + cbase + nt * 8;
            float* p1 = p0 + (size_t)8 * Ndim;
            *reinterpret_cast<float2*>(p0) = make_float2(c[0], c[1]);
            *reinterpret_cast<float2*>(p1) = make_float2(c[2], c[3]);
        }
    }
}

// ---------------- fp32 -> bf16 hi/lo split ---------------------------------
__global__ void split_kernel(const float4* __restrict__ in,
                             uint2* __restrict__ hi, uint2* __restrict__ lo, int n4)
{
    int i = blockIdx.x * blockDim.x + threadIdx.x;
    if (i >= n4) return;
    float4 v = in[i];
    float vv[4] = { v.x, v.y, v.z, v.w };
    unsigned short h[4], l[4];
    #pragma unroll
    for (int k = 0; k < 4; k++) {
        __nv_bfloat16 hb = __float2bfloat16(vv[k]);
        __nv_bfloat16 lb = __float2bfloat16(vv[k] - __bfloat162float(hb));
        h[k] = __bfloat16_as_ushort(hb);
        l[k] = __bfloat16_as_ushort(lb);
    }
    uint2 ho, lo_;
    ho.x = (uint32_t)h[0] | ((uint32_t)h[1] << 16);
    ho.y = (uint32_t)h[2] | ((uint32_t)h[3] << 16);
    lo_.x = (uint32_t)l[0] | ((uint32_t)l[1] << 16);
    lo_.y = (uint32_t)l[2] | ((uint32_t)l[3] << 16);
    hi[i] = ho;
    lo[i] = lo_;
}

// ---------------- W[K,N] -> Wt[N,K] bf16 hi/lo transpose-split -------------
__global__ void transpose_split_kernel(const float* __restrict__ W,
                                       __nv_bfloat16* __restrict__ Th,
                                       __nv_bfloat16* __restrict__ Tl, int N)
{
    __shared__ float t[32][33];
    const int n0 = blockIdx.x * 32, k0 = blockIdx.y * 32;
    const int tx = threadIdx.x, ty = threadIdx.y;
    #pragma unroll
    for (int i = 0; i < 32; i += 8)
        t[ty + i][tx] = W[(size_t)(k0 + ty + i) * N + n0 + tx];
    __syncthreads();
    #pragma unroll
    for (int i = 0; i < 32; i += 8) {
        float v = t[tx][ty + i];
        __nv_bfloat16 hb = __float2bfloat16(v);
        size_t o = (size_t)(n0 + ty + i) * GK + k0 + tx;
        Th[o] = hb;
        Tl[o] = __float2bfloat16(v - __bfloat162float(hb));
    }
}

// ---------------- RoPE table ------------------------------------------------
__global__ void rope_table_kernel(float* __restrict__ gcos, float* __restrict__ gsin)
{
    int i = blockIdx.x * blockDim.x + threadIdx.x;
    if (i >= TT * 32) return;
    int t = i >> 5;
    int d = i & 31;
    float inv = (float)exp(-((double)(2 * d) / 64.0) * log(10000.0));
    float ang = (float)t * inv;
    gcos[i] = cosf(ang);
    gsin[i] = sinf(ang);
}

// ---------------- fused RoPE + bf16 hi/lo convert + V transpose ------------
// q[B,T,C] -> qh/ql [B,H,T,D] (scaled by 1/8); kv k-half -> kh/kl [B,H,T,D];
// kv v-half -> vth/vtl [B,H,D,T].
__global__ void __launch_bounds__(256)
rope_convert_kernel(const float* __restrict__ qg, const float* __restrict__ kvg,
                    const float* __restrict__ gcos, const float* __restrict__ gsin,
                    __nv_bfloat16* __restrict__ qh, __nv_bfloat16* __restrict__ ql,
                    __nv_bfloat16* __restrict__ kh, __nv_bfloat16* __restrict__ kl,
                    __nv_bfloat16* __restrict__ vth, __nv_bfloat16* __restrict__ vtl)
{
    __shared__ float vs[64][65];
    const int tid = threadIdx.x;
    const int t0 = blockIdx.x * 64, h = blockIdx.y, b = blockIdx.z;
    const size_t bh = (size_t)b * HH + h;
    const int trow = tid >> 4;
    const int dp = (tid & 15) * 2;

    #pragma unroll
    for (int i = 0; i < 4; i++) {
        int t = t0 + trow + i * 16;
        float c0 = gcos[t * 32 + dp],  c1 = gcos[t * 32 + dp + 1];
        float s0 = gsin[t * 32 + dp],  s1 = gsin[t * 32 + dp + 1];
        size_t db = (bh * TT + t) * 64;
        // q (scaled by 1/8 = 1/sqrt(D))
        {
            size_t qb = ((size_t)b * TT + t) * CC + h * 64;
            float2 xa = *reinterpret_cast<const float2*>(qg + qb + dp);
            float2 xb = *reinterpret_cast<const float2*>(qg + qb + dp + 32);
            float o0 = (xa.x * c0 - xb.x * s0) * 0.125f;
            float o1 = (xa.y * c1 - xb.y * s1) * 0.125f;
            float o2 = (xb.x * c0 + xa.x * s0) * 0.125f;
            float o3 = (xb.y * c1 + xa.y * s1) * 0.125f;
            store_hl(qh, ql, db + dp, o0, o1);
            store_hl(qh, ql, db + dp + 32, o2, o3);
        }
        // k
        {
            size_t kb = ((size_t)b * TT + t) * (2 * CC) + h * 64;
            float2 xa = *reinterpret_cast<const float2*>(kvg + kb + dp);
            float2 xb = *reinterpret_cast<const float2*>(kvg + kb + dp + 32);
            float o0 = xa.x * c0 - xb.x * s0;
            float o1 = xa.y * c1 - xb.y * s1;
            float o2 = xb.x * c0 + xa.x * s0;
            float o3 = xb.y * c1 + xa.y * s1;
            store_hl(kh, kl, db + dp, o0, o1);
            store_hl(kh, kl, db + dp + 32, o2, o3);
        }
    }
    // v transpose
    #pragma unroll
    for (int i = 0; i < 16; i++) {
        int idx = i * 256 + tid;
        int r = idx >> 6, d = idx & 63;
        vs[d][r] = kvg[((size_t)b * TT + t0 + r) * (2 * CC) + CC + h * 64 + d];
    }
    __syncthreads();
    #pragma unroll
    for (int i = 0; i < 8; i++) {
        int idx = i * 256 + tid;
        int d = idx >> 5, t2 = (idx & 31) * 2;
        store_hl(vth, vtl, (bh * 64 + d) * TT + t0 + t2, vs[d][t2], vs[d][t2 + 1]);
    }
}

// ---------------- Flash attention on HMMA (bf16 hi/lo, fp32 accum) --------
#define FROWB 144
#define FQ_TILE (128 * FROWB)        // 18432
#define FKV_TILE (64 * FROWB)        // 9216
#define FSTAGE (4 * FKV_TILE)        // 36864
#define FSMEM (2 * FQ_TILE + 2 * FSTAGE)   // 110592

__global__ void __launch_bounds__(256, 1)
flash_mma_kernel(const __nv_bfloat16* __restrict__ qh, const __nv_bfloat16* __restrict__ ql,
                 const __nv_bfloat16* __restrict__ kh, const __nv_bfloat16* __restrict__ kl,
                 const __nv_bfloat16* __restrict__ vth, const __nv_bfloat16* __restrict__ vtl,
                 __nv_bfloat16* __restrict__ yh, __nv_bfloat16* __restrict__ yl)
{
    extern __shared__ char smem_raw[];
    const uint32_t sQ  = smem_u32(smem_raw);
    const uint32_t sKV = sQ + 2 * FQ_TILE;

    const int tid = threadIdx.x, lane = tid & 31, warp = tid >> 5;
    const int t0 = blockIdx.x * 128;
    const int h = blockIdx.y, b = blockIdx.z;
    const size_t bh = (size_t)b * HH + h;
    const int nkv = t0 / 64 + 2;

    // Q prefetch (hi, lo)
    #pragma unroll
    for (int i = 0; i < 8; i++) {
        int idx = i * 256 + tid;
        int arr = idx >> 10, r = (idx >> 3) & 127, j = idx & 7;
        const __nv_bfloat16* g = (arr ? ql : qh) + (bh * TT + t0 + r) * 64 + j * 8;
        cp_async16(sQ + arr * FQ_TILE + r * FROWB + j * 16, g);
    }
    auto pref_kv = [&](int n) {
        const uint32_t sb = sKV + (uint32_t)(n & 1) * FSTAGE;
        const int j0 = n * 64;
        #pragma unroll
        for (int i = 0; i < 8; i++) {
            int idx = i * 256 + tid;
            int arr = idx >> 9, r = (idx >> 3) & 63, j = idx & 7;
            const __nv_bfloat16* g;
            if (arr == 0)      g = kh  + (bh * TT + j0 + r) * 64 + j * 8;
            else if (arr == 1) g = kl  + (bh * TT + j0 + r) * 64 + j * 8;
            else if (arr == 2) g = vth + (bh * 64 + r) * TT + j0 + j * 8;
            else               g = vtl + (bh * 64 + r) * TT + j0 + j * 8;
            cp_async16(sb + arr * FKV_TILE + r * FROWB + j * 16, g);
        }
    };
    pref_kv(0);
    asm volatile("cp.async.commit_group;" ::: "memory");
    pref_kv(1);
    asm volatile("cp.async.commit_group;" ::: "memory");

    const int wrow = t0 + warp * 16;        // warp's first q row (global)
    const int gr = lane >> 2;
    const int qk = (lane & 3) * 2;
    const int row0 = wrow + gr;
    const int row1 = row0 + 8;

    uint32_t qa_h[4][4], qa_l[4][4];
    float O[8][4];
    #pragma unroll
    for (int nt = 0; nt < 8; nt++)
        #pragma unroll
        for (int e = 0; e < 4; e++) O[nt][e] = 0.f;
    float mA = -1e30f, mB = -1e30f, lA = 0.f, lB = 0.f;

    const uint32_t bBaseOff = ((lane & 7) + ((lane >> 4) << 3)) * FROWB + (((lane >> 3) & 1) << 4);

    for (int n = 0; n < nkv; n++) {
        asm volatile("cp.async.wait_group 1;" ::: "memory");
        __syncthreads();

        if (n == 0) {
            const uint32_t qb = sQ + (warp * 16 + (lane & 15)) * FROWB + ((lane >> 4) << 4);
            #pragma unroll
            for (int ks = 0; ks < 4; ks++) {
                ldsm_x4(qa_h[ks][0], qa_h[ks][1], qa_h[ks][2], qa_h[ks][3], qb + ks * 32);
                ldsm_x4(qa_l[ks][0], qa_l[ks][1], qa_l[ks][2], qa_l[ks][3],
                        qb + FQ_TILE + ks * 32);
            }
        }

        const int j0 = n * 64;
        if (j0 <= wrow + 15) {
            const uint32_t sb = sKV + (uint32_t)(n & 1) * FSTAGE;
            float S[8][4];
            #pragma unroll
            for (int nt = 0; nt < 8; nt++)
                #pragma unroll
                for (int e = 0; e < 4; e++) S[nt][e] = 0.f;

            // ---- S = Q K^T (3-product split) ----
            #pragma unroll
            for (int ks = 0; ks < 4; ks++) {
                uint32_t B0h[8], B1h[8], B0l[8], B1l[8];
                #pragma unroll
                for (int q2 = 0; q2 < 4; q2++) {
                    const uint32_t off = bBaseOff + q2 * (16 * FROWB) + ks * 32;
                    ldsm_x4(B0h[q2*2], B1h[q2*2], B0h[q2*2+1], B1h[q2*2+1], sb + off);
                    ldsm_x4(B0l[q2*2], B1l[q2*2], B0l[q2*2+1], B1l[q2*2+1],
                            sb + FKV_TILE + off);
                }
                #pragma unroll
                for (int nt = 0; nt < 8; nt++) {
                    float* c = S[nt];
                    mma16816(c[0], c[1], c[2], c[3],
                             qa_h[ks][0], qa_h[ks][1], qa_h[ks][2], qa_h[ks][3],
                             B0h[nt], B1h[nt]);
                    mma16816(c[0], c[1], c[2], c[3],
                             qa_h[ks][0], qa_h[ks][1], qa_h[ks][2], qa_h[ks][3],
                             B0l[nt], B1l[nt]);
                    mma16816(c[0], c[1], c[2], c[3],
                             qa_l[ks][0], qa_l[ks][1], qa_l[ks][2], qa_l[ks][3],
                             B0h[nt], B1h[nt]);
                }
            }

            // ---- causal mask (only near the diagonal) ----
            if (j0 + 63 > wrow) {
                #pragma unroll
                for (int nt = 0; nt < 8; nt++) {
                    const int c0 = j0 + nt * 8 + qk;
                    if (c0 > row0)     S[nt][0] = -1e30f;
                    if (c0 + 1 > row0) S[nt][1] = -1e30f;
                    if (c0 > row1)     S[nt][2] = -1e30f;
                    if (c0 + 1 > row1) S[nt][3] = -1e30f;
                }
            }

            // ---- online softmax ----
            float tmA = -1e30f, tmB = -1e30f;
            #pragma unroll
            for (int nt = 0; nt < 8; nt++) {
                tmA = fmaxf(tmA, fmaxf(S[nt][0], S[nt][1]));
                tmB = fmaxf(tmB, fmaxf(S[nt][2], S[nt][3]));
            }
            tmA = fmaxf(tmA, __shfl_xor_sync(0xffffffffu, tmA, 1));
            tmA = fmaxf(tmA, __shfl_xor_sync(0xffffffffu, tmA, 2));
            tmB = fmaxf(tmB, __shfl_xor_sync(0xffffffffu, tmB, 1));
            tmB = fmaxf(tmB, __shfl_xor_sync(0xffffffffu, tmB, 2));
            const float mnA = fmaxf(mA, tmA), mnB = fmaxf(mB, tmB);
            const float aA = __expf(mA - mnA), aB = __expf(mB - mnB);
            float sumA = 0.f, sumB = 0.f;
            #pragma unroll
            for (int nt = 0; nt < 8; nt++) {
                S[nt][0] = __expf(S[nt][0] - mnA);
                S[nt][1] = __expf(S[nt][1] - mnA);
                S[nt][2] = __expf(S[nt][2] - mnB);
                S[nt][3] = __expf(S[nt][3] - mnB);
                sumA += S[nt][0] + S[nt][1];
                sumB += S[nt][2] + S[nt][3];
            }
            sumA += __shfl_xor_sync(0xffffffffu, sumA, 1);
            sumA += __shfl_xor_sync(0xffffffffu, sumA, 2);
            sumB += __shfl_xor_sync(0xffffffffu, sumB, 1);
            sumB += __shfl_xor_sync(0xffffffffu, sumB, 2);
            lA = lA * aA + sumA;
            lB = lB * aB + sumB;
            mA = mnA; mB = mnB;
            #pragma unroll
            for (int nt = 0; nt < 8; nt++) {
                O[nt][0] *= aA; O[nt][1] *= aA;
                O[nt][2] *= aB; O[nt][3] *= aB;
            }

            // ---- O += P V (3-product split) ----
            const uint32_t vb = sb + 2 * FKV_TILE;
            #pragma unroll
            for (int ks = 0; ks < 4; ks++) {
                // pack P a-frags for this k16 step (kv cols 16ks..16ks+15)
                const int n0t = 2 * ks, n1t = 2 * ks + 1;
                uint32_t pah[4], pal[4];
                {
                    __nv_bfloat162 h0 = __float22bfloat162_rn(make_float2(S[n0t][0], S[n0t][1]));
                    __nv_bfloat162 h1 = __float22bfloat162_rn(make_float2(S[n0t][2], S[n0t][3]));
                    __nv_bfloat162 h2 = __float22bfloat162_rn(make_float2(S[n1t][0], S[n1t][1]));
                    __nv_bfloat162 h3 = __float22bfloat162_rn(make_float2(S[n1t][2], S[n1t][3]));
                    pah[0] = *reinterpret_cast<uint32_t*>(&h0);
                    pah[1] = *reinterpret_cast<uint32_t*>(&h1);
                    pah[2] = *reinterpret_cast<uint32_t*>(&h2);
                    pah[3] = *reinterpret_cast<uint32_t*>(&h3);
                    pal[0] = pack_bf16(S[n0t][0] - __bfloat162float(h0.x),
                                       S[n0t][1] - __bfloat162float(h0.y));
                    pal[1] = pack_bf16(S[n0t][2] - __bfloat162float(h1.x),
                                       S[n0t][3] - __bfloat162float(h1.y));
                    pal[2] = pack_bf16(S[n1t][0] - __bfloat162float(h2.x),
                                       S[n1t][1] - __bfloat162float(h2.y));
                    pal[3] = pack_bf16(S[n1t][2] - __bfloat162float(h3.x),
                                       S[n1t][3] - __bfloat162float(h3.y));
                }
                uint32_t V0h[8], V1h[8], V0l[8], V1l[8];
                #pragma unroll
                for (int q2 = 0; q2 < 4; q2++) {
                    const uint32_t off = bBaseOff + q2 * (16 * FROWB) + ks * 32;
                    ldsm_x4(V0h[q2*2], V1h[q2*2], V0h[q2*2+1], V1h[q2*2+1], vb + off);
                    ldsm_x4(V0l[q2*2], V1l[q2*2], V0l[q2*2+1], V1l[q2*2+1],
                            vb + FKV_TILE + off);
                }
                #pragma unroll
                for (int nt = 0; nt < 8; nt++) {
                    float* c = O[nt];
                    mma16816(c[0], c[1], c[2], c[3],
                             pah[0], pah[1], pah[2], pah[3], V0h[nt], V1h[nt]);
                    mma16816(c[0], c[1], c[2], c[3],
                             pah[0], pah[1], pah[2], pah[3], V0l[nt], V1l[nt]);
                    mma16816(c[0], c[1], c[2], c[3],
                             pal[0], pal[1], pal[2], pal[3], V0h[nt], V1h[nt]);
                }
            }
        }
        __syncthreads();
        if (n + 2 < nkv) pref_kv(n + 2);
        asm volatile("cp.async.commit_group;" ::: "memory");
    }

    // ---- epilogue: y = O / l, write bf16 hi/lo [B,T,C] ----
    const float iA = 1.f / lA, iB = 1.f / lB;
    #pragma unroll
    for (int nt = 0; nt < 8; nt++) {
        const size_t d0 = (size_t)h * 64 + nt * 8 + qk;
        store_hl(yh, yl, ((size_t)b * TT + row0) * CC + d0, O[nt][0] * iA, O[nt][1] * iA);
        store_hl(yh, yl, ((size_t)b * TT + row1) * CC + d0, O[nt][2] * iB, O[nt][3] * iB);
    }
}

// ---------------- launch ---------------------------------------------------
extern "C" void kernel_launch(void* const* d_in, const int* in_sizes, int n_in,
                              void* d_out, int out_size)
{
    const float* x   = (const float*)d_in[0];
    const float* Wq  = (const float*)d_in[1];
    const float* Wkv = (const float*)d_in[2];
    const float* Wc  = (const float*)d_in[3];
    float* out = (float*)d_out;

    float *q, *kv, *gc, *gs;
    __nv_bfloat16 *xh, *xl, *yh, *yl, *wqh, *wql, *wkvh, *wkvl, *wch, *wcl;
    __nv_bfloat16 *qh, *ql, *kh, *kl, *vth, *vtl;
    cudaGetSymbolAddress((void**)&q,  g_q);
    cudaGetSymbolAddress((void**)&kv, g_kv);
    cudaGetSymbolAddress((void**)&gc, g_cos);
    cudaGetSymbolAddress((void**)&gs, g_sin);
    cudaGetSymbolAddress((void**)&xh, g_xh);
    cudaGetSymbolAddress((void**)&xl, g_xl);
    cudaGetSymbolAddress((void**)&yh, g_yh);
    cudaGetSymbolAddress((void**)&yl, g_yl);
    cudaGetSymbolAddress((void**)&wqh, g_wqh);
    cudaGetSymbolAddress((void**)&wql, g_wql);
    cudaGetSymbolAddress((void**)&wkvh, g_wkvh);
    cudaGetSymbolAddress((void**)&wkvl, g_wkvl);
    cudaGetSymbolAddress((void**)&wch, g_wch);
    cudaGetSymbolAddress((void**)&wcl, g_wcl);
    cudaGetSymbolAddress((void**)&qh, g_qh);
    cudaGetSymbolAddress((void**)&ql, g_ql);
    cudaGetSymbolAddress((void**)&kh, g_kh);
    cudaGetSymbolAddress((void**)&kl, g_kl);
    cudaGetSymbolAddress((void**)&vth, g_vth);
    cudaGetSymbolAddress((void**)&vtl, g_vtl);

    cudaFuncSetAttribute(gemm_kernel_mma, cudaFuncAttributeMaxDynamicSharedMemorySize, SMEM_DYN);
    cudaFuncSetAttribute(flash_mma_kernel, cudaFuncAttributeMaxDynamicSharedMemorySize, FSMEM);

    rope_table_kernel<<<(TT * 32 + 255) / 256, 256>>>(gc, gs);

    // split x
    {
        int n4 = MM * GK / 4;
        split_kernel<<<(n4 + 255) / 256, 256>>>((const float4*)x, (uint2*)xh, (uint2*)xl, n4);
    }
    // transpose-split weights
    transpose_split_kernel<<<dim3(CC / 32, GK / 32), dim3(32, 8)>>>(Wq, wqh, wql, CC);
    transpose_split_kernel<<<dim3(2 * CC / 32, GK / 32), dim3(32, 8)>>>(Wkv, wkvh, wkvl, 2 * CC);
    transpose_split_kernel<<<dim3(CC / 32, GK / 32), dim3(32, 8)>>>(Wc, wch, wcl, CC);

    // q = x @ Wq ; kv = x @ Wkv
    gemm_kernel_mma<<<dim3(CC / 128, MM / 128), 256, SMEM_DYN>>>(xh, xl, wqh, wql, q, CC);
    gemm_kernel_mma<<<dim3(2 * CC / 128, MM / 128), 256, SMEM_DYN>>>(xh, xl, wkvh, wkvl, kv, 2 * CC);

    // fused RoPE + convert + V transpose
    rope_convert_kernel<<<dim3(TT / 64, HH, BB), 256>>>(q, kv, gc, gs, qh, ql, kh, kl, vth, vtl);

    // attention (writes yh/yl directly)
    flash_mma_kernel<<<dim3(TT / 128, HH, BB), 256, FSMEM>>>(qh, ql, kh, kl, vth, vtl, yh, yl);

    // out = y @ Wc
    gemm_kernel_mma<<<dim3(CC / 128, MM / 128), 256, SMEM_DYN>>>(yh, yl, wch, wcl, out, CC);
}

// round 5
// speedup vs baseline: 3.2044x; 1.0199x over previous
#include <cuda_runtime.h>
#include <cuda_bf16.h>
#include <math.h>
#include <stdint.h>

#define BB 4
#define TT 2048
#define HH 16
#define DD 64
#define CC (HH*DD)      // 1024
#define MM (BB*TT)      // 8192
#define GK 1024         // K of all GEMMs

// ---------------- scratch (device globals; no allocation allowed) ----------
__device__ __align__(256) float g_cos[TT * 32];
__device__ __align__(256) float g_sin[TT * 32];

// bf16 split operands
__device__ __align__(256) __nv_bfloat16 g_xh[(size_t)MM * GK];
__device__ __align__(256) __nv_bfloat16 g_xl[(size_t)MM * GK];
__device__ __align__(256) __nv_bfloat16 g_yh[(size_t)MM * GK];
__device__ __align__(256) __nv_bfloat16 g_yl[(size_t)MM * GK];
// attention operands [B,H,T,D] (q,k) and [B,H,D,T] (v transposed)
__device__ __align__(256) __nv_bfloat16 g_qh[(size_t)BB*HH*TT*DD];
__device__ __align__(256) __nv_bfloat16 g_ql[(size_t)BB*HH*TT*DD];
__device__ __align__(256) __nv_bfloat16 g_kh[(size_t)BB*HH*TT*DD];
__device__ __align__(256) __nv_bfloat16 g_kl[(size_t)BB*HH*TT*DD];
__device__ __align__(256) __nv_bfloat16 g_vth[(size_t)BB*HH*TT*DD];
__device__ __align__(256) __nv_bfloat16 g_vtl[(size_t)BB*HH*TT*DD];
// transposed weights [N, K]: combined [Wq^T; Wk^T; Wv^T] = [3C, K]
__device__ __align__(256) __nv_bfloat16 g_wh[(size_t)3 * CC * GK];
__device__ __align__(256) __nv_bfloat16 g_wl[(size_t)3 * CC * GK];
__device__ __align__(256) __nv_bfloat16 g_wch[(size_t)CC * GK];
__device__ __align__(256) __nv_bfloat16 g_wcl[(size_t)CC * GK];

// ---------------- helpers ----------------------------------------------------
__device__ __forceinline__ uint32_t smem_u32(const void* p) {
    return (uint32_t)__cvta_generic_to_shared(p);
}

__device__ __forceinline__ void cp_async16(uint32_t saddr, const void* gaddr) {
    asm volatile("cp.async.cg.shared.global [%0], [%1], 16;" :: "r"(saddr), "l"(gaddr) : "memory");
}

__device__ __forceinline__ void ldsm_x4(uint32_t& r0, uint32_t& r1, uint32_t& r2, uint32_t& r3,
                                        uint32_t addr) {
    asm volatile("ldmatrix.sync.aligned.m8n8.x4.shared.b16 {%0,%1,%2,%3}, [%4];"
                 : "=r"(r0), "=r"(r1), "=r"(r2), "=r"(r3) : "r"(addr));
}

__device__ __forceinline__ void mma16816(float& c0, float& c1, float& c2, float& c3,
                                         uint32_t a0, uint32_t a1, uint32_t a2, uint32_t a3,
                                         uint32_t b0, uint32_t b1) {
    asm volatile(
        "mma.sync.aligned.m16n8k16.row.col.f32.bf16.bf16.f32 "
        "{%0,%1,%2,%3}, {%4,%5,%6,%7}, {%8,%9}, {%0,%1,%2,%3};"
        : "+f"(c0), "+f"(c1), "+f"(c2), "+f"(c3)
        : "r"(a0), "r"(a1), "r"(a2), "r"(a3), "r"(b0), "r"(b1));
}

__device__ __forceinline__ uint32_t pack_bf16(float a, float b) {
    __nv_bfloat162 t = __float22bfloat162_rn(make_float2(a, b));
    return *reinterpret_cast<uint32_t*>(&t);
}

__device__ __forceinline__ void store_hl(__nv_bfloat16* hi, __nv_bfloat16* lo,
                                         size_t off, float a, float b) {
    __nv_bfloat162 h = __float22bfloat162_rn(make_float2(a, b));
    float ra = a - __bfloat162float(h.x);
    float rb = b - __bfloat162float(h.y);
    __nv_bfloat162 l = __float22bfloat162_rn(make_float2(ra, rb));
    *reinterpret_cast<__nv_bfloat162*>(hi + off) = h;
    *reinterpret_cast<__nv_bfloat162*>(lo + off) = l;
}

// ---------------- HMMA GEMM: C = (Ah+Al) @ (Bh+Bl)^T -----------------------
// mode 0: plain fp32 store to Cm.
// mode 1: fused QKV epilogue (RoPE+scale for Q, RoPE for K, transpose for V,
//         bf16 hi/lo outputs). Ndim must be 3072, col-tile ct: 0-7 Q, 8-15 K,
//         16-23 V.
#define BK 32
#define NUMK (GK / BK)          // 32
#define ROWB 80                 // 64B data + 16B pad
#define TILE_B (128 * ROWB)     // 10240
#define STAGE_B (4 * TILE_B)    // 40960
#define NSTAGE 3
#define SMEM_DYN (NSTAGE * STAGE_B)   // 122880

__global__ void __launch_bounds__(256, 1)
gemm_kernel_mma(const __nv_bfloat16* __restrict__ Ah, const __nv_bfloat16* __restrict__ Al,
                const __nv_bfloat16* __restrict__ Bh, const __nv_bfloat16* __restrict__ Bl,
                float* __restrict__ Cm, int Ndim, int mode,
                const float* __restrict__ gcos, const float* __restrict__ gsin,
                __nv_bfloat16* __restrict__ qh, __nv_bfloat16* __restrict__ ql,
                __nv_bfloat16* __restrict__ kh, __nv_bfloat16* __restrict__ kl,
                __nv_bfloat16* __restrict__ vth, __nv_bfloat16* __restrict__ vtl)
{
    extern __shared__ char smem_raw[];
    const uint32_t sbase = smem_u32(smem_raw);

    const int tid  = threadIdx.x;
    const int lane = tid & 31;
    const int warp = tid >> 5;
    const int mw   = warp & 1;
    const int nw   = warp >> 1;
    const int m0 = blockIdx.y * 128;
    const int n0 = blockIdx.x * 128;

    const __nv_bfloat16* tp[4] = { Ah, Al, Bh, Bl };

    auto prefetch = [&](int kc) {
        const uint32_t sstage = sbase + (uint32_t)(kc % NSTAGE) * STAGE_B;
        #pragma unroll
        for (int i = 0; i < 8; i++) {
            const int c = i * 256 + tid;
            const int tile = c >> 9;
            const int r = (c >> 2) & 127;
            const int j = c & 3;
            const int row0 = (tile < 2) ? m0 : n0;
            const __nv_bfloat16* g = tp[tile] + (size_t)(row0 + r) * GK + kc * BK + j * 8;
            cp_async16(sstage + tile * TILE_B + r * ROWB + j * 16, g);
        }
    };

    prefetch(0);
    asm volatile("cp.async.commit_group;" ::: "memory");
    prefetch(1);
    asm volatile("cp.async.commit_group;" ::: "memory");

    const uint32_t aBase = (uint32_t)((mw * 64 + (lane & 15)) * ROWB + ((lane >> 4) << 4));
    const uint32_t bBase = (uint32_t)((nw * 32 + (lane & 7) + ((lane >> 4) << 3)) * ROWB
                                      + (((lane >> 3) & 1) << 4));

    float acc[4][4][4];
    #pragma unroll
    for (int mt = 0; mt < 4; mt++)
        #pragma unroll
        for (int nt = 0; nt < 4; nt++)
            #pragma unroll
            for (int e = 0; e < 4; e++) acc[mt][nt][e] = 0.f;

    for (int kc = 0; kc < NUMK; kc++) {
        asm volatile("cp.async.wait_group 1;" ::: "memory");
        __syncthreads();

        if (kc + 2 < NUMK) prefetch(kc + 2);
        asm volatile("cp.async.commit_group;" ::: "memory");

        const uint32_t sstage = sbase + (uint32_t)(kc % NSTAGE) * STAGE_B;
        const uint32_t aTile = sstage;
        const uint32_t bTile = sstage + 2 * TILE_B;

        #pragma unroll
        for (int ks = 0; ks < 2; ks++) {
            const uint32_t kb = ks * 32;
            uint32_t ah[4][4], al[4][4];
            #pragma unroll
            for (int mt = 0; mt < 4; mt++) {
                const uint32_t off = aBase + mt * (16 * ROWB) + kb;
                ldsm_x4(ah[mt][0], ah[mt][1], ah[mt][2], ah[mt][3], aTile + off);
                ldsm_x4(al[mt][0], al[mt][1], al[mt][2], al[mt][3], aTile + TILE_B + off);
            }
            uint32_t bh[4][2], bl[4][2];
            #pragma unroll
            for (int np = 0; np < 2; np++) {
                const uint32_t off = bBase + np * (16 * ROWB) + kb;
                ldsm_x4(bh[np*2][0], bh[np*2][1], bh[np*2+1][0], bh[np*2+1][1], bTile + off);
                ldsm_x4(bl[np*2][0], bl[np*2][1], bl[np*2+1][0], bl[np*2+1][1],
                        bTile + TILE_B + off);
            }
            #pragma unroll
            for (int mt = 0; mt < 4; mt++) {
                #pragma unroll
                for (int nt = 0; nt < 4; nt++) {
                    float* c = acc[mt][nt];
                    mma16816(c[0], c[1], c[2], c[3],
                             ah[mt][0], ah[mt][1], ah[mt][2], ah[mt][3],
                             bh[nt][0], bh[nt][1]);
                    mma16816(c[0], c[1], c[2], c[3],
                             ah[mt][0], ah[mt][1], ah[mt][2], ah[mt][3],
                             bl[nt][0], bl[nt][1]);
                    mma16816(c[0], c[1], c[2], c[3],
                             al[mt][0], al[mt][1], al[mt][2], al[mt][3],
                             bh[nt][0], bh[nt][1]);
                }
            }
        }
        __syncthreads();
    }

    if (mode == 0) {
        const int rbase = m0 + mw * 64 + (lane >> 2);
        const int cbase = n0 + nw * 32 + ((lane & 3) << 1);
        #pragma unroll
        for (int mt = 0; mt < 4; mt++) {
            #pragma unroll
            for (int nt = 0; nt < 4; nt++) {
                float* c = acc[mt][nt];
                float* p0 = Cm + (size_t)(rbase + mt * 16) * Ndim + cbase + nt * 8;
                float* p1 = p0 + (size_t)8 * Ndim;
                *reinterpret_cast<float2*>(p0) = make_float2(c[0], c[1]);
                *reinterpret_cast<float2*>(p1) = make_float2(c[2], c[3]);
            }
        }
        return;
    }

    // ---- fused QKV epilogue ----
    // stage the fp32 tile to smem [128][132]
    float* sm = reinterpret_cast<float*>(smem_raw);
    const int rloc = mw * 64 + (lane >> 2);
    const int cloc = nw * 32 + ((lane & 3) << 1);
    #pragma unroll
    for (int mt = 0; mt < 4; mt++) {
        #pragma unroll
        for (int nt = 0; nt < 4; nt++) {
            float* c = acc[mt][nt];
            float* p0 = sm + (size_t)(rloc + mt * 16) * 132 + cloc + nt * 8;
            *reinterpret_cast<float2*>(p0)       = make_float2(c[0], c[1]);
            *reinterpret_cast<float2*>(p0 + 8 * 132) = make_float2(c[2], c[3]);
        }
    }
    __syncthreads();

    const int ct = blockIdx.x;
    const int b = m0 >> 11;            // TT = 2048
    const int t_base = m0 & (TT - 1);

    if (ct < 16) {
        // Q (ct<8) or K (8<=ct<16): RoPE, (Q scaled), write [B,H,T,D]
        const bool isQ = (ct < 8);
        const float qs = isQ ? 0.125f : 1.0f;
        __nv_bfloat16* dh = isQ ? qh : kh;
        __nv_bfloat16* dl = isQ ? ql : kl;
        const int hbase = (isQ ? ct : (ct - 8)) * 2;
        #pragma unroll
        for (int i = 0; i < 16; i++) {
            const int idx = i * 256 + tid;
            const int dp = (idx & 15) * 2;
            const int hs = (idx >> 4) & 1;
            const int r  = idx >> 5;
            const int t  = t_base + r;
            const float c0 = gcos[t * 32 + dp],  c1 = gcos[t * 32 + dp + 1];
            const float s0 = gsin[t * 32 + dp],  s1 = gsin[t * 32 + dp + 1];
            const float* row = sm + (size_t)r * 132 + hs * 64;
            const float x1 = row[dp],      x1b = row[dp + 1];
            const float x2 = row[dp + 32], x2b = row[dp + 33];
            const float o0 = (x1 * c0 - x2 * s0) * qs;
            const float o1 = (x1b * c1 - x2b * s1) * qs;
            const float o2 = (x2 * c0 + x1 * s0) * qs;
            const float o3 = (x2b * c1 + x1b * s1) * qs;
            const size_t base = (((size_t)b * HH + hbase + hs) * TT + t) * 64;
            store_hl(dh, dl, base + dp, o0, o1);
            store_hl(dh, dl, base + dp + 32, o2, o3);
        }
    } else {
        // V: transpose to [B,H,D,T]
        const int hbase = (ct - 16) * 2;
        #pragma unroll
        for (int i = 0; i < 32; i++) {
            const int idx = i * 256 + tid;
            const int c  = idx >> 6;          // 0..127
            const int t2 = idx & 63;
            const int hs = c >> 6;
            const int d  = c & 63;
            const float a  = sm[(size_t)(2 * t2) * 132 + c];
            const float bv = sm[(size_t)(2 * t2 + 1) * 132 + c];
            const int t = t_base + 2 * t2;
            store_hl(vth, vtl,
                     (((size_t)b * HH + hbase + hs) * 64 + d) * TT + t, a, bv);
        }
    }
}

// ---------------- fp32 -> bf16 hi/lo split ---------------------------------
__global__ void split_kernel(const float4* __restrict__ in,
                             uint2* __restrict__ hi, uint2* __restrict__ lo, int n4)
{
    int i = blockIdx.x * blockDim.x + threadIdx.x;
    if (i >= n4) return;
    float4 v = in[i];
    float vv[4] = { v.x, v.y, v.z, v.w };
    unsigned short h[4], l[4];
    #pragma unroll
    for (int k = 0; k < 4; k++) {
        __nv_bfloat16 hb = __float2bfloat16(vv[k]);
        __nv_bfloat16 lb = __float2bfloat16(vv[k] - __bfloat162float(hb));
        h[k] = __bfloat16_as_ushort(hb);
        l[k] = __bfloat16_as_ushort(lb);
    }
    uint2 ho, lo_;
    ho.x = (uint32_t)h[0] | ((uint32_t)h[1] << 16);
    ho.y = (uint32_t)h[2] | ((uint32_t)h[3] << 16);
    lo_.x = (uint32_t)l[0] | ((uint32_t)l[1] << 16);
    lo_.y = (uint32_t)l[2] | ((uint32_t)l[3] << 16);
    hi[i] = ho;
    lo[i] = lo_;
}

// ---------------- W[K,N] -> Wt[N,K] bf16 hi/lo transpose-split -------------
__global__ void transpose_split_kernel(const float* __restrict__ W,
                                       __nv_bfloat16* __restrict__ Th,
                                       __nv_bfloat16* __restrict__ Tl, int N)
{
    __shared__ float t[32][33];
    const int n0 = blockIdx.x * 32, k0 = blockIdx.y * 32;
    const int tx = threadIdx.x, ty = threadIdx.y;
    #pragma unroll
    for (int i = 0; i < 32; i += 8)
        t[ty + i][tx] = W[(size_t)(k0 + ty + i) * N + n0 + tx];
    __syncthreads();
    #pragma unroll
    for (int i = 0; i < 32; i += 8) {
        float v = t[tx][ty + i];
        __nv_bfloat16 hb = __float2bfloat16(v);
        size_t o = (size_t)(n0 + ty + i) * GK + k0 + tx;
        Th[o] = hb;
        Tl[o] = __float2bfloat16(v - __bfloat162float(hb));
    }
}

// ---------------- RoPE table ------------------------------------------------
__global__ void rope_table_kernel(float* __restrict__ gcos, float* __restrict__ gsin)
{
    int i = blockIdx.x * blockDim.x + threadIdx.x;
    if (i >= TT * 32) return;
    int t = i >> 5;
    int d = i & 31;
    float inv = (float)exp(-((double)(2 * d) / 64.0) * log(10000.0));
    float ang = (float)t * inv;
    gcos[i] = cosf(ang);
    gsin[i] = sinf(ang);
}

// ---------------- Flash attention on HMMA (bf16 hi/lo, fp32 accum) --------
#define FROWB 144
#define FQ_TILE (128 * FROWB)        // 18432
#define FKV_TILE (64 * FROWB)        // 9216
#define FSTAGE (4 * FKV_TILE)        // 36864
#define FSMEM (2 * FQ_TILE + 2 * FSTAGE)   // 110592

__global__ void __launch_bounds__(256, 1)
flash_mma_kernel(const __nv_bfloat16* __restrict__ qh, const __nv_bfloat16* __restrict__ ql,
                 const __nv_bfloat16* __restrict__ kh, const __nv_bfloat16* __restrict__ kl,
                 const __nv_bfloat16* __restrict__ vth, const __nv_bfloat16* __restrict__ vtl,
                 __nv_bfloat16* __restrict__ yh, __nv_bfloat16* __restrict__ yl)
{
    extern __shared__ char smem_raw[];
    const uint32_t sQ  = smem_u32(smem_raw);
    const uint32_t sKV = sQ + 2 * FQ_TILE;

    const int tid = threadIdx.x, lane = tid & 31, warp = tid >> 5;
    const int t0 = blockIdx.x * 128;
    const int h = blockIdx.y, b = blockIdx.z;
    const size_t bh = (size_t)b * HH + h;
    const int nkv = t0 / 64 + 2;

    #pragma unroll
    for (int i = 0; i < 8; i++) {
        int idx = i * 256 + tid;
        int arr = idx >> 10, r = (idx >> 3) & 127, j = idx & 7;
        const __nv_bfloat16* g = (arr ? ql : qh) + (bh * TT + t0 + r) * 64 + j * 8;
        cp_async16(sQ + arr * FQ_TILE + r * FROWB + j * 16, g);
    }
    auto pref_kv = [&](int n) {
        const uint32_t sb = sKV + (uint32_t)(n & 1) * FSTAGE;
        const int j0 = n * 64;
        #pragma unroll
        for (int i = 0; i < 8; i++) {
            int idx = i * 256 + tid;
            int arr = idx >> 9, r = (idx >> 3) & 63, j = idx & 7;
            const __nv_bfloat16* g;
            if (arr == 0)      g = kh  + (bh * TT + j0 + r) * 64 + j * 8;
            else if (arr == 1) g = kl  + (bh * TT + j0 + r) * 64 + j * 8;
            else if (arr == 2) g = vth + (bh * 64 + r) * TT + j0 + j * 8;
            else               g = vtl + (bh * 64 + r) * TT + j0 + j * 8;
            cp_async16(sb + arr * FKV_TILE + r * FROWB + j * 16, g);
        }
    };
    pref_kv(0);
    asm volatile("cp.async.commit_group;" ::: "memory");
    pref_kv(1);
    asm volatile("cp.async.commit_group;" ::: "memory");

    const int wrow = t0 + warp * 16;
    const int gr = lane >> 2;
    const int qk = (lane & 3) * 2;
    const int row0 = wrow + gr;
    const int row1 = row0 + 8;

    uint32_t qa_h[4][4], qa_l[4][4];
    float O[8][4];
    #pragma unroll
    for (int nt = 0; nt < 8; nt++)
        #pragma unroll
        for (int e = 0; e < 4; e++) O[nt][e] = 0.f;
    float mA = -1e30f, mB = -1e30f, lA = 0.f, lB = 0.f;

    const uint32_t bBaseOff = ((lane & 7) + ((lane >> 4) << 3)) * FROWB + (((lane >> 3) & 1) << 4);

    for (int n = 0; n < nkv; n++) {
        asm volatile("cp.async.wait_group 1;" ::: "memory");
        __syncthreads();

        if (n == 0) {
            const uint32_t qb = sQ + (warp * 16 + (lane & 15)) * FROWB + ((lane >> 4) << 4);
            #pragma unroll
            for (int ks = 0; ks < 4; ks++) {
                ldsm_x4(qa_h[ks][0], qa_h[ks][1], qa_h[ks][2], qa_h[ks][3], qb + ks * 32);
                ldsm_x4(qa_l[ks][0], qa_l[ks][1], qa_l[ks][2], qa_l[ks][3],
                        qb + FQ_TILE + ks * 32);
            }
        }

        const int j0 = n * 64;
        if (j0 <= wrow + 15) {
            const uint32_t sb = sKV + (uint32_t)(n & 1) * FSTAGE;
            float S[8][4];
            #pragma unroll
            for (int nt = 0; nt < 8; nt++)
                #pragma unroll
                for (int e = 0; e < 4; e++) S[nt][e] = 0.f;

            #pragma unroll
            for (int ks = 0; ks < 4; ks++) {
                uint32_t B0h[8], B1h[8], B0l[8], B1l[8];
                #pragma unroll
                for (int q2 = 0; q2 < 4; q2++) {
                    const uint32_t off = bBaseOff + q2 * (16 * FROWB) + ks * 32;
                    ldsm_x4(B0h[q2*2], B1h[q2*2], B0h[q2*2+1], B1h[q2*2+1], sb + off);
                    ldsm_x4(B0l[q2*2], B1l[q2*2], B0l[q2*2+1], B1l[q2*2+1],
                            sb + FKV_TILE + off);
                }
                #pragma unroll
                for (int nt = 0; nt < 8; nt++) {
                    float* c = S[nt];
                    mma16816(c[0], c[1], c[2], c[3],
                             qa_h[ks][0], qa_h[ks][1], qa_h[ks][2], qa_h[ks][3],
                             B0h[nt], B1h[nt]);
                    mma16816(c[0], c[1], c[2], c[3],
                             qa_h[ks][0], qa_h[ks][1], qa_h[ks][2], qa_h[ks][3],
                             B0l[nt], B1l[nt]);
                    mma16816(c[0], c[1], c[2], c[3],
                             qa_l[ks][0], qa_l[ks][1], qa_l[ks][2], qa_l[ks][3],
                             B0h[nt], B1h[nt]);
                }
            }

            if (j0 + 63 > wrow) {
                #pragma unroll
                for (int nt = 0; nt < 8; nt++) {
                    const int c0 = j0 + nt * 8 + qk;
                    if (c0 > row0)     S[nt][0] = -1e30f;
                    if (c0 + 1 > row0) S[nt][1] = -1e30f;
                    if (c0 > row1)     S[nt][2] = -1e30f;
                    if (c0 + 1 > row1) S[nt][3] = -1e30f;
                }
            }

            float tmA = -1e30f, tmB = -1e30f;
            #pragma unroll
            for (int nt = 0; nt < 8; nt++) {
                tmA = fmaxf(tmA, fmaxf(S[nt][0], S[nt][1]));
                tmB = fmaxf(tmB, fmaxf(S[nt][2], S[nt][3]));
            }
            tmA = fmaxf(tmA, __shfl_xor_sync(0xffffffffu, tmA, 1));
            tmA = fmaxf(tmA, __shfl_xor_sync(0xffffffffu, tmA, 2));
            tmB = fmaxf(tmB, __shfl_xor_sync(0xffffffffu, tmB, 1));
            tmB = fmaxf(tmB, __shfl_xor_sync(0xffffffffu, tmB, 2));
            const float mnA = fmaxf(mA, tmA), mnB = fmaxf(mB, tmB);
            const float aA = __expf(mA - mnA), aB = __expf(mB - mnB);
            float sumA = 0.f, sumB = 0.f;
            #pragma unroll
            for (int nt = 0; nt < 8; nt++) {
                S[nt][0] = __expf(S[nt][0] - mnA);
                S[nt][1] = __expf(S[nt][1] - mnA);
                S[nt][2] = __expf(S[nt][2] - mnB);
                S[nt][3] = __expf(S[nt][3] - mnB);
                sumA += S[nt][0] + S[nt][1];
                sumB += S[nt][2] + S[nt][3];
            }
            sumA += __shfl_xor_sync(0xffffffffu, sumA, 1);
            sumA += __shfl_xor_sync(0xffffffffu, sumA, 2);
            sumB += __shfl_xor_sync(0xffffffffu, sumB, 1);
            sumB += __shfl_xor_sync(0xffffffffu, sumB, 2);
            lA = lA * aA + sumA;
            lB = lB * aB + sumB;
            mA = mnA; mB = mnB;
            #pragma unroll
            for (int nt = 0; nt < 8; nt++) {
                O[nt][0] *= aA; O[nt][1] *= aA;
                O[nt][2] *= aB; O[nt][3] *= aB;
            }

            const uint32_t vb = sb + 2 * FKV_TILE;
            #pragma unroll
            for (int ks = 0; ks < 4; ks++) {
                const int n0t = 2 * ks, n1t = 2 * ks + 1;
                uint32_t pah[4], pal[4];
                {
                    __nv_bfloat162 h0 = __float22bfloat162_rn(make_float2(S[n0t][0], S[n0t][1]));
                    __nv_bfloat162 h1 = __float22bfloat162_rn(make_float2(S[n0t][2], S[n0t][3]));
                    __nv_bfloat162 h2 = __float22bfloat162_rn(make_float2(S[n1t][0], S[n1t][1]));
                    __nv_bfloat162 h3 = __float22bfloat162_rn(make_float2(S[n1t][2], S[n1t][3]));
                    pah[0] = *reinterpret_cast<uint32_t*>(&h0);
                    pah[1] = *reinterpret_cast<uint32_t*>(&h1);
                    pah[2] = *reinterpret_cast<uint32_t*>(&h2);
                    pah[3] = *reinterpret_cast<uint32_t*>(&h3);
                    pal[0] = pack_bf16(S[n0t][0] - __bfloat162float(h0.x),
                                       S[n0t][1] - __bfloat162float(h0.y));
                    pal[1] = pack_bf16(S[n0t][2] - __bfloat162float(h1.x),
                                       S[n0t][3] - __bfloat162float(h1.y));
                    pal[2] = pack_bf16(S[n1t][0] - __bfloat162float(h2.x),
                                       S[n1t][1] - __bfloat162float(h2.y));
                    pal[3] = pack_bf16(S[n1t][2] - __bfloat162float(h3.x),
                                       S[n1t][3] - __bfloat162float(h3.y));
                }
                uint32_t V0h[8], V1h[8], V0l[8], V1l[8];
                #pragma unroll
                for (int q2 = 0; q2 < 4; q2++) {
                    const uint32_t off = bBaseOff + q2 * (16 * FROWB) + ks * 32;
                    ldsm_x4(V0h[q2*2], V1h[q2*2], V0h[q2*2+1], V1h[q2*2+1], vb + off);
                    ldsm_x4(V0l[q2*2], V1l[q2*2], V0l[q2*2+1], V1l[q2*2+1],
                            vb + FKV_TILE + off);
                }
                #pragma unroll
                for (int nt = 0; nt < 8; nt++) {
                    float* c = O[nt];
                    mma16816(c[0], c[1], c[2], c[3],
                             pah[0], pah[1], pah[2], pah[3], V0h[nt], V1h[nt]);
                    mma16816(c[0], c[1], c[2], c[3],
                             pah[0], pah[1], pah[2], pah[3], V0l[nt], V1l[nt]);
                    mma16816(c[0], c[1], c[2], c[3],
                             pal[0], pal[1], pal[2], pal[3], V0h[nt], V1h[nt]);
                }
            }
        }
        __syncthreads();
        if (n + 2 < nkv) pref_kv(n + 2);
        asm volatile("cp.async.commit_group;" ::: "memory");
    }

    const float iA = 1.f / lA, iB = 1.f / lB;
    #pragma unroll
    for (int nt = 0; nt < 8; nt++) {
        const size_t d0 = (size_t)h * 64 + nt * 8 + qk;
        store_hl(yh, yl, ((size_t)b * TT + row0) * CC + d0, O[nt][0] * iA, O[nt][1] * iA);
        store_hl(yh, yl, ((size_t)b * TT + row1) * CC + d0, O[nt][2] * iB, O[nt][3] * iB);
    }
}

// ---------------- launch ---------------------------------------------------
extern "C" void kernel_launch(void* const* d_in, const int* in_sizes, int n_in,
                              void* d_out, int out_size)
{
    const float* x   = (const float*)d_in[0];
    const float* Wq  = (const float*)d_in[1];
    const float* Wkv = (const float*)d_in[2];
    const float* Wc  = (const float*)d_in[3];
    float* out = (float*)d_out;

    float *gc, *gs;
    __nv_bfloat16 *xh, *xl, *yh, *yl, *wh, *wl, *wch, *wcl;
    __nv_bfloat16 *qh, *ql, *kh, *kl, *vth, *vtl;
    cudaGetSymbolAddress((void**)&gc, g_cos);
    cudaGetSymbolAddress((void**)&gs, g_sin);
    cudaGetSymbolAddress((void**)&xh, g_xh);
    cudaGetSymbolAddress((void**)&xl, g_xl);
    cudaGetSymbolAddress((void**)&yh, g_yh);
    cudaGetSymbolAddress((void**)&yl, g_yl);
    cudaGetSymbolAddress((void**)&wh, g_wh);
    cudaGetSymbolAddress((void**)&wl, g_wl);
    cudaGetSymbolAddress((void**)&wch, g_wch);
    cudaGetSymbolAddress((void**)&wcl, g_wcl);
    cudaGetSymbolAddress((void**)&qh, g_qh);
    cudaGetSymbolAddress((void**)&ql, g_ql);
    cudaGetSymbolAddress((void**)&kh, g_kh);
    cudaGetSymbolAddress((void**)&kl, g_kl);
    cudaGetSymbolAddress((void**)&vth, g_vth);
    cudaGetSymbolAddress((void**)&vtl, g_vtl);

    cudaFuncSetAttribute(gemm_kernel_mma, cudaFuncAttributeMaxDynamicSharedMemorySize, SMEM_DYN);
    cudaFuncSetAttribute(flash_mma_kernel, cudaFuncAttributeMaxDynamicSharedMemorySize, FSMEM);

    rope_table_kernel<<<(TT * 32 + 255) / 256, 256>>>(gc, gs);

    // split x
    {
        int n4 = MM * GK / 4;
        split_kernel<<<(n4 + 255) / 256, 256>>>((const float4*)x, (uint2*)xh, (uint2*)xl, n4);
    }
    // transpose-split weights into combined [Wq^T; Wkv^T] and Wc^T
    transpose_split_kernel<<<dim3(CC / 32, GK / 32), dim3(32, 8)>>>(Wq, wh, wl, CC);
    transpose_split_kernel<<<dim3(2 * CC / 32, GK / 32), dim3(32, 8)>>>(
        Wkv, wh + (size_t)CC * GK, wl + (size_t)CC * GK, 2 * CC);
    transpose_split_kernel<<<dim3(CC / 32, GK / 32), dim3(32, 8)>>>(Wc, wch, wcl, CC);

    // fused QKV GEMM: [8192,1024] x [1024,3072] with RoPE/convert epilogue
    gemm_kernel_mma<<<dim3(3 * CC / 128, MM / 128), 256, SMEM_DYN>>>(
        xh, xl, wh, wl, nullptr, 3 * CC, 1, gc, gs, qh, ql, kh, kl, vth, vtl);

    // attention (writes yh/yl directly)
    flash_mma_kernel<<<dim3(TT / 128, HH, BB), 256, FSMEM>>>(qh, ql, kh, kl, vth, vtl, yh, yl);

    // out = y @ Wc
    gemm_kernel_mma<<<dim3(CC / 128, MM / 128), 256, SMEM_DYN>>>(
        yh, yl, wch, wcl, out, CC, 0, nullptr, nullptr,
        nullptr, nullptr, nullptr, nullptr, nullptr, nullptr);
}

// round 6
// speedup vs baseline: 3.2217x; 1.0054x over previous
#include <cuda_runtime.h>
#include <cuda_bf16.h>
#include <math.h>
#include <stdint.h>

#define BB 4
#define TT 2048
#define HH 16
#define DD 64
#define CC (HH*DD)      // 1024
#define MM (BB*TT)      // 8192
#define GK 1024         // K of all GEMMs

// ---------------- scratch (device globals; no allocation allowed) ----------
__device__ __align__(256) float g_cos[TT * 32];
__device__ __align__(256) float g_sin[TT * 32];

// bf16 split operands
__device__ __align__(256) __nv_bfloat16 g_xh[(size_t)MM * GK];
__device__ __align__(256) __nv_bfloat16 g_xl[(size_t)MM * GK];
__device__ __align__(256) __nv_bfloat16 g_yh[(size_t)MM * GK];
__device__ __align__(256) __nv_bfloat16 g_yl[(size_t)MM * GK];
// attention operands [B,H,T,D] (q,k) and [B,H,D,T] (v transposed)
__device__ __align__(256) __nv_bfloat16 g_qh[(size_t)BB*HH*TT*DD];
__device__ __align__(256) __nv_bfloat16 g_ql[(size_t)BB*HH*TT*DD];
__device__ __align__(256) __nv_bfloat16 g_kh[(size_t)BB*HH*TT*DD];
__device__ __align__(256) __nv_bfloat16 g_kl[(size_t)BB*HH*TT*DD];
__device__ __align__(256) __nv_bfloat16 g_vth[(size_t)BB*HH*TT*DD];
__device__ __align__(256) __nv_bfloat16 g_vtl[(size_t)BB*HH*TT*DD];
// transposed weights [N, K]: combined [Wq^T; Wk^T; Wv^T] = [3C, K]
__device__ __align__(256) __nv_bfloat16 g_wh[(size_t)3 * CC * GK];
__device__ __align__(256) __nv_bfloat16 g_wl[(size_t)3 * CC * GK];
__device__ __align__(256) __nv_bfloat16 g_wch[(size_t)CC * GK];
__device__ __align__(256) __nv_bfloat16 g_wcl[(size_t)CC * GK];

// ---------------- helpers ----------------------------------------------------
__device__ __forceinline__ uint32_t smem_u32(const void* p) {
    return (uint32_t)__cvta_generic_to_shared(p);
}

__device__ __forceinline__ void cp_async16(uint32_t saddr, const void* gaddr) {
    asm volatile("cp.async.cg.shared.global [%0], [%1], 16;" :: "r"(saddr), "l"(gaddr) : "memory");
}

__device__ __forceinline__ void ldsm_x4(uint32_t& r0, uint32_t& r1, uint32_t& r2, uint32_t& r3,
                                        uint32_t addr) {
    asm volatile("ldmatrix.sync.aligned.m8n8.x4.shared.b16 {%0,%1,%2,%3}, [%4];"
                 : "=r"(r0), "=r"(r1), "=r"(r2), "=r"(r3) : "r"(addr));
}

__device__ __forceinline__ void mma16816(float& c0, float& c1, float& c2, float& c3,
                                         uint32_t a0, uint32_t a1, uint32_t a2, uint32_t a3,
                                         uint32_t b0, uint32_t b1) {
    asm volatile(
        "mma.sync.aligned.m16n8k16.row.col.f32.bf16.bf16.f32 "
        "{%0,%1,%2,%3}, {%4,%5,%6,%7}, {%8,%9}, {%0,%1,%2,%3};"
        : "+f"(c0), "+f"(c1), "+f"(c2), "+f"(c3)
        : "r"(a0), "r"(a1), "r"(a2), "r"(a3), "r"(b0), "r"(b1));
}

__device__ __forceinline__ uint32_t pack_bf16(float a, float b) {
    __nv_bfloat162 t = __float22bfloat162_rn(make_float2(a, b));
    return *reinterpret_cast<uint32_t*>(&t);
}

__device__ __forceinline__ void store_hl(__nv_bfloat16* hi, __nv_bfloat16* lo,
                                         size_t off, float a, float b) {
    __nv_bfloat162 h = __float22bfloat162_rn(make_float2(a, b));
    float ra = a - __bfloat162float(h.x);
    float rb = b - __bfloat162float(h.y);
    __nv_bfloat162 l = __float22bfloat162_rn(make_float2(ra, rb));
    *reinterpret_cast<__nv_bfloat162*>(hi + off) = h;
    *reinterpret_cast<__nv_bfloat162*>(lo + off) = l;
}

// ---------------- HMMA GEMM: C = (Ah+Al) @ (Bh+Bl)^T -----------------------
#define BK 32
#define NUMK (GK / BK)          // 32
#define ROWB 80                 // 64B data + 16B pad
#define TILE_B (128 * ROWB)     // 10240
#define STAGE_B (4 * TILE_B)    // 40960
#define NSTAGE 3
#define SMEM_DYN (NSTAGE * STAGE_B)   // 122880

__global__ void __launch_bounds__(256, 1)
gemm_kernel_mma(const __nv_bfloat16* __restrict__ Ah, const __nv_bfloat16* __restrict__ Al,
                const __nv_bfloat16* __restrict__ Bh, const __nv_bfloat16* __restrict__ Bl,
                float* __restrict__ Cm, int Ndim, int mode,
                const float* __restrict__ gcos, const float* __restrict__ gsin,
                __nv_bfloat16* __restrict__ qh, __nv_bfloat16* __restrict__ ql,
                __nv_bfloat16* __restrict__ kh, __nv_bfloat16* __restrict__ kl,
                __nv_bfloat16* __restrict__ vth, __nv_bfloat16* __restrict__ vtl)
{
    extern __shared__ char smem_raw[];
    const uint32_t sbase = smem_u32(smem_raw);

    const int tid  = threadIdx.x;
    const int lane = tid & 31;
    const int warp = tid >> 5;
    const int mw   = warp & 1;
    const int nw   = warp >> 1;
    const int m0 = blockIdx.y * 128;
    const int n0 = blockIdx.x * 128;

    const __nv_bfloat16* tp[4] = { Ah, Al, Bh, Bl };

    auto prefetch = [&](int kc) {
        const uint32_t sstage = sbase + (uint32_t)(kc % NSTAGE) * STAGE_B;
        #pragma unroll
        for (int i = 0; i < 8; i++) {
            const int c = i * 256 + tid;
            const int tile = c >> 9;
            const int r = (c >> 2) & 127;
            const int j = c & 3;
            const int row0 = (tile < 2) ? m0 : n0;
            const __nv_bfloat16* g = tp[tile] + (size_t)(row0 + r) * GK + kc * BK + j * 8;
            cp_async16(sstage + tile * TILE_B + r * ROWB + j * 16, g);
        }
    };

    prefetch(0);
    asm volatile("cp.async.commit_group;" ::: "memory");
    prefetch(1);
    asm volatile("cp.async.commit_group;" ::: "memory");

    const uint32_t aBase = (uint32_t)((mw * 64 + (lane & 15)) * ROWB + ((lane >> 4) << 4));
    const uint32_t bBase = (uint32_t)((nw * 32 + (lane & 7) + ((lane >> 4) << 3)) * ROWB
                                      + (((lane >> 3) & 1) << 4));

    float acc[4][4][4];
    #pragma unroll
    for (int mt = 0; mt < 4; mt++)
        #pragma unroll
        for (int nt = 0; nt < 4; nt++)
            #pragma unroll
            for (int e = 0; e < 4; e++) acc[mt][nt][e] = 0.f;

    for (int kc = 0; kc < NUMK; kc++) {
        asm volatile("cp.async.wait_group 1;" ::: "memory");
        __syncthreads();

        if (kc + 2 < NUMK) prefetch(kc + 2);
        asm volatile("cp.async.commit_group;" ::: "memory");

        const uint32_t sstage = sbase + (uint32_t)(kc % NSTAGE) * STAGE_B;
        const uint32_t aTile = sstage;
        const uint32_t bTile = sstage + 2 * TILE_B;

        #pragma unroll
        for (int ks = 0; ks < 2; ks++) {
            const uint32_t kb = ks * 32;
            uint32_t ah[4][4], al[4][4];
            #pragma unroll
            for (int mt = 0; mt < 4; mt++) {
                const uint32_t off = aBase + mt * (16 * ROWB) + kb;
                ldsm_x4(ah[mt][0], ah[mt][1], ah[mt][2], ah[mt][3], aTile + off);
                ldsm_x4(al[mt][0], al[mt][1], al[mt][2], al[mt][3], aTile + TILE_B + off);
            }
            uint32_t bh[4][2], bl[4][2];
            #pragma unroll
            for (int np = 0; np < 2; np++) {
                const uint32_t off = bBase + np * (16 * ROWB) + kb;
                ldsm_x4(bh[np*2][0], bh[np*2][1], bh[np*2+1][0], bh[np*2+1][1], bTile + off);
                ldsm_x4(bl[np*2][0], bl[np*2][1], bl[np*2+1][0], bl[np*2+1][1],
                        bTile + TILE_B + off);
            }
            #pragma unroll
            for (int mt = 0; mt < 4; mt++) {
                #pragma unroll
                for (int nt = 0; nt < 4; nt++) {
                    float* c = acc[mt][nt];
                    mma16816(c[0], c[1], c[2], c[3],
                             ah[mt][0], ah[mt][1], ah[mt][2], ah[mt][3],
                             bh[nt][0], bh[nt][1]);
                    mma16816(c[0], c[1], c[2], c[3],
                             ah[mt][0], ah[mt][1], ah[mt][2], ah[mt][3],
                             bl[nt][0], bl[nt][1]);
                    mma16816(c[0], c[1], c[2], c[3],
                             al[mt][0], al[mt][1], al[mt][2], al[mt][3],
                             bh[nt][0], bh[nt][1]);
                }
            }
        }
        __syncthreads();
    }

    if (mode == 0) {
        const int rbase = m0 + mw * 64 + (lane >> 2);
        const int cbase = n0 + nw * 32 + ((lane & 3) << 1);
        #pragma unroll
        for (int mt = 0; mt < 4; mt++) {
            #pragma unroll
            for (int nt = 0; nt < 4; nt++) {
                float* c = acc[mt][nt];
                float* p0 = Cm + (size_t)(rbase + mt * 16) * Ndim + cbase + nt * 8;
                float* p1 = p0 + (size_t)8 * Ndim;
                *reinterpret_cast<float2*>(p0) = make_float2(c[0], c[1]);
                *reinterpret_cast<float2*>(p1) = make_float2(c[2], c[3]);
            }
        }
        return;
    }

    // ---- fused QKV epilogue ----
    float* sm = reinterpret_cast<float*>(smem_raw);
    const int rloc = mw * 64 + (lane >> 2);
    const int cloc = nw * 32 + ((lane & 3) << 1);
    #pragma unroll
    for (int mt = 0; mt < 4; mt++) {
        #pragma unroll
        for (int nt = 0; nt < 4; nt++) {
            float* c = acc[mt][nt];
            float* p0 = sm + (size_t)(rloc + mt * 16) * 132 + cloc + nt * 8;
            *reinterpret_cast<float2*>(p0)       = make_float2(c[0], c[1]);
            *reinterpret_cast<float2*>(p0 + 8 * 132) = make_float2(c[2], c[3]);
        }
    }
    __syncthreads();

    const int ct = blockIdx.x;
    const int b = m0 >> 11;
    const int t_base = m0 & (TT - 1);

    if (ct < 16) {
        const bool isQ = (ct < 8);
        const float qs = isQ ? 0.125f : 1.0f;
        __nv_bfloat16* dh = isQ ? qh : kh;
        __nv_bfloat16* dl = isQ ? ql : kl;
        const int hbase = (isQ ? ct : (ct - 8)) * 2;
        #pragma unroll
        for (int i = 0; i < 16; i++) {
            const int idx = i * 256 + tid;
            const int dp = (idx & 15) * 2;
            const int hs = (idx >> 4) & 1;
            const int r  = idx >> 5;
            const int t  = t_base + r;
            const float c0 = gcos[t * 32 + dp],  c1 = gcos[t * 32 + dp + 1];
            const float s0 = gsin[t * 32 + dp],  s1 = gsin[t * 32 + dp + 1];
            const float* row = sm + (size_t)r * 132 + hs * 64;
            const float x1 = row[dp],      x1b = row[dp + 1];
            const float x2 = row[dp + 32], x2b = row[dp + 33];
            const float o0 = (x1 * c0 - x2 * s0) * qs;
            const float o1 = (x1b * c1 - x2b * s1) * qs;
            const float o2 = (x2 * c0 + x1 * s0) * qs;
            const float o3 = (x2b * c1 + x1b * s1) * qs;
            const size_t base = (((size_t)b * HH + hbase + hs) * TT + t) * 64;
            store_hl(dh, dl, base + dp, o0, o1);
            store_hl(dh, dl, base + dp + 32, o2, o3);
        }
    } else {
        const int hbase = (ct - 16) * 2;
        #pragma unroll
        for (int i = 0; i < 32; i++) {
            const int idx = i * 256 + tid;
            const int c  = idx >> 6;
            const int t2 = idx & 63;
            const int hs = c >> 6;
            const int d  = c & 63;
            const float a  = sm[(size_t)(2 * t2) * 132 + c];
            const float bv = sm[(size_t)(2 * t2 + 1) * 132 + c];
            const int t = t_base + 2 * t2;
            store_hl(vth, vtl,
                     (((size_t)b * HH + hbase + hs) * 64 + d) * TT + t, a, bv);
        }
    }
}

// ---------------- fp32 -> bf16 hi/lo split ---------------------------------
__global__ void split_kernel(const float4* __restrict__ in,
                             uint2* __restrict__ hi, uint2* __restrict__ lo, int n4)
{
    int i = blockIdx.x * blockDim.x + threadIdx.x;
    if (i >= n4) return;
    float4 v = in[i];
    float vv[4] = { v.x, v.y, v.z, v.w };
    unsigned short h[4], l[4];
    #pragma unroll
    for (int k = 0; k < 4; k++) {
        __nv_bfloat16 hb = __float2bfloat16(vv[k]);
        __nv_bfloat16 lb = __float2bfloat16(vv[k] - __bfloat162float(hb));
        h[k] = __bfloat16_as_ushort(hb);
        l[k] = __bfloat16_as_ushort(lb);
    }
    uint2 ho, lo_;
    ho.x = (uint32_t)h[0] | ((uint32_t)h[1] << 16);
    ho.y = (uint32_t)h[2] | ((uint32_t)h[3] << 16);
    lo_.x = (uint32_t)l[0] | ((uint32_t)l[1] << 16);
    lo_.y = (uint32_t)l[2] | ((uint32_t)l[3] << 16);
    hi[i] = ho;
    lo[i] = lo_;
}

// -------- combined W transpose-split: all three weights in ONE launch ------
// grid.x: 0..31 -> Wq cols, 32..95 -> Wkv cols, 96..127 -> Wc cols; grid.y: k-tiles
__global__ void transpose_split_all(const float* __restrict__ Wq,
                                    const float* __restrict__ Wkv,
                                    const float* __restrict__ Wc,
                                    __nv_bfloat16* __restrict__ wh,
                                    __nv_bfloat16* __restrict__ wl,
                                    __nv_bfloat16* __restrict__ wch,
                                    __nv_bfloat16* __restrict__ wcl)
{
    __shared__ float t[32][33];
    const int nx = blockIdx.x;
    const int k0 = blockIdx.y * 32;
    const float* W;
    __nv_bfloat16 *Th, *Tl;
    int N, n0;
    if (nx < 32)       { W = Wq;  N = CC;     n0 = nx * 32;        Th = wh;  Tl = wl; }
    else if (nx < 96)  { W = Wkv; N = 2 * CC; n0 = (nx - 32) * 32;
                         Th = wh + (size_t)CC * GK; Tl = wl + (size_t)CC * GK; }
    else               { W = Wc;  N = CC;     n0 = (nx - 96) * 32; Th = wch; Tl = wcl; }

    const int tx = threadIdx.x, ty = threadIdx.y;
    #pragma unroll
    for (int i = 0; i < 32; i += 8)
        t[ty + i][tx] = W[(size_t)(k0 + ty + i) * N + n0 + tx];
    __syncthreads();
    #pragma unroll
    for (int i = 0; i < 32; i += 8) {
        float v = t[tx][ty + i];
        __nv_bfloat16 hb = __float2bfloat16(v);
        size_t o = (size_t)(n0 + ty + i) * GK + k0 + tx;
        Th[o] = hb;
        Tl[o] = __float2bfloat16(v - __bfloat162float(hb));
    }
}

// ---------------- RoPE table ------------------------------------------------
__global__ void rope_table_kernel(float* __restrict__ gcos, float* __restrict__ gsin)
{
    int i = blockIdx.x * blockDim.x + threadIdx.x;
    if (i >= TT * 32) return;
    int t = i >> 5;
    int d = i & 31;
    float inv = (float)exp(-((double)(2 * d) / 64.0) * log(10000.0));
    float ang = (float)t * inv;
    gcos[i] = cosf(ang);
    gsin[i] = sinf(ang);
}

// ---------------- Flash attention on HMMA (bf16 hi/lo, fp32 accum) --------
#define FROWB 144
#define FQ_TILE (128 * FROWB)        // 18432
#define FKV_TILE (64 * FROWB)        // 9216
#define FSTAGE (4 * FKV_TILE)        // 36864
#define FSMEM (2 * FQ_TILE + 2 * FSTAGE)   // 110592

__global__ void __launch_bounds__(256, 1)
flash_mma_kernel(const __nv_bfloat16* __restrict__ qh, const __nv_bfloat16* __restrict__ ql,
                 const __nv_bfloat16* __restrict__ kh, const __nv_bfloat16* __restrict__ kl,
                 const __nv_bfloat16* __restrict__ vth, const __nv_bfloat16* __restrict__ vtl,
                 __nv_bfloat16* __restrict__ yh, __nv_bfloat16* __restrict__ yl)
{
    extern __shared__ char smem_raw[];
    const uint32_t sQ  = smem_u32(smem_raw);
    const uint32_t sKV = sQ + 2 * FQ_TILE;

    const int tid = threadIdx.x, lane = tid & 31, warp = tid >> 5;
    // heavy-first: large t0 scheduled first for better wave packing (causal)
    const int t0 = (gridDim.x - 1 - blockIdx.x) * 128;
    const int h = blockIdx.y, b = blockIdx.z;
    const size_t bh = (size_t)b * HH + h;
    const int nkv = t0 / 64 + 2;

    #pragma unroll
    for (int i = 0; i < 8; i++) {
        int idx = i * 256 + tid;
        int arr = idx >> 10, r = (idx >> 3) & 127, j = idx & 7;
        const __nv_bfloat16* g = (arr ? ql : qh) + (bh * TT + t0 + r) * 64 + j * 8;
        cp_async16(sQ + arr * FQ_TILE + r * FROWB + j * 16, g);
    }
    auto pref_kv = [&](int n) {
        const uint32_t sb = sKV + (uint32_t)(n & 1) * FSTAGE;
        const int j0 = n * 64;
        #pragma unroll
        for (int i = 0; i < 8; i++) {
            int idx = i * 256 + tid;
            int arr = idx >> 9, r = (idx >> 3) & 63, j = idx & 7;
            const __nv_bfloat16* g;
            if (arr == 0)      g = kh  + (bh * TT + j0 + r) * 64 + j * 8;
            else if (arr == 1) g = kl  + (bh * TT + j0 + r) * 64 + j * 8;
            else if (arr == 2) g = vth + (bh * 64 + r) * TT + j0 + j * 8;
            else               g = vtl + (bh * 64 + r) * TT + j0 + j * 8;
            cp_async16(sb + arr * FKV_TILE + r * FROWB + j * 16, g);
        }
    };
    pref_kv(0);
    asm volatile("cp.async.commit_group;" ::: "memory");
    pref_kv(1);
    asm volatile("cp.async.commit_group;" ::: "memory");

    const int wrow = t0 + warp * 16;
    const int gr = lane >> 2;
    const int qk = (lane & 3) * 2;
    const int row0 = wrow + gr;
    const int row1 = row0 + 8;

    uint32_t qa_h[4][4], qa_l[4][4];
    float O[8][4];
    #pragma unroll
    for (int nt = 0; nt < 8; nt++)
        #pragma unroll
        for (int e = 0; e < 4; e++) O[nt][e] = 0.f;
    float mA = -1e30f, mB = -1e30f, lA = 0.f, lB = 0.f;

    const uint32_t bBaseOff = ((lane & 7) + ((lane >> 4) << 3)) * FROWB + (((lane >> 3) & 1) << 4);

    for (int n = 0; n < nkv; n++) {
        asm volatile("cp.async.wait_group 1;" ::: "memory");
        __syncthreads();

        if (n == 0) {
            const uint32_t qb = sQ + (warp * 16 + (lane & 15)) * FROWB + ((lane >> 4) << 4);
            #pragma unroll
            for (int ks = 0; ks < 4; ks++) {
                ldsm_x4(qa_h[ks][0], qa_h[ks][1], qa_h[ks][2], qa_h[ks][3], qb + ks * 32);
                ldsm_x4(qa_l[ks][0], qa_l[ks][1], qa_l[ks][2], qa_l[ks][3],
                        qb + FQ_TILE + ks * 32);
            }
        }

        const int j0 = n * 64;
        if (j0 <= wrow + 15) {
            const uint32_t sb = sKV + (uint32_t)(n & 1) * FSTAGE;
            float S[8][4];
            #pragma unroll
            for (int nt = 0; nt < 8; nt++)
                #pragma unroll
                for (int e = 0; e < 4; e++) S[nt][e] = 0.f;

            #pragma unroll
            for (int ks = 0; ks < 4; ks++) {
                uint32_t B0h[8], B1h[8], B0l[8], B1l[8];
                #pragma unroll
                for (int q2 = 0; q2 < 4; q2++) {
                    const uint32_t off = bBaseOff + q2 * (16 * FROWB) + ks * 32;
                    ldsm_x4(B0h[q2*2], B1h[q2*2], B0h[q2*2+1], B1h[q2*2+1], sb + off);
                    ldsm_x4(B0l[q2*2], B1l[q2*2], B0l[q2*2+1], B1l[q2*2+1],
                            sb + FKV_TILE + off);
                }
                #pragma unroll
                for (int nt = 0; nt < 8; nt++) {
                    float* c = S[nt];
                    mma16816(c[0], c[1], c[2], c[3],
                             qa_h[ks][0], qa_h[ks][1], qa_h[ks][2], qa_h[ks][3],
                             B0h[nt], B1h[nt]);
                    mma16816(c[0], c[1], c[2], c[3],
                             qa_h[ks][0], qa_h[ks][1], qa_h[ks][2], qa_h[ks][3],
                             B0l[nt], B1l[nt]);
                    mma16816(c[0], c[1], c[2], c[3],
                             qa_l[ks][0], qa_l[ks][1], qa_l[ks][2], qa_l[ks][3],
                             B0h[nt], B1h[nt]);
                }
            }

            if (j0 + 63 > wrow) {
                #pragma unroll
                for (int nt = 0; nt < 8; nt++) {
                    const int c0 = j0 + nt * 8 + qk;
                    if (c0 > row0)     S[nt][0] = -1e30f;
                    if (c0 + 1 > row0) S[nt][1] = -1e30f;
                    if (c0 > row1)     S[nt][2] = -1e30f;
                    if (c0 + 1 > row1) S[nt][3] = -1e30f;
                }
            }

            float tmA = -1e30f, tmB = -1e30f;
            #pragma unroll
            for (int nt = 0; nt < 8; nt++) {
                tmA = fmaxf(tmA, fmaxf(S[nt][0], S[nt][1]));
                tmB = fmaxf(tmB, fmaxf(S[nt][2], S[nt][3]));
            }
            tmA = fmaxf(tmA, __shfl_xor_sync(0xffffffffu, tmA, 1));
            tmA = fmaxf(tmA, __shfl_xor_sync(0xffffffffu, tmA, 2));
            tmB = fmaxf(tmB, __shfl_xor_sync(0xffffffffu, tmB, 1));
            tmB = fmaxf(tmB, __shfl_xor_sync(0xffffffffu, tmB, 2));
            const float mnA = fmaxf(mA, tmA), mnB = fmaxf(mB, tmB);
            const float aA = __expf(mA - mnA), aB = __expf(mB - mnB);
            float sumA = 0.f, sumB = 0.f;
            #pragma unroll
            for (int nt = 0; nt < 8; nt++) {
                S[nt][0] = __expf(S[nt][0] - mnA);
                S[nt][1] = __expf(S[nt][1] - mnA);
                S[nt][2] = __expf(S[nt][2] - mnB);
                S[nt][3] = __expf(S[nt][3] - mnB);
                sumA += S[nt][0] + S[nt][1];
                sumB += S[nt][2] + S[nt][3];
            }
            sumA += __shfl_xor_sync(0xffffffffu, sumA, 1);
            sumA += __shfl_xor_sync(0xffffffffu, sumA, 2);
            sumB += __shfl_xor_sync(0xffffffffu, sumB, 1);
            sumB += __shfl_xor_sync(0xffffffffu, sumB, 2);
            lA = lA * aA + sumA;
            lB = lB * aB + sumB;
            mA = mnA; mB = mnB;
            #pragma unroll
            for (int nt = 0; nt < 8; nt++) {
                O[nt][0] *= aA; O[nt][1] *= aA;
                O[nt][2] *= aB; O[nt][3] *= aB;
            }

            const uint32_t vb = sb + 2 * FKV_TILE;
            #pragma unroll
            for (int ks = 0; ks < 4; ks++) {
                const int n0t = 2 * ks, n1t = 2 * ks + 1;
                uint32_t pah[4], pal[4];
                {
                    __nv_bfloat162 h0 = __float22bfloat162_rn(make_float2(S[n0t][0], S[n0t][1]));
                    __nv_bfloat162 h1 = __float22bfloat162_rn(make_float2(S[n0t][2], S[n0t][3]));
                    __nv_bfloat162 h2 = __float22bfloat162_rn(make_float2(S[n1t][0], S[n1t][1]));
                    __nv_bfloat162 h3 = __float22bfloat162_rn(make_float2(S[n1t][2], S[n1t][3]));
                    pah[0] = *reinterpret_cast<uint32_t*>(&h0);
                    pah[1] = *reinterpret_cast<uint32_t*>(&h1);
                    pah[2] = *reinterpret_cast<uint32_t*>(&h2);
                    pah[3] = *reinterpret_cast<uint32_t*>(&h3);
                    pal[0] = pack_bf16(S[n0t][0] - __bfloat162float(h0.x),
                                       S[n0t][1] - __bfloat162float(h0.y));
                    pal[1] = pack_bf16(S[n0t][2] - __bfloat162float(h1.x),
                                       S[n0t][3] - __bfloat162float(h1.y));
                    pal[2] = pack_bf16(S[n1t][0] - __bfloat162float(h2.x),
                                       S[n1t][1] - __bfloat162float(h2.y));
                    pal[3] = pack_bf16(S[n1t][2] - __bfloat162float(h3.x),
                                       S[n1t][3] - __bfloat162float(h3.y));
                }
                uint32_t V0h[8], V1h[8], V0l[8], V1l[8];
                #pragma unroll
                for (int q2 = 0; q2 < 4; q2++) {
                    const uint32_t off = bBaseOff + q2 * (16 * FROWB) + ks * 32;
                    ldsm_x4(V0h[q2*2], V1h[q2*2], V0h[q2*2+1], V1h[q2*2+1], vb + off);
                    ldsm_x4(V0l[q2*2], V1l[q2*2], V0l[q2*2+1], V1l[q2*2+1],
                            vb + FKV_TILE + off);
                }
                #pragma unroll
                for (int nt = 0; nt < 8; nt++) {
                    float* c = O[nt];
                    mma16816(c[0], c[1], c[2], c[3],
                             pah[0], pah[1], pah[2], pah[3], V0h[nt], V1h[nt]);
                    mma16816(c[0], c[1], c[2], c[3],
                             pah[0], pah[1], pah[2], pah[3], V0l[nt], V1l[nt]);
                    mma16816(c[0], c[1], c[2], c[3],
                             pal[0], pal[1], pal[2], pal[3], V0h[nt], V1h[nt]);
                }
            }
        }
        __syncthreads();
        if (n + 2 < nkv) pref_kv(n + 2);
        asm volatile("cp.async.commit_group;" ::: "memory");
    }

    const float iA = 1.f / lA, iB = 1.f / lB;
    #pragma unroll
    for (int nt = 0; nt < 8; nt++) {
        const size_t d0 = (size_t)h * 64 + nt * 8 + qk;
        store_hl(yh, yl, ((size_t)b * TT + row0) * CC + d0, O[nt][0] * iA, O[nt][1] * iA);
        store_hl(yh, yl, ((size_t)b * TT + row1) * CC + d0, O[nt][2] * iB, O[nt][3] * iB);
    }
}

// ---------------- launch ---------------------------------------------------
extern "C" void kernel_launch(void* const* d_in, const int* in_sizes, int n_in,
                              void* d_out, int out_size)
{
    const float* x   = (const float*)d_in[0];
    const float* Wq  = (const float*)d_in[1];
    const float* Wkv = (const float*)d_in[2];
    const float* Wc  = (const float*)d_in[3];
    float* out = (float*)d_out;

    float *gc, *gs;
    __nv_bfloat16 *xh, *xl, *yh, *yl, *wh, *wl, *wch, *wcl;
    __nv_bfloat16 *qh, *ql, *kh, *kl, *vth, *vtl;
    cudaGetSymbolAddress((void**)&gc, g_cos);
    cudaGetSymbolAddress((void**)&gs, g_sin);
    cudaGetSymbolAddress((void**)&xh, g_xh);
    cudaGetSymbolAddress((void**)&xl, g_xl);
    cudaGetSymbolAddress((void**)&yh, g_yh);
    cudaGetSymbolAddress((void**)&yl, g_yl);
    cudaGetSymbolAddress((void**)&wh, g_wh);
    cudaGetSymbolAddress((void**)&wl, g_wl);
    cudaGetSymbolAddress((void**)&wch, g_wch);
    cudaGetSymbolAddress((void**)&wcl, g_wcl);
    cudaGetSymbolAddress((void**)&qh, g_qh);
    cudaGetSymbolAddress((void**)&ql, g_ql);
    cudaGetSymbolAddress((void**)&kh, g_kh);
    cudaGetSymbolAddress((void**)&kl, g_kl);
    cudaGetSymbolAddress((void**)&vth, g_vth);
    cudaGetSymbolAddress((void**)&vtl, g_vtl);

    cudaFuncSetAttribute(gemm_kernel_mma, cudaFuncAttributeMaxDynamicSharedMemorySize, SMEM_DYN);
    cudaFuncSetAttribute(flash_mma_kernel, cudaFuncAttributeMaxDynamicSharedMemorySize, FSMEM);

    // #0
    rope_table_kernel<<<(TT * 32 + 255) / 256, 256>>>(gc, gs);
    // #1: split x
    {
        int n4 = MM * GK / 4;
        split_kernel<<<(n4 + 255) / 256, 256>>>((const float4*)x, (uint2*)xh, (uint2*)xl, n4);
    }
    // #2: ALL weight transposes in one launch
    transpose_split_all<<<dim3(128, GK / 32), dim3(32, 8)>>>(Wq, Wkv, Wc, wh, wl, wch, wcl);

    // #3: fused QKV GEMM (this is the launch ncu captures)
    gemm_kernel_mma<<<dim3(3 * CC / 128, MM / 128), 256, SMEM_DYN>>>(
        xh, xl, wh, wl, nullptr, 3 * CC, 1, gc, gs, qh, ql, kh, kl, vth, vtl);

    // #4: attention (writes yh/yl directly)
    flash_mma_kernel<<<dim3(TT / 128, HH, BB), 256, FSMEM>>>(qh, ql, kh, kl, vth, vtl, yh, yl);

    // #5: out = y @ Wc
    gemm_kernel_mma<<<dim3(CC / 128, MM / 128), 256, SMEM_DYN>>>(
        yh, yl, wch, wcl, out, CC, 0, nullptr, nullptr,
        nullptr, nullptr, nullptr, nullptr, nullptr, nullptr);
}

// round 7
// speedup vs baseline: 3.5510x; 1.1022x over previous
#include <cuda_runtime.h>
#include <cuda_bf16.h>
#include <math.h>
#include <stdint.h>

#define BB 4
#define TT 2048
#define HH 16
#define DD 64
#define CC (HH*DD)      // 1024
#define MM (BB*TT)      // 8192
#define GK 1024         // K of all GEMMs

// ---------------- scratch (device globals; no allocation allowed) ----------
__device__ __align__(256) float g_cos[TT * 32];
__device__ __align__(256) float g_sin[TT * 32];

__device__ __align__(256) __nv_bfloat16 g_xh[(size_t)MM * GK];
__device__ __align__(256) __nv_bfloat16 g_xl[(size_t)MM * GK];
__device__ __align__(256) __nv_bfloat16 g_yh[(size_t)MM * GK];
__device__ __align__(256) __nv_bfloat16 g_yl[(size_t)MM * GK];
__device__ __align__(256) __nv_bfloat16 g_qh[(size_t)BB*HH*TT*DD];
__device__ __align__(256) __nv_bfloat16 g_ql[(size_t)BB*HH*TT*DD];
__device__ __align__(256) __nv_bfloat16 g_kh[(size_t)BB*HH*TT*DD];
__device__ __align__(256) __nv_bfloat16 g_kl[(size_t)BB*HH*TT*DD];
__device__ __align__(256) __nv_bfloat16 g_vth[(size_t)BB*HH*TT*DD];
__device__ __align__(256) __nv_bfloat16 g_vtl[(size_t)BB*HH*TT*DD];
__device__ __align__(256) __nv_bfloat16 g_wh[(size_t)3 * CC * GK];
__device__ __align__(256) __nv_bfloat16 g_wl[(size_t)3 * CC * GK];
__device__ __align__(256) __nv_bfloat16 g_wch[(size_t)CC * GK];
__device__ __align__(256) __nv_bfloat16 g_wcl[(size_t)CC * GK];

// ---------------- helpers ----------------------------------------------------
__device__ __forceinline__ uint32_t smem_u32(const void* p) {
    return (uint32_t)__cvta_generic_to_shared(p);
}

__device__ __forceinline__ void cp_async16(uint32_t saddr, const void* gaddr) {
    asm volatile("cp.async.cg.shared.global [%0], [%1], 16;" :: "r"(saddr), "l"(gaddr) : "memory");
}

__device__ __forceinline__ void ldsm_x4(uint32_t& r0, uint32_t& r1, uint32_t& r2, uint32_t& r3,
                                        uint32_t addr) {
    asm volatile("ldmatrix.sync.aligned.m8n8.x4.shared.b16 {%0,%1,%2,%3}, [%4];"
                 : "=r"(r0), "=r"(r1), "=r"(r2), "=r"(r3) : "r"(addr));
}

__device__ __forceinline__ void mma16816(float& c0, float& c1, float& c2, float& c3,
                                         uint32_t a0, uint32_t a1, uint32_t a2, uint32_t a3,
                                         uint32_t b0, uint32_t b1) {
    asm volatile(
        "mma.sync.aligned.m16n8k16.row.col.f32.bf16.bf16.f32 "
        "{%0,%1,%2,%3}, {%4,%5,%6,%7}, {%8,%9}, {%0,%1,%2,%3};"
        : "+f"(c0), "+f"(c1), "+f"(c2), "+f"(c3)
        : "r"(a0), "r"(a1), "r"(a2), "r"(a3), "r"(b0), "r"(b1));
}

__device__ __forceinline__ uint32_t pack_bf16(float a, float b) {
    __nv_bfloat162 t = __float22bfloat162_rn(make_float2(a, b));
    return *reinterpret_cast<uint32_t*>(&t);
}

__device__ __forceinline__ void store_hl(__nv_bfloat16* hi, __nv_bfloat16* lo,
                                         size_t off, float a, float b) {
    __nv_bfloat162 h = __float22bfloat162_rn(make_float2(a, b));
    float ra = a - __bfloat162float(h.x);
    float rb = b - __bfloat162float(h.y);
    __nv_bfloat162 l = __float22bfloat162_rn(make_float2(ra, rb));
    *reinterpret_cast<__nv_bfloat162*>(hi + off) = h;
    *reinterpret_cast<__nv_bfloat162*>(lo + off) = l;
}

// ---------------- HMMA GEMM: C = (Ah+Al) @ (Bh+Bl)^T -----------------------
// 2-stage cp.async pipeline, 2 CTAs/SM (smem 80KB, regs capped at 128).
#define BK 32
#define NUMK (GK / BK)          // 32
#define ROWB 80                 // 64B data + 16B pad
#define TILE_B (128 * ROWB)     // 10240
#define STAGE_B (4 * TILE_B)    // 40960
#define NSTAGE 2
#define SMEM_DYN (NSTAGE * STAGE_B)   // 81920

__global__ void __launch_bounds__(256, 2)
gemm_kernel_mma(const __nv_bfloat16* __restrict__ Ah, const __nv_bfloat16* __restrict__ Al,
                const __nv_bfloat16* __restrict__ Bh, const __nv_bfloat16* __restrict__ Bl,
                float* __restrict__ Cm, int Ndim, int mode,
                const float* __restrict__ gcos, const float* __restrict__ gsin,
                __nv_bfloat16* __restrict__ qh, __nv_bfloat16* __restrict__ ql,
                __nv_bfloat16* __restrict__ kh, __nv_bfloat16* __restrict__ kl,
                __nv_bfloat16* __restrict__ vth, __nv_bfloat16* __restrict__ vtl)
{
    extern __shared__ char smem_raw[];
    const uint32_t sbase = smem_u32(smem_raw);

    const int tid  = threadIdx.x;
    const int lane = tid & 31;
    const int warp = tid >> 5;
    const int mw   = warp & 1;
    const int nw   = warp >> 1;
    const int m0 = blockIdx.y * 128;
    const int n0 = blockIdx.x * 128;

    const __nv_bfloat16* tp[4] = { Ah, Al, Bh, Bl };

    auto prefetch = [&](int kc) {
        const uint32_t sstage = sbase + (uint32_t)(kc & 1) * STAGE_B;
        #pragma unroll
        for (int i = 0; i < 8; i++) {
            const int c = i * 256 + tid;
            const int tile = c >> 9;
            const int r = (c >> 2) & 127;
            const int j = c & 3;
            const int row0 = (tile < 2) ? m0 : n0;
            const __nv_bfloat16* g = tp[tile] + (size_t)(row0 + r) * GK + kc * BK + j * 8;
            cp_async16(sstage + tile * TILE_B + r * ROWB + j * 16, g);
        }
    };

    prefetch(0);
    asm volatile("cp.async.commit_group;" ::: "memory");
    prefetch(1);
    asm volatile("cp.async.commit_group;" ::: "memory");

    const uint32_t aBase = (uint32_t)((mw * 64 + (lane & 15)) * ROWB + ((lane >> 4) << 4));
    const uint32_t bBase = (uint32_t)((nw * 32 + (lane & 7) + ((lane >> 4) << 3)) * ROWB
                                      + (((lane >> 3) & 1) << 4));

    float acc[4][4][4];
    #pragma unroll
    for (int mt = 0; mt < 4; mt++)
        #pragma unroll
        for (int nt = 0; nt < 4; nt++)
            #pragma unroll
            for (int e = 0; e < 4; e++) acc[mt][nt][e] = 0.f;

    for (int kc = 0; kc < NUMK; kc++) {
        asm volatile("cp.async.wait_group 1;" ::: "memory");
        __syncthreads();

        const uint32_t sstage = sbase + (uint32_t)(kc & 1) * STAGE_B;
        const uint32_t aTile = sstage;
        const uint32_t bTile = sstage + 2 * TILE_B;

        #pragma unroll
        for (int ks = 0; ks < 2; ks++) {
            const uint32_t kb = ks * 32;
            // B fragments first (hi, lo): 16 regs
            uint32_t bh[4][2], bl[4][2];
            #pragma unroll
            for (int np = 0; np < 2; np++) {
                const uint32_t off = bBase + np * (16 * ROWB) + kb;
                ldsm_x4(bh[np*2][0], bh[np*2][1], bh[np*2+1][0], bh[np*2+1][1], bTile + off);
                ldsm_x4(bl[np*2][0], bl[np*2][1], bl[np*2+1][0], bl[np*2+1][1],
                        bTile + TILE_B + off);
            }
            // per m-tile: load A hi/lo (8 regs), fire 12 MMAs
            #pragma unroll
            for (int mt = 0; mt < 4; mt++) {
                uint32_t ah[4], al[4];
                const uint32_t off = aBase + mt * (16 * ROWB) + kb;
                ldsm_x4(ah[0], ah[1], ah[2], ah[3], aTile + off);
                ldsm_x4(al[0], al[1], al[2], al[3], aTile + TILE_B + off);
                #pragma unroll
                for (int nt = 0; nt < 4; nt++) {
                    float* c = acc[mt][nt];
                    mma16816(c[0], c[1], c[2], c[3],
                             ah[0], ah[1], ah[2], ah[3], bh[nt][0], bh[nt][1]);
                    mma16816(c[0], c[1], c[2], c[3],
                             ah[0], ah[1], ah[2], ah[3], bl[nt][0], bl[nt][1]);
                    mma16816(c[0], c[1], c[2], c[3],
                             al[0], al[1], al[2], al[3], bh[nt][0], bh[nt][1]);
                }
            }
        }
        __syncthreads();
        if (kc + 2 < NUMK) prefetch(kc + 2);
        asm volatile("cp.async.commit_group;" ::: "memory");
    }

    if (mode == 0) {
        const int rbase = m0 + mw * 64 + (lane >> 2);
        const int cbase = n0 + nw * 32 + ((lane & 3) << 1);
        #pragma unroll
        for (int mt = 0; mt < 4; mt++) {
            #pragma unroll
            for (int nt = 0; nt < 4; nt++) {
                float* c = acc[mt][nt];
                float* p0 = Cm + (size_t)(rbase + mt * 16) * Ndim + cbase + nt * 8;
                float* p1 = p0 + (size_t)8 * Ndim;
                *reinterpret_cast<float2*>(p0) = make_float2(c[0], c[1]);
                *reinterpret_cast<float2*>(p1) = make_float2(c[2], c[3]);
            }
        }
        return;
    }

    // ---- fused QKV epilogue: stage fp32 tile in smem [128][132] ----
    float* sm = reinterpret_cast<float*>(smem_raw);
    __syncthreads();
    const int rloc = mw * 64 + (lane >> 2);
    const int cloc = nw * 32 + ((lane & 3) << 1);
    #pragma unroll
    for (int mt = 0; mt < 4; mt++) {
        #pragma unroll
        for (int nt = 0; nt < 4; nt++) {
            float* c = acc[mt][nt];
            float* p0 = sm + (size_t)(rloc + mt * 16) * 132 + cloc + nt * 8;
            *reinterpret_cast<float2*>(p0)       = make_float2(c[0], c[1]);
            *reinterpret_cast<float2*>(p0 + 8 * 132) = make_float2(c[2], c[3]);
        }
    }
    __syncthreads();

    const int ct = blockIdx.x;
    const int b = m0 >> 11;
    const int t_base = m0 & (TT - 1);

    if (ct < 16) {
        const bool isQ = (ct < 8);
        const float qs = isQ ? 0.125f : 1.0f;
        __nv_bfloat16* dh = isQ ? qh : kh;
        __nv_bfloat16* dl = isQ ? ql : kl;
        const int hbase = (isQ ? ct : (ct - 8)) * 2;
        #pragma unroll
        for (int i = 0; i < 16; i++) {
            const int idx = i * 256 + tid;
            const int dp = (idx & 15) * 2;
            const int hs = (idx >> 4) & 1;
            const int r  = idx >> 5;
            const int t  = t_base + r;
            const float c0 = gcos[t * 32 + dp],  c1 = gcos[t * 32 + dp + 1];
            const float s0 = gsin[t * 32 + dp],  s1 = gsin[t * 32 + dp + 1];
            const float* row = sm + (size_t)r * 132 + hs * 64;
            const float x1 = row[dp],      x1b = row[dp + 1];
            const float x2 = row[dp + 32], x2b = row[dp + 33];
            const float o0 = (x1 * c0 - x2 * s0) * qs;
            const float o1 = (x1b * c1 - x2b * s1) * qs;
            const float o2 = (x2 * c0 + x1 * s0) * qs;
            const float o3 = (x2b * c1 + x1b * s1) * qs;
            const size_t base = (((size_t)b * HH + hbase + hs) * TT + t) * 64;
            store_hl(dh, dl, base + dp, o0, o1);
            store_hl(dh, dl, base + dp + 32, o2, o3);
        }
    } else {
        const int hbase = (ct - 16) * 2;
        #pragma unroll
        for (int i = 0; i < 32; i++) {
            const int idx = i * 256 + tid;
            const int c  = idx >> 6;
            const int t2 = idx & 63;
            const int hs = c >> 6;
            const int d  = c & 63;
            const float a  = sm[(size_t)(2 * t2) * 132 + c];
            const float bv = sm[(size_t)(2 * t2 + 1) * 132 + c];
            const int t = t_base + 2 * t2;
            store_hl(vth, vtl,
                     (((size_t)b * HH + hbase + hs) * 64 + d) * TT + t, a, bv);
        }
    }
}

// ---------------- fp32 -> bf16 hi/lo split ---------------------------------
__global__ void split_kernel(const float4* __restrict__ in,
                             uint2* __restrict__ hi, uint2* __restrict__ lo, int n4)
{
    int i = blockIdx.x * blockDim.x + threadIdx.x;
    if (i >= n4) return;
    float4 v = in[i];
    float vv[4] = { v.x, v.y, v.z, v.w };
    unsigned short h[4], l[4];
    #pragma unroll
    for (int k = 0; k < 4; k++) {
        __nv_bfloat16 hb = __float2bfloat16(vv[k]);
        __nv_bfloat16 lb = __float2bfloat16(vv[k] - __bfloat162float(hb));
        h[k] = __bfloat16_as_ushort(hb);
        l[k] = __bfloat16_as_ushort(lb);
    }
    uint2 ho, lo_;
    ho.x = (uint32_t)h[0] | ((uint32_t)h[1] << 16);
    ho.y = (uint32_t)h[2] | ((uint32_t)h[3] << 16);
    lo_.x = (uint32_t)l[0] | ((uint32_t)l[1] << 16);
    lo_.y = (uint32_t)l[2] | ((uint32_t)l[3] << 16);
    hi[i] = ho;
    lo[i] = lo_;
}

// -------- combined W transpose-split: all three weights in ONE launch ------
__global__ void transpose_split_all(const float* __restrict__ Wq,
                                    const float* __restrict__ Wkv,
                                    const float* __restrict__ Wc,
                                    __nv_bfloat16* __restrict__ wh,
                                    __nv_bfloat16* __restrict__ wl,
                                    __nv_bfloat16* __restrict__ wch,
                                    __nv_bfloat16* __restrict__ wcl)
{
    __shared__ float t[32][33];
    const int nx = blockIdx.x;
    const int k0 = blockIdx.y * 32;
    const float* W;
    __nv_bfloat16 *Th, *Tl;
    int N, n0;
    if (nx < 32)       { W = Wq;  N = CC;     n0 = nx * 32;        Th = wh;  Tl = wl; }
    else if (nx < 96)  { W = Wkv; N = 2 * CC; n0 = (nx - 32) * 32;
                         Th = wh + (size_t)CC * GK; Tl = wl + (size_t)CC * GK; }
    else               { W = Wc;  N = CC;     n0 = (nx - 96) * 32; Th = wch; Tl = wcl; }

    const int tx = threadIdx.x, ty = threadIdx.y;
    #pragma unroll
    for (int i = 0; i < 32; i += 8)
        t[ty + i][tx] = W[(size_t)(k0 + ty + i) * N + n0 + tx];
    __syncthreads();
    #pragma unroll
    for (int i = 0; i < 32; i += 8) {
        float v = t[tx][ty + i];
        __nv_bfloat16 hb = __float2bfloat16(v);
        size_t o = (size_t)(n0 + ty + i) * GK + k0 + tx;
        Th[o] = hb;
        Tl[o] = __float2bfloat16(v - __bfloat162float(hb));
    }
}

// ---------------- RoPE table ------------------------------------------------
__global__ void rope_table_kernel(float* __restrict__ gcos, float* __restrict__ gsin)
{
    int i = blockIdx.x * blockDim.x + threadIdx.x;
    if (i >= TT * 32) return;
    int t = i >> 5;
    int d = i & 31;
    float inv = (float)exp(-((double)(2 * d) / 64.0) * log(10000.0));
    float ang = (float)t * inv;
    gcos[i] = cosf(ang);
    gsin[i] = sinf(ang);
}

// ---------------- Flash attention on HMMA (bf16 hi/lo, fp32 accum) --------
#define FROWB 144
#define FQ_TILE (128 * FROWB)        // 18432
#define FKV_TILE (64 * FROWB)        // 9216
#define FSTAGE (4 * FKV_TILE)        // 36864
#define FSMEM (2 * FQ_TILE + 2 * FSTAGE)   // 110592

__global__ void __launch_bounds__(256, 1)
flash_mma_kernel(const __nv_bfloat16* __restrict__ qh, const __nv_bfloat16* __restrict__ ql,
                 const __nv_bfloat16* __restrict__ kh, const __nv_bfloat16* __restrict__ kl,
                 const __nv_bfloat16* __restrict__ vth, const __nv_bfloat16* __restrict__ vtl,
                 __nv_bfloat16* __restrict__ yh, __nv_bfloat16* __restrict__ yl)
{
    extern __shared__ char smem_raw[];
    const uint32_t sQ  = smem_u32(smem_raw);
    const uint32_t sKV = sQ + 2 * FQ_TILE;

    const int tid = threadIdx.x, lane = tid & 31, warp = tid >> 5;
    const int t0 = (gridDim.x - 1 - blockIdx.x) * 128;   // heavy-first
    const int h = blockIdx.y, b = blockIdx.z;
    const size_t bh = (size_t)b * HH + h;
    const int nkv = t0 / 64 + 2;

    #pragma unroll
    for (int i = 0; i < 8; i++) {
        int idx = i * 256 + tid;
        int arr = idx >> 10, r = (idx >> 3) & 127, j = idx & 7;
        const __nv_bfloat16* g = (arr ? ql : qh) + (bh * TT + t0 + r) * 64 + j * 8;
        cp_async16(sQ + arr * FQ_TILE + r * FROWB + j * 16, g);
    }
    auto pref_kv = [&](int n) {
        const uint32_t sb = sKV + (uint32_t)(n & 1) * FSTAGE;
        const int j0 = n * 64;
        #pragma unroll
        for (int i = 0; i < 8; i++) {
            int idx = i * 256 + tid;
            int arr = idx >> 9, r = (idx >> 3) & 63, j = idx & 7;
            const __nv_bfloat16* g;
            if (arr == 0)      g = kh  + (bh * TT + j0 + r) * 64 + j * 8;
            else if (arr == 1) g = kl  + (bh * TT + j0 + r) * 64 + j * 8;
            else if (arr == 2) g = vth + (bh * 64 + r) * TT + j0 + j * 8;
            else               g = vtl + (bh * 64 + r) * TT + j0 + j * 8;
            cp_async16(sb + arr * FKV_TILE + r * FROWB + j * 16, g);
        }
    };
    pref_kv(0);
    asm volatile("cp.async.commit_group;" ::: "memory");
    pref_kv(1);
    asm volatile("cp.async.commit_group;" ::: "memory");

    const int wrow = t0 + warp * 16;
    const int gr = lane >> 2;
    const int qk = (lane & 3) * 2;
    const int row0 = wrow + gr;
    const int row1 = row0 + 8;

    uint32_t qa_h[4][4], qa_l[4][4];
    float O[8][4];
    #pragma unroll
    for (int nt = 0; nt < 8; nt++)
        #pragma unroll
        for (int e = 0; e < 4; e++) O[nt][e] = 0.f;
    float mA = -1e30f, mB = -1e30f, lA = 0.f, lB = 0.f;

    const uint32_t bBaseOff = ((lane & 7) + ((lane >> 4) << 3)) * FROWB + (((lane >> 3) & 1) << 4);

    for (int n = 0; n < nkv; n++) {
        asm volatile("cp.async.wait_group 1;" ::: "memory");
        __syncthreads();

        if (n == 0) {
            const uint32_t qb = sQ + (warp * 16 + (lane & 15)) * FROWB + ((lane >> 4) << 4);
            #pragma unroll
            for (int ks = 0; ks < 4; ks++) {
                ldsm_x4(qa_h[ks][0], qa_h[ks][1], qa_h[ks][2], qa_h[ks][3], qb + ks * 32);
                ldsm_x4(qa_l[ks][0], qa_l[ks][1], qa_l[ks][2], qa_l[ks][3],
                        qb + FQ_TILE + ks * 32);
            }
        }

        const int j0 = n * 64;
        if (j0 <= wrow + 15) {
            const uint32_t sb = sKV + (uint32_t)(n & 1) * FSTAGE;
            float S[8][4];
            #pragma unroll
            for (int nt = 0; nt < 8; nt++)
                #pragma unroll
                for (int e = 0; e < 4; e++) S[nt][e] = 0.f;

            #pragma unroll
            for (int ks = 0; ks < 4; ks++) {
                uint32_t B0h[8], B1h[8], B0l[8], B1l[8];
                #pragma unroll
                for (int q2 = 0; q2 < 4; q2++) {
                    const uint32_t off = bBaseOff + q2 * (16 * FROWB) + ks * 32;
                    ldsm_x4(B0h[q2*2], B1h[q2*2], B0h[q2*2+1], B1h[q2*2+1], sb + off);
                    ldsm_x4(B0l[q2*2], B1l[q2*2], B0l[q2*2+1], B1l[q2*2+1],
                            sb + FKV_TILE + off);
                }
                #pragma unroll
                for (int nt = 0; nt < 8; nt++) {
                    float* c = S[nt];
                    mma16816(c[0], c[1], c[2], c[3],
                             qa_h[ks][0], qa_h[ks][1], qa_h[ks][2], qa_h[ks][3],
                             B0h[nt], B1h[nt]);
                    mma16816(c[0], c[1], c[2], c[3],
                             qa_h[ks][0], qa_h[ks][1], qa_h[ks][2], qa_h[ks][3],
                             B0l[nt], B1l[nt]);
                    mma16816(c[0], c[1], c[2], c[3],
                             qa_l[ks][0], qa_l[ks][1], qa_l[ks][2], qa_l[ks][3],
                             B0h[nt], B1h[nt]);
                }
            }

            if (j0 + 63 > wrow) {
                #pragma unroll
                for (int nt = 0; nt < 8; nt++) {
                    const int c0 = j0 + nt * 8 + qk;
                    if (c0 > row0)     S[nt][0] = -1e30f;
                    if (c0 + 1 > row0) S[nt][1] = -1e30f;
                    if (c0 > row1)     S[nt][2] = -1e30f;
                    if (c0 + 1 > row1) S[nt][3] = -1e30f;
                }
            }

            float tmA = -1e30f, tmB = -1e30f;
            #pragma unroll
            for (int nt = 0; nt < 8; nt++) {
                tmA = fmaxf(tmA, fmaxf(S[nt][0], S[nt][1]));
                tmB = fmaxf(tmB, fmaxf(S[nt][2], S[nt][3]));
            }
            tmA = fmaxf(tmA, __shfl_xor_sync(0xffffffffu, tmA, 1));
            tmA = fmaxf(tmA, __shfl_xor_sync(0xffffffffu, tmA, 2));
            tmB = fmaxf(tmB, __shfl_xor_sync(0xffffffffu, tmB, 1));
            tmB = fmaxf(tmB, __shfl_xor_sync(0xffffffffu, tmB, 2));
            const float mnA = fmaxf(mA, tmA), mnB = fmaxf(mB, tmB);
            const float aA = __expf(mA - mnA), aB = __expf(mB - mnB);
            float sumA = 0.f, sumB = 0.f;
            #pragma unroll
            for (int nt = 0; nt < 8; nt++) {
                S[nt][0] = __expf(S[nt][0] - mnA);
                S[nt][1] = __expf(S[nt][1] - mnA);
                S[nt][2] = __expf(S[nt][2] - mnB);
                S[nt][3] = __expf(S[nt][3] - mnB);
                sumA += S[nt][0] + S[nt][1];
                sumB += S[nt][2] + S[nt][3];
            }
            sumA += __shfl_xor_sync(0xffffffffu, sumA, 1);
            sumA += __shfl_xor_sync(0xffffffffu, sumA, 2);
            sumB += __shfl_xor_sync(0xffffffffu, sumB, 1);
            sumB += __shfl_xor_sync(0xffffffffu, sumB, 2);
            lA = lA * aA + sumA;
            lB = lB * aB + sumB;
            mA = mnA; mB = mnB;
            #pragma unroll
            for (int nt = 0; nt < 8; nt++) {
                O[nt][0] *= aA; O[nt][1] *= aA;
                O[nt][2] *= aB; O[nt][3] *= aB;
            }

            const uint32_t vb = sb + 2 * FKV_TILE;
            #pragma unroll
            for (int ks = 0; ks < 4; ks++) {
                const int n0t = 2 * ks, n1t = 2 * ks + 1;
                uint32_t pah[4], pal[4];
                {
                    __nv_bfloat162 h0 = __float22bfloat162_rn(make_float2(S[n0t][0], S[n0t][1]));
                    __nv_bfloat162 h1 = __float22bfloat162_rn(make_float2(S[n0t][2], S[n0t][3]));
                    __nv_bfloat162 h2 = __float22bfloat162_rn(make_float2(S[n1t][0], S[n1t][1]));
                    __nv_bfloat162 h3 = __float22bfloat162_rn(make_float2(S[n1t][2], S[n1t][3]));
                    pah[0] = *reinterpret_cast<uint32_t*>(&h0);
                    pah[1] = *reinterpret_cast<uint32_t*>(&h1);
                    pah[2] = *reinterpret_cast<uint32_t*>(&h2);
                    pah[3] = *reinterpret_cast<uint32_t*>(&h3);
                    pal[0] = pack_bf16(S[n0t][0] - __bfloat162float(h0.x),
                                       S[n0t][1] - __bfloat162float(h0.y));
                    pal[1] = pack_bf16(S[n0t][2] - __bfloat162float(h1.x),
                                       S[n0t][3] - __bfloat162float(h1.y));
                    pal[2] = pack_bf16(S[n1t][0] - __bfloat162float(h2.x),
                                       S[n1t][1] - __bfloat162float(h2.y));
                    pal[3] = pack_bf16(S[n1t][2] - __bfloat162float(h3.x),
                                       S[n1t][3] - __bfloat162float(h3.y));
                }
                uint32_t V0h[8], V1h[8], V0l[8], V1l[8];
                #pragma unroll
                for (int q2 = 0; q2 < 4; q2++) {
                    const uint32_t off = bBaseOff + q2 * (16 * FROWB) + ks * 32;
                    ldsm_x4(V0h[q2*2], V1h[q2*2], V0h[q2*2+1], V1h[q2*2+1], vb + off);
                    ldsm_x4(V0l[q2*2], V1l[q2*2], V0l[q2*2+1], V1l[q2*2+1],
                            vb + FKV_TILE + off);
                }
                #pragma unroll
                for (int nt = 0; nt < 8; nt++) {
                    float* c = O[nt];
                    mma16816(c[0], c[1], c[2], c[3],
                             pah[0], pah[1], pah[2], pah[3], V0h[nt], V1h[nt]);
                    mma16816(c[0], c[1], c[2], c[3],
                             pah[0], pah[1], pah[2], pah[3], V0l[nt], V1l[nt]);
                    mma16816(c[0], c[1], c[2], c[3],
                             pal[0], pal[1], pal[2], pal[3], V0h[nt], V1h[nt]);
                }
            }
        }
        __syncthreads();
        if (n + 2 < nkv) pref_kv(n + 2);
        asm volatile("cp.async.commit_group;" ::: "memory");
    }

    const float iA = 1.f / lA, iB = 1.f / lB;
    #pragma unroll
    for (int nt = 0; nt < 8; nt++) {
        const size_t d0 = (size_t)h * 64 + nt * 8 + qk;
        store_hl(yh, yl, ((size_t)b * TT + row0) * CC + d0, O[nt][0] * iA, O[nt][1] * iA);
        store_hl(yh, yl, ((size_t)b * TT + row1) * CC + d0, O[nt][2] * iB, O[nt][3] * iB);
    }
}

// ---------------- launch ---------------------------------------------------
extern "C" void kernel_launch(void* const* d_in, const int* in_sizes, int n_in,
                              void* d_out, int out_size)
{
    const float* x   = (const float*)d_in[0];
    const float* Wq  = (const float*)d_in[1];
    const float* Wkv = (const float*)d_in[2];
    const float* Wc  = (const float*)d_in[3];
    float* out = (float*)d_out;

    float *gc, *gs;
    __nv_bfloat16 *xh, *xl, *yh, *yl, *wh, *wl, *wch, *wcl;
    __nv_bfloat16 *qh, *ql, *kh, *kl, *vth, *vtl;
    cudaGetSymbolAddress((void**)&gc, g_cos);
    cudaGetSymbolAddress((void**)&gs, g_sin);
    cudaGetSymbolAddress((void**)&xh, g_xh);
    cudaGetSymbolAddress((void**)&xl, g_xl);
    cudaGetSymbolAddress((void**)&yh, g_yh);
    cudaGetSymbolAddress((void**)&yl, g_yl);
    cudaGetSymbolAddress((void**)&wh, g_wh);
    cudaGetSymbolAddress((void**)&wl, g_wl);
    cudaGetSymbolAddress((void**)&wch, g_wch);
    cudaGetSymbolAddress((void**)&wcl, g_wcl);
    cudaGetSymbolAddress((void**)&qh, g_qh);
    cudaGetSymbolAddress((void**)&ql, g_ql);
    cudaGetSymbolAddress((void**)&kh, g_kh);
    cudaGetSymbolAddress((void**)&kl, g_kl);
    cudaGetSymbolAddress((void**)&vth, g_vth);
    cudaGetSymbolAddress((void**)&vtl, g_vtl);

    cudaFuncSetAttribute(gemm_kernel_mma, cudaFuncAttributeMaxDynamicSharedMemorySize, SMEM_DYN);
    cudaFuncSetAttribute(flash_mma_kernel, cudaFuncAttributeMaxDynamicSharedMemorySize, FSMEM);

    // #0
    rope_table_kernel<<<(TT * 32 + 255) / 256, 256>>>(gc, gs);
    // #1: split x
    {
        int n4 = MM * GK / 4;
        split_kernel<<<(n4 + 255) / 256, 256>>>((const float4*)x, (uint2*)xh, (uint2*)xl, n4);
    }
    // #2: all weight transposes
    transpose_split_all<<<dim3(128, GK / 32), dim3(32, 8)>>>(Wq, Wkv, Wc, wh, wl, wch, wcl);

    // #3: fused QKV GEMM (ncu target)
    gemm_kernel_mma<<<dim3(3 * CC / 128, MM / 128), 256, SMEM_DYN>>>(
        xh, xl, wh, wl, nullptr, 3 * CC, 1, gc, gs, qh, ql, kh, kl, vth, vtl);

    // #4: attention
    flash_mma_kernel<<<dim3(TT / 128, HH, BB), 256, FSMEM>>>(qh, ql, kh, kl, vth, vtl, yh, yl);

    // #5: out = y @ Wc
    gemm_kernel_mma<<<dim3(CC / 128, MM / 128), 256, SMEM_DYN>>>(
        yh, yl, wch, wcl, out, CC, 0, nullptr, nullptr,
        nullptr, nullptr, nullptr, nullptr, nullptr, nullptr);
}

// round 8
// speedup vs baseline: 3.5798x; 1.0081x over previous
#include <cuda_runtime.h>
#include <cuda_bf16.h>
#include <math.h>
#include <stdint.h>

#define BB 4
#define TT 2048
#define HH 16
#define DD 64
#define CC (HH*DD)      // 1024
#define MM (BB*TT)      // 8192
#define GK 1024         // K of all GEMMs

// ---------------- scratch (device globals; no allocation allowed) ----------
__device__ __align__(256) float g_cos[TT * 32];
__device__ __align__(256) float g_sin[TT * 32];

__device__ __align__(256) __nv_bfloat16 g_xh[(size_t)MM * GK];
__device__ __align__(256) __nv_bfloat16 g_xl[(size_t)MM * GK];
__device__ __align__(256) __nv_bfloat16 g_yh[(size_t)MM * GK];
__device__ __align__(256) __nv_bfloat16 g_yl[(size_t)MM * GK];
__device__ __align__(256) __nv_bfloat16 g_qh[(size_t)BB*HH*TT*DD];
__device__ __align__(256) __nv_bfloat16 g_ql[(size_t)BB*HH*TT*DD];
__device__ __align__(256) __nv_bfloat16 g_kh[(size_t)BB*HH*TT*DD];
__device__ __align__(256) __nv_bfloat16 g_kl[(size_t)BB*HH*TT*DD];
__device__ __align__(256) __nv_bfloat16 g_vth[(size_t)BB*HH*TT*DD];
__device__ __align__(256) __nv_bfloat16 g_vtl[(size_t)BB*HH*TT*DD];
__device__ __align__(256) __nv_bfloat16 g_wh[(size_t)3 * CC * GK];
__device__ __align__(256) __nv_bfloat16 g_wl[(size_t)3 * CC * GK];
__device__ __align__(256) __nv_bfloat16 g_wch[(size_t)CC * GK];
__device__ __align__(256) __nv_bfloat16 g_wcl[(size_t)CC * GK];

// ---------------- helpers ----------------------------------------------------
__device__ __forceinline__ uint32_t smem_u32(const void* p) {
    return (uint32_t)__cvta_generic_to_shared(p);
}

__device__ __forceinline__ void cp_async16(uint32_t saddr, const void* gaddr) {
    asm volatile("cp.async.cg.shared.global [%0], [%1], 16;" :: "r"(saddr), "l"(gaddr) : "memory");
}

__device__ __forceinline__ void ldsm_x4(uint32_t& r0, uint32_t& r1, uint32_t& r2, uint32_t& r3,
                                        uint32_t addr) {
    asm volatile("ldmatrix.sync.aligned.m8n8.x4.shared.b16 {%0,%1,%2,%3}, [%4];"
                 : "=r"(r0), "=r"(r1), "=r"(r2), "=r"(r3) : "r"(addr));
}

__device__ __forceinline__ void mma16816(float& c0, float& c1, float& c2, float& c3,
                                         uint32_t a0, uint32_t a1, uint32_t a2, uint32_t a3,
                                         uint32_t b0, uint32_t b1) {
    asm volatile(
        "mma.sync.aligned.m16n8k16.row.col.f32.bf16.bf16.f32 "
        "{%0,%1,%2,%3}, {%4,%5,%6,%7}, {%8,%9}, {%0,%1,%2,%3};"
        : "+f"(c0), "+f"(c1), "+f"(c2), "+f"(c3)
        : "r"(a0), "r"(a1), "r"(a2), "r"(a3), "r"(b0), "r"(b1));
}

__device__ __forceinline__ uint32_t pack_bf16(float a, float b) {
    __nv_bfloat162 t = __float22bfloat162_rn(make_float2(a, b));
    return *reinterpret_cast<uint32_t*>(&t);
}

__device__ __forceinline__ void store_hl(__nv_bfloat16* hi, __nv_bfloat16* lo,
                                         size_t off, float a, float b) {
    __nv_bfloat162 h = __float22bfloat162_rn(make_float2(a, b));
    float ra = a - __bfloat162float(h.x);
    float rb = b - __bfloat162float(h.y);
    __nv_bfloat162 l = __float22bfloat162_rn(make_float2(ra, rb));
    *reinterpret_cast<__nv_bfloat162*>(hi + off) = h;
    *reinterpret_cast<__nv_bfloat162*>(lo + off) = l;
}

// ---------------- HMMA GEMM: C = (Ah+Al) @ (Bh+Bl)^T -----------------------
// 128x128 CTA tile, 4 warps (2x2), warp tile 64x64 (acc=128 regs),
// 2-stage cp.async pipeline, 2 CTAs/SM.
#define BK 32
#define NUMK (GK / BK)          // 32
#define ROWB 80                 // 64B data + 16B pad
#define TILE_B (128 * ROWB)     // 10240
#define STAGE_B (4 * TILE_B)    // 40960
#define SMEM_DYN (2 * STAGE_B)  // 81920

__global__ void __launch_bounds__(128, 2)
gemm_kernel_mma(const __nv_bfloat16* __restrict__ Ah, const __nv_bfloat16* __restrict__ Al,
                const __nv_bfloat16* __restrict__ Bh, const __nv_bfloat16* __restrict__ Bl,
                float* __restrict__ Cm, int Ndim, int mode,
                const float* __restrict__ gcos, const float* __restrict__ gsin,
                __nv_bfloat16* __restrict__ qh, __nv_bfloat16* __restrict__ ql,
                __nv_bfloat16* __restrict__ kh, __nv_bfloat16* __restrict__ kl,
                __nv_bfloat16* __restrict__ vth, __nv_bfloat16* __restrict__ vtl)
{
    extern __shared__ char smem_raw[];
    const uint32_t sbase = smem_u32(smem_raw);

    const int tid  = threadIdx.x;
    const int lane = tid & 31;
    const int warp = tid >> 5;        // 0..3
    const int mw   = warp & 1;        // 64-row half
    const int nw   = warp >> 1;       // 64-col half
    const int m0 = blockIdx.y * 128;
    const int n0 = blockIdx.x * 128;

    const __nv_bfloat16* tp[4] = { Ah, Al, Bh, Bl };

    auto prefetch = [&](int kc) {
        const uint32_t sstage = sbase + (uint32_t)(kc & 1) * STAGE_B;
        #pragma unroll
        for (int i = 0; i < 16; i++) {
            const int c = i * 128 + tid;
            const int tile = c >> 9;
            const int r = (c >> 2) & 127;
            const int j = c & 3;
            const int row0 = (tile < 2) ? m0 : n0;
            const __nv_bfloat16* g = tp[tile] + (size_t)(row0 + r) * GK + kc * BK + j * 8;
            cp_async16(sstage + tile * TILE_B + r * ROWB + j * 16, g);
        }
    };

    prefetch(0);
    asm volatile("cp.async.commit_group;" ::: "memory");
    prefetch(1);
    asm volatile("cp.async.commit_group;" ::: "memory");

    const uint32_t aBase = (uint32_t)((mw * 64 + (lane & 15)) * ROWB + ((lane >> 4) << 4));
    const uint32_t bBase = (uint32_t)((nw * 64 + (lane & 7) + ((lane >> 4) << 3)) * ROWB
                                      + (((lane >> 3) & 1) << 4));

    float acc[4][8][4];
    #pragma unroll
    for (int mt = 0; mt < 4; mt++)
        #pragma unroll
        for (int nt = 0; nt < 8; nt++)
            #pragma unroll
            for (int e = 0; e < 4; e++) acc[mt][nt][e] = 0.f;

    for (int kc = 0; kc < NUMK; kc++) {
        asm volatile("cp.async.wait_group 1;" ::: "memory");
        __syncthreads();

        const uint32_t sstage = sbase + (uint32_t)(kc & 1) * STAGE_B;
        const uint32_t aTile = sstage;
        const uint32_t bTile = sstage + 2 * TILE_B;

        #pragma unroll
        for (int ks = 0; ks < 2; ks++) {
            const uint32_t kb = ks * 32;
            // B fragments (hi, lo): 8 n8-tiles -> 32 regs
            uint32_t bh[8][2], bl[8][2];
            #pragma unroll
            for (int np = 0; np < 4; np++) {
                const uint32_t off = bBase + np * (16 * ROWB) + kb;
                ldsm_x4(bh[np*2][0], bh[np*2][1], bh[np*2+1][0], bh[np*2+1][1], bTile + off);
                ldsm_x4(bl[np*2][0], bl[np*2][1], bl[np*2+1][0], bl[np*2+1][1],
                        bTile + TILE_B + off);
            }
            #pragma unroll
            for (int mt = 0; mt < 4; mt++) {
                uint32_t ah[4], al[4];
                const uint32_t off = aBase + mt * (16 * ROWB) + kb;
                ldsm_x4(ah[0], ah[1], ah[2], ah[3], aTile + off);
                ldsm_x4(al[0], al[1], al[2], al[3], aTile + TILE_B + off);
                #pragma unroll
                for (int nt = 0; nt < 8; nt++) {
                    float* c = acc[mt][nt];
                    mma16816(c[0], c[1], c[2], c[3],
                             ah[0], ah[1], ah[2], ah[3], bh[nt][0], bh[nt][1]);
                    mma16816(c[0], c[1], c[2], c[3],
                             ah[0], ah[1], ah[2], ah[3], bl[nt][0], bl[nt][1]);
                    mma16816(c[0], c[1], c[2], c[3],
                             al[0], al[1], al[2], al[3], bh[nt][0], bh[nt][1]);
                }
            }
        }
        __syncthreads();
        if (kc + 2 < NUMK) prefetch(kc + 2);
        asm volatile("cp.async.commit_group;" ::: "memory");
    }

    if (mode == 0) {
        const int rbase = m0 + mw * 64 + (lane >> 2);
        const int cbase = n0 + nw * 64 + ((lane & 3) << 1);
        #pragma unroll
        for (int mt = 0; mt < 4; mt++) {
            #pragma unroll
            for (int nt = 0; nt < 8; nt++) {
                float* c = acc[mt][nt];
                float* p0 = Cm + (size_t)(rbase + mt * 16) * Ndim + cbase + nt * 8;
                float* p1 = p0 + (size_t)8 * Ndim;
                *reinterpret_cast<float2*>(p0) = make_float2(c[0], c[1]);
                *reinterpret_cast<float2*>(p1) = make_float2(c[2], c[3]);
            }
        }
        return;
    }

    // ---- fused QKV epilogue: stage fp32 tile in smem [128][132] ----
    float* sm = reinterpret_cast<float*>(smem_raw);
    __syncthreads();
    const int rloc = mw * 64 + (lane >> 2);
    const int cloc = nw * 64 + ((lane & 3) << 1);
    #pragma unroll
    for (int mt = 0; mt < 4; mt++) {
        #pragma unroll
        for (int nt = 0; nt < 8; nt++) {
            float* c = acc[mt][nt];
            float* p0 = sm + (size_t)(rloc + mt * 16) * 132 + cloc + nt * 8;
            *reinterpret_cast<float2*>(p0)           = make_float2(c[0], c[1]);
            *reinterpret_cast<float2*>(p0 + 8 * 132) = make_float2(c[2], c[3]);
        }
    }
    __syncthreads();

    const int ct = blockIdx.x;
    const int b = m0 >> 11;
    const int t_base = m0 & (TT - 1);

    if (ct < 16) {
        const bool isQ = (ct < 8);
        const float qs = isQ ? 0.125f : 1.0f;
        __nv_bfloat16* dh = isQ ? qh : kh;
        __nv_bfloat16* dl = isQ ? ql : kl;
        const int hbase = (isQ ? ct : (ct - 8)) * 2;
        #pragma unroll
        for (int i = 0; i < 32; i++) {
            const int idx = i * 128 + tid;
            const int dp = (idx & 15) * 2;
            const int hs = (idx >> 4) & 1;
            const int r  = idx >> 5;
            const int t  = t_base + r;
            const float c0 = gcos[t * 32 + dp],  c1 = gcos[t * 32 + dp + 1];
            const float s0 = gsin[t * 32 + dp],  s1 = gsin[t * 32 + dp + 1];
            const float* row = sm + (size_t)r * 132 + hs * 64;
            const float x1 = row[dp],      x1b = row[dp + 1];
            const float x2 = row[dp + 32], x2b = row[dp + 33];
            const float o0 = (x1 * c0 - x2 * s0) * qs;
            const float o1 = (x1b * c1 - x2b * s1) * qs;
            const float o2 = (x2 * c0 + x1 * s0) * qs;
            const float o3 = (x2b * c1 + x1b * s1) * qs;
            const size_t base = (((size_t)b * HH + hbase + hs) * TT + t) * 64;
            store_hl(dh, dl, base + dp, o0, o1);
            store_hl(dh, dl, base + dp + 32, o2, o3);
        }
    } else {
        const int hbase = (ct - 16) * 2;
        #pragma unroll
        for (int i = 0; i < 64; i++) {
            const int idx = i * 128 + tid;
            const int c  = idx >> 6;
            const int t2 = idx & 63;
            const int hs = c >> 6;
            const int d  = c & 63;
            const float a  = sm[(size_t)(2 * t2) * 132 + c];
            const float bv = sm[(size_t)(2 * t2 + 1) * 132 + c];
            const int t = t_base + 2 * t2;
            store_hl(vth, vtl,
                     (((size_t)b * HH + hbase + hs) * 64 + d) * TT + t, a, bv);
        }
    }
}

// ---------------- fp32 -> bf16 hi/lo split ---------------------------------
__global__ void split_kernel(const float4* __restrict__ in,
                             uint2* __restrict__ hi, uint2* __restrict__ lo, int n4)
{
    int i = blockIdx.x * blockDim.x + threadIdx.x;
    if (i >= n4) return;
    float4 v = in[i];
    float vv[4] = { v.x, v.y, v.z, v.w };
    unsigned short h[4], l[4];
    #pragma unroll
    for (int k = 0; k < 4; k++) {
        __nv_bfloat16 hb = __float2bfloat16(vv[k]);
        __nv_bfloat16 lb = __float2bfloat16(vv[k] - __bfloat162float(hb));
        h[k] = __bfloat16_as_ushort(hb);
        l[k] = __bfloat16_as_ushort(lb);
    }
    uint2 ho, lo_;
    ho.x = (uint32_t)h[0] | ((uint32_t)h[1] << 16);
    ho.y = (uint32_t)h[2] | ((uint32_t)h[3] << 16);
    lo_.x = (uint32_t)l[0] | ((uint32_t)l[1] << 16);
    lo_.y = (uint32_t)l[2] | ((uint32_t)l[3] << 16);
    hi[i] = ho;
    lo[i] = lo_;
}

// -------- combined W transpose-split: all three weights in ONE launch ------
__global__ void transpose_split_all(const float* __restrict__ Wq,
                                    const float* __restrict__ Wkv,
                                    const float* __restrict__ Wc,
                                    __nv_bfloat16* __restrict__ wh,
                                    __nv_bfloat16* __restrict__ wl,
                                    __nv_bfloat16* __restrict__ wch,
                                    __nv_bfloat16* __restrict__ wcl)
{
    __shared__ float t[32][33];
    const int nx = blockIdx.x;
    const int k0 = blockIdx.y * 32;
    const float* W;
    __nv_bfloat16 *Th, *Tl;
    int N, n0;
    if (nx < 32)       { W = Wq;  N = CC;     n0 = nx * 32;        Th = wh;  Tl = wl; }
    else if (nx < 96)  { W = Wkv; N = 2 * CC; n0 = (nx - 32) * 32;
                         Th = wh + (size_t)CC * GK; Tl = wl + (size_t)CC * GK; }
    else               { W = Wc;  N = CC;     n0 = (nx - 96) * 32; Th = wch; Tl = wcl; }

    const int tx = threadIdx.x, ty = threadIdx.y;
    #pragma unroll
    for (int i = 0; i < 32; i += 8)
        t[ty + i][tx] = W[(size_t)(k0 + ty + i) * N + n0 + tx];
    __syncthreads();
    #pragma unroll
    for (int i = 0; i < 32; i += 8) {
        float v = t[tx][ty + i];
        __nv_bfloat16 hb = __float2bfloat16(v);
        size_t o = (size_t)(n0 + ty + i) * GK + k0 + tx;
        Th[o] = hb;
        Tl[o] = __float2bfloat16(v - __bfloat162float(hb));
    }
}

// ---------------- RoPE table ------------------------------------------------
__global__ void rope_table_kernel(float* __restrict__ gcos, float* __restrict__ gsin)
{
    int i = blockIdx.x * blockDim.x + threadIdx.x;
    if (i >= TT * 32) return;
    int t = i >> 5;
    int d = i & 31;
    float inv = (float)exp(-((double)(2 * d) / 64.0) * log(10000.0));
    float ang = (float)t * inv;
    gcos[i] = cosf(ang);
    gsin[i] = sinf(ang);
}

// ---------------- Flash attention on HMMA (bf16 hi/lo, fp32 accum) --------
#define FROWB 144
#define FQ_TILE (128 * FROWB)        // 18432
#define FKV_TILE (64 * FROWB)        // 9216
#define FSTAGE (4 * FKV_TILE)        // 36864
#define FSMEM (2 * FQ_TILE + 2 * FSTAGE)   // 110592

__global__ void __launch_bounds__(256, 1)
flash_mma_kernel(const __nv_bfloat16* __restrict__ qh, const __nv_bfloat16* __restrict__ ql,
                 const __nv_bfloat16* __restrict__ kh, const __nv_bfloat16* __restrict__ kl,
                 const __nv_bfloat16* __restrict__ vth, const __nv_bfloat16* __restrict__ vtl,
                 __nv_bfloat16* __restrict__ yh, __nv_bfloat16* __restrict__ yl)
{
    extern __shared__ char smem_raw[];
    const uint32_t sQ  = smem_u32(smem_raw);
    const uint32_t sKV = sQ + 2 * FQ_TILE;

    const int tid = threadIdx.x, lane = tid & 31, warp = tid >> 5;
    const int t0 = (gridDim.x - 1 - blockIdx.x) * 128;   // heavy-first
    const int h = blockIdx.y, b = blockIdx.z;
    const size_t bh = (size_t)b * HH + h;
    const int nkv = t0 / 64 + 2;

    #pragma unroll
    for (int i = 0; i < 8; i++) {
        int idx = i * 256 + tid;
        int arr = idx >> 10, r = (idx >> 3) & 127, j = idx & 7;
        const __nv_bfloat16* g = (arr ? ql : qh) + (bh * TT + t0 + r) * 64 + j * 8;
        cp_async16(sQ + arr * FQ_TILE + r * FROWB + j * 16, g);
    }
    auto pref_kv = [&](int n) {
        const uint32_t sb = sKV + (uint32_t)(n & 1) * FSTAGE;
        const int j0 = n * 64;
        #pragma unroll
        for (int i = 0; i < 8; i++) {
            int idx = i * 256 + tid;
            int arr = idx >> 9, r = (idx >> 3) & 63, j = idx & 7;
            const __nv_bfloat16* g;
            if (arr == 0)      g = kh  + (bh * TT + j0 + r) * 64 + j * 8;
            else if (arr == 1) g = kl  + (bh * TT + j0 + r) * 64 + j * 8;
            else if (arr == 2) g = vth + (bh * 64 + r) * TT + j0 + j * 8;
            else               g = vtl + (bh * 64 + r) * TT + j0 + j * 8;
            cp_async16(sb + arr * FKV_TILE + r * FROWB + j * 16, g);
        }
    };
    pref_kv(0);
    asm volatile("cp.async.commit_group;" ::: "memory");
    pref_kv(1);
    asm volatile("cp.async.commit_group;" ::: "memory");

    const int wrow = t0 + warp * 16;
    const int gr = lane >> 2;
    const int qk = (lane & 3) * 2;
    const int row0 = wrow + gr;
    const int row1 = row0 + 8;

    uint32_t qa_h[4][4], qa_l[4][4];
    float O[8][4];
    #pragma unroll
    for (int nt = 0; nt < 8; nt++)
        #pragma unroll
        for (int e = 0; e < 4; e++) O[nt][e] = 0.f;
    float mA = -1e30f, mB = -1e30f, lA = 0.f, lB = 0.f;

    const uint32_t bBaseOff = ((lane & 7) + ((lane >> 4) << 3)) * FROWB + (((lane >> 3) & 1) << 4);

    for (int n = 0; n < nkv; n++) {
        asm volatile("cp.async.wait_group 1;" ::: "memory");
        __syncthreads();

        if (n == 0) {
            const uint32_t qb = sQ + (warp * 16 + (lane & 15)) * FROWB + ((lane >> 4) << 4);
            #pragma unroll
            for (int ks = 0; ks < 4; ks++) {
                ldsm_x4(qa_h[ks][0], qa_h[ks][1], qa_h[ks][2], qa_h[ks][3], qb + ks * 32);
                ldsm_x4(qa_l[ks][0], qa_l[ks][1], qa_l[ks][2], qa_l[ks][3],
                        qb + FQ_TILE + ks * 32);
            }
        }

        const int j0 = n * 64;
        if (j0 <= wrow + 15) {
            const uint32_t sb = sKV + (uint32_t)(n & 1) * FSTAGE;
            float S[8][4];
            #pragma unroll
            for (int nt = 0; nt < 8; nt++)
                #pragma unroll
                for (int e = 0; e < 4; e++) S[nt][e] = 0.f;

            #pragma unroll
            for (int ks = 0; ks < 4; ks++) {
                uint32_t B0h[8], B1h[8], B0l[8], B1l[8];
                #pragma unroll
                for (int q2 = 0; q2 < 4; q2++) {
                    const uint32_t off = bBaseOff + q2 * (16 * FROWB) + ks * 32;
                    ldsm_x4(B0h[q2*2], B1h[q2*2], B0h[q2*2+1], B1h[q2*2+1], sb + off);
                    ldsm_x4(B0l[q2*2], B1l[q2*2], B0l[q2*2+1], B1l[q2*2+1],
                            sb + FKV_TILE + off);
                }
                #pragma unroll
                for (int nt = 0; nt < 8; nt++) {
                    float* c = S[nt];
                    mma16816(c[0], c[1], c[2], c[3],
                             qa_h[ks][0], qa_h[ks][1], qa_h[ks][2], qa_h[ks][3],
                             B0h[nt], B1h[nt]);
                    mma16816(c[0], c[1], c[2], c[3],
                             qa_h[ks][0], qa_h[ks][1], qa_h[ks][2], qa_h[ks][3],
                             B0l[nt], B1l[nt]);
                    mma16816(c[0], c[1], c[2], c[3],
                             qa_l[ks][0], qa_l[ks][1], qa_l[ks][2], qa_l[ks][3],
                             B0h[nt], B1h[nt]);
                }
            }

            if (j0 + 63 > wrow) {
                #pragma unroll
                for (int nt = 0; nt < 8; nt++) {
                    const int c0 = j0 + nt * 8 + qk;
                    if (c0 > row0)     S[nt][0] = -1e30f;
                    if (c0 + 1 > row0) S[nt][1] = -1e30f;
                    if (c0 > row1)     S[nt][2] = -1e30f;
                    if (c0 + 1 > row1) S[nt][3] = -1e30f;
                }
            }

            float tmA = -1e30f, tmB = -1e30f;
            #pragma unroll
            for (int nt = 0; nt < 8; nt++) {
                tmA = fmaxf(tmA, fmaxf(S[nt][0], S[nt][1]));
                tmB = fmaxf(tmB, fmaxf(S[nt][2], S[nt][3]));
            }
            tmA = fmaxf(tmA, __shfl_xor_sync(0xffffffffu, tmA, 1));
            tmA = fmaxf(tmA, __shfl_xor_sync(0xffffffffu, tmA, 2));
            tmB = fmaxf(tmB, __shfl_xor_sync(0xffffffffu, tmB, 1));
            tmB = fmaxf(tmB, __shfl_xor_sync(0xffffffffu, tmB, 2));
            const float mnA = fmaxf(mA, tmA), mnB = fmaxf(mB, tmB);
            const float aA = __expf(mA - mnA), aB = __expf(mB - mnB);
            float sumA = 0.f, sumB = 0.f;
            #pragma unroll
            for (int nt = 0; nt < 8; nt++) {
                S[nt][0] = __expf(S[nt][0] - mnA);
                S[nt][1] = __expf(S[nt][1] - mnA);
                S[nt][2] = __expf(S[nt][2] - mnB);
                S[nt][3] = __expf(S[nt][3] - mnB);
                sumA += S[nt][0] + S[nt][1];
                sumB += S[nt][2] + S[nt][3];
            }
            sumA += __shfl_xor_sync(0xffffffffu, sumA, 1);
            sumA += __shfl_xor_sync(0xffffffffu, sumA, 2);
            sumB += __shfl_xor_sync(0xffffffffu, sumB, 1);
            sumB += __shfl_xor_sync(0xffffffffu, sumB, 2);
            lA = lA * aA + sumA;
            lB = lB * aB + sumB;
            mA = mnA; mB = mnB;
            #pragma unroll
            for (int nt = 0; nt < 8; nt++) {
                O[nt][0] *= aA; O[nt][1] *= aA;
                O[nt][2] *= aB; O[nt][3] *= aB;
            }

            const uint32_t vb = sb + 2 * FKV_TILE;
            #pragma unroll
            for (int ks = 0; ks < 4; ks++) {
                const int n0t = 2 * ks, n1t = 2 * ks + 1;
                uint32_t pah[4], pal[4];
                {
                    __nv_bfloat162 h0 = __float22bfloat162_rn(make_float2(S[n0t][0], S[n0t][1]));
                    __nv_bfloat162 h1 = __float22bfloat162_rn(make_float2(S[n0t][2], S[n0t][3]));
                    __nv_bfloat162 h2 = __float22bfloat162_rn(make_float2(S[n1t][0], S[n1t][1]));
                    __nv_bfloat162 h3 = __float22bfloat162_rn(make_float2(S[n1t][2], S[n1t][3]));
                    pah[0] = *reinterpret_cast<uint32_t*>(&h0);
                    pah[1] = *reinterpret_cast<uint32_t*>(&h1);
                    pah[2] = *reinterpret_cast<uint32_t*>(&h2);
                    pah[3] = *reinterpret_cast<uint32_t*>(&h3);
                    pal[0] = pack_bf16(S[n0t][0] - __bfloat162float(h0.x),
                                       S[n0t][1] - __bfloat162float(h0.y));
                    pal[1] = pack_bf16(S[n0t][2] - __bfloat162float(h1.x),
                                       S[n0t][3] - __bfloat162float(h1.y));
                    pal[2] = pack_bf16(S[n1t][0] - __bfloat162float(h2.x),
                                       S[n1t][1] - __bfloat162float(h2.y));
                    pal[3] = pack_bf16(S[n1t][2] - __bfloat162float(h3.x),
                                       S[n1t][3] - __bfloat162float(h3.y));
                }
                uint32_t V0h[8], V1h[8], V0l[8], V1l[8];
                #pragma unroll
                for (int q2 = 0; q2 < 4; q2++) {
                    const uint32_t off = bBaseOff + q2 * (16 * FROWB) + ks * 32;
                    ldsm_x4(V0h[q2*2], V1h[q2*2], V0h[q2*2+1], V1h[q2*2+1], vb + off);
                    ldsm_x4(V0l[q2*2], V1l[q2*2], V0l[q2*2+1], V1l[q2*2+1],
                            vb + FKV_TILE + off);
                }
                #pragma unroll
                for (int nt = 0; nt < 8; nt++) {
                    float* c = O[nt];
                    mma16816(c[0], c[1], c[2], c[3],
                             pah[0], pah[1], pah[2], pah[3], V0h[nt], V1h[nt]);
                    mma16816(c[0], c[1], c[2], c[3],
                             pah[0], pah[1], pah[2], pah[3], V0l[nt], V1l[nt]);
                    mma16816(c[0], c[1], c[2], c[3],
                             pal[0], pal[1], pal[2], pal[3], V0h[nt], V1h[nt]);
                }
            }
        }
        __syncthreads();
        if (n + 2 < nkv) pref_kv(n + 2);
        asm volatile("cp.async.commit_group;" ::: "memory");
    }

    const float iA = 1.f / lA, iB = 1.f / lB;
    #pragma unroll
    for (int nt = 0; nt < 8; nt++) {
        const size_t d0 = (size_t)h * 64 + nt * 8 + qk;
        store_hl(yh, yl, ((size_t)b * TT + row0) * CC + d0, O[nt][0] * iA, O[nt][1] * iA);
        store_hl(yh, yl, ((size_t)b * TT + row1) * CC + d0, O[nt][2] * iB, O[nt][3] * iB);
    }
}

// ---------------- launch ---------------------------------------------------
extern "C" void kernel_launch(void* const* d_in, const int* in_sizes, int n_in,
                              void* d_out, int out_size)
{
    const float* x   = (const float*)d_in[0];
    const float* Wq  = (const float*)d_in[1];
    const float* Wkv = (const float*)d_in[2];
    const float* Wc  = (const float*)d_in[3];
    float* out = (float*)d_out;

    float *gc, *gs;
    __nv_bfloat16 *xh, *xl, *yh, *yl, *wh, *wl, *wch, *wcl;
    __nv_bfloat16 *qh, *ql, *kh, *kl, *vth, *vtl;
    cudaGetSymbolAddress((void**)&gc, g_cos);
    cudaGetSymbolAddress((void**)&gs, g_sin);
    cudaGetSymbolAddress((void**)&xh, g_xh);
    cudaGetSymbolAddress((void**)&xl, g_xl);
    cudaGetSymbolAddress((void**)&yh, g_yh);
    cudaGetSymbolAddress((void**)&yl, g_yl);
    cudaGetSymbolAddress((void**)&wh, g_wh);
    cudaGetSymbolAddress((void**)&wl, g_wl);
    cudaGetSymbolAddress((void**)&wch, g_wch);
    cudaGetSymbolAddress((void**)&wcl, g_wcl);
    cudaGetSymbolAddress((void**)&qh, g_qh);
    cudaGetSymbolAddress((void**)&ql, g_ql);
    cudaGetSymbolAddress((void**)&kh, g_kh);
    cudaGetSymbolAddress((void**)&kl, g_kl);
    cudaGetSymbolAddress((void**)&vth, g_vth);
    cudaGetSymbolAddress((void**)&vtl, g_vtl);

    cudaFuncSetAttribute(gemm_kernel_mma, cudaFuncAttributeMaxDynamicSharedMemorySize, SMEM_DYN);
    cudaFuncSetAttribute(flash_mma_kernel, cudaFuncAttributeMaxDynamicSharedMemorySize, FSMEM);

    // #0
    rope_table_kernel<<<(TT * 32 + 255) / 256, 256>>>(gc, gs);
    // #1: split x
    {
        int n4 = MM * GK / 4;
        split_kernel<<<(n4 + 255) / 256, 256>>>((const float4*)x, (uint2*)xh, (uint2*)xl, n4);
    }
    // #2: all weight transposes
    transpose_split_all<<<dim3(128, GK / 32), dim3(32, 8)>>>(Wq, Wkv, Wc, wh, wl, wch, wcl);

    // #3: fused QKV GEMM (ncu target)
    gemm_kernel_mma<<<dim3(3 * CC / 128, MM / 128), 128, SMEM_DYN>>>(
        xh, xl, wh, wl, nullptr, 3 * CC, 1, gc, gs, qh, ql, kh, kl, vth, vtl);

    // #4: attention
    flash_mma_kernel<<<dim3(TT / 128, HH, BB), 256, FSMEM>>>(qh, ql, kh, kl, vth, vtl, yh, yl);

    // #5: out = y @ Wc
    gemm_kernel_mma<<<dim3(CC / 128, MM / 128), 128, SMEM_DYN>>>(
        yh, yl, wch, wcl, out, CC, 0, nullptr, nullptr,
        nullptr, nullptr, nullptr, nullptr, nullptr, nullptr);
}

// round 9
// speedup vs baseline: 4.1393x; 1.1563x over previous
#include <cuda_runtime.h>
#include <cuda_bf16.h>
#include <math.h>
#include <stdint.h>

#define BB 4
#define TT 2048
#define HH 16
#define DD 64
#define CC (HH*DD)      // 1024
#define MM (BB*TT)      // 8192
#define GK 1024         // K of all GEMMs

// ---------------- scratch (device globals; no allocation allowed) ----------
__device__ __align__(256) float g_cos[TT * 32];
__device__ __align__(256) float g_sin[TT * 32];

__device__ __align__(256) __nv_bfloat16 g_xh[(size_t)MM * GK];
__device__ __align__(256) __nv_bfloat16 g_xl[(size_t)MM * GK];
__device__ __align__(256) __nv_bfloat16 g_yh[(size_t)MM * GK];
__device__ __align__(256) __nv_bfloat16 g_yl[(size_t)MM * GK];
__device__ __align__(256) __nv_bfloat16 g_qh[(size_t)BB*HH*TT*DD];
__device__ __align__(256) __nv_bfloat16 g_ql[(size_t)BB*HH*TT*DD];
__device__ __align__(256) __nv_bfloat16 g_kh[(size_t)BB*HH*TT*DD];
__device__ __align__(256) __nv_bfloat16 g_kl[(size_t)BB*HH*TT*DD];
__device__ __align__(256) __nv_bfloat16 g_vth[(size_t)BB*HH*TT*DD];
__device__ __align__(256) __nv_bfloat16 g_vtl[(size_t)BB*HH*TT*DD];
__device__ __align__(256) __nv_bfloat16 g_wh[(size_t)3 * CC * GK];
__device__ __align__(256) __nv_bfloat16 g_wl[(size_t)3 * CC * GK];
__device__ __align__(256) __nv_bfloat16 g_wch[(size_t)CC * GK];
__device__ __align__(256) __nv_bfloat16 g_wcl[(size_t)CC * GK];

// ---------------- helpers ----------------------------------------------------
__device__ __forceinline__ uint32_t smem_u32(const void* p) {
    return (uint32_t)__cvta_generic_to_shared(p);
}

__device__ __forceinline__ void cp_async16(uint32_t saddr, const void* gaddr) {
    asm volatile("cp.async.cg.shared.global [%0], [%1], 16;" :: "r"(saddr), "l"(gaddr) : "memory");
}

__device__ __forceinline__ void ldsm_x4(uint32_t& r0, uint32_t& r1, uint32_t& r2, uint32_t& r3,
                                        uint32_t addr) {
    asm volatile("ldmatrix.sync.aligned.m8n8.x4.shared.b16 {%0,%1,%2,%3}, [%4];"
                 : "=r"(r0), "=r"(r1), "=r"(r2), "=r"(r3) : "r"(addr));
}

__device__ __forceinline__ void mma16816(float& c0, float& c1, float& c2, float& c3,
                                         uint32_t a0, uint32_t a1, uint32_t a2, uint32_t a3,
                                         uint32_t b0, uint32_t b1) {
    asm volatile(
        "mma.sync.aligned.m16n8k16.row.col.f32.bf16.bf16.f32 "
        "{%0,%1,%2,%3}, {%4,%5,%6,%7}, {%8,%9}, {%0,%1,%2,%3};"
        : "+f"(c0), "+f"(c1), "+f"(c2), "+f"(c3)
        : "r"(a0), "r"(a1), "r"(a2), "r"(a3), "r"(b0), "r"(b1));
}

__device__ __forceinline__ uint32_t pack_bf16(float a, float b) {
    __nv_bfloat162 t = __float22bfloat162_rn(make_float2(a, b));
    return *reinterpret_cast<uint32_t*>(&t);
}

__device__ __forceinline__ void store_hl(__nv_bfloat16* hi, __nv_bfloat16* lo,
                                         size_t off, float a, float b) {
    __nv_bfloat162 h = __float22bfloat162_rn(make_float2(a, b));
    float ra = a - __bfloat162float(h.x);
    float rb = b - __bfloat162float(h.y);
    __nv_bfloat162 l = __float22bfloat162_rn(make_float2(ra, rb));
    *reinterpret_cast<__nv_bfloat162*>(hi + off) = h;
    *reinterpret_cast<__nv_bfloat162*>(lo + off) = l;
}

// ---------------- HMMA GEMM: C = (Ah+Al) @ (Bh+Bl)^T -----------------------
// 128x128 CTA tile, 8 warps (2m x 4n), warp tile 64x32, 3-stage cp.async
// pipeline with ONE barrier per k-chunk, XOR-swizzled 64B rows, 2 CTAs/SM.
#define BK 32
#define NUMK (GK / BK)          // 32
#define ROWB 64                 // 64B data, swizzled (no pad)
#define TILE_B (128 * ROWB)     // 8192
#define STAGE_B (4 * TILE_B)    // 32768
#define SMEM_DYN (3 * STAGE_B)  // 98304 -> 2 CTAs/SM

__global__ void __launch_bounds__(256, 2)
gemm_kernel_mma(const __nv_bfloat16* __restrict__ Ah, const __nv_bfloat16* __restrict__ Al,
                const __nv_bfloat16* __restrict__ Bh, const __nv_bfloat16* __restrict__ Bl,
                float* __restrict__ Cm, int Ndim, int mode,
                const float* __restrict__ gcos, const float* __restrict__ gsin,
                __nv_bfloat16* __restrict__ qh, __nv_bfloat16* __restrict__ ql,
                __nv_bfloat16* __restrict__ kh, __nv_bfloat16* __restrict__ kl,
                __nv_bfloat16* __restrict__ vth, __nv_bfloat16* __restrict__ vtl)
{
    extern __shared__ char smem_raw[];
    const uint32_t sbase = smem_u32(smem_raw);

    const int tid  = threadIdx.x;
    const int lane = tid & 31;
    const int warp = tid >> 5;
    const int mw   = warp & 1;        // 2 m-halves
    const int nw   = warp >> 1;       // 4 n-quarters
    const int m0 = blockIdx.y * 128;
    const int n0 = blockIdx.x * 128;

    const __nv_bfloat16* tp[4] = { Ah, Al, Bh, Bl };

    // swizzle: chunk' = chunk ^ ((row>>1)&3); conflict-free ldsm + stores
    auto prefetch = [&](int kc) {
        const uint32_t sstage = sbase + (uint32_t)(kc % 3) * STAGE_B;
        #pragma unroll
        for (int i = 0; i < 8; i++) {
            const int c = i * 256 + tid;
            const int tile = c >> 9;
            const int r = (c >> 2) & 127;
            const int j = c & 3;
            const int row0 = (tile < 2) ? m0 : n0;
            const __nv_bfloat16* g = tp[tile] + (size_t)(row0 + r) * GK + kc * BK + j * 8;
            cp_async16(sstage + tile * TILE_B + r * ROWB + ((j ^ ((r >> 1) & 3)) << 4), g);
        }
    };

    prefetch(0);
    asm volatile("cp.async.commit_group;" ::: "memory");
    prefetch(1);
    asm volatile("cp.async.commit_group;" ::: "memory");

    const uint32_t aRowBase = (uint32_t)((mw * 64 + (lane & 15)) * ROWB);
    const uint32_t xa = ((lane & 15) >> 1) & 3;
    const uint32_t bRowBase = (uint32_t)((nw * 32 + (lane & 7) + ((lane >> 4) << 3)) * ROWB);
    const uint32_t xb = ((lane & 7) >> 1) & 3;
    const uint32_t aHalf = (lane >> 4);        // chunk half for A
    const uint32_t bHalf = ((lane >> 3) & 1);  // chunk half for B

    float acc[4][4][4];
    #pragma unroll
    for (int mt = 0; mt < 4; mt++)
        #pragma unroll
        for (int nt = 0; nt < 4; nt++)
            #pragma unroll
            for (int e = 0; e < 4; e++) acc[mt][nt][e] = 0.f;

    for (int kc = 0; kc < NUMK; kc++) {
        asm volatile("cp.async.wait_group 1;" ::: "memory");
        __syncthreads();   // single barrier per iter (3-stage overwrite safety)

        const uint32_t sstage = sbase + (uint32_t)(kc % 3) * STAGE_B;
        const uint32_t aTile = sstage;
        const uint32_t bTile = sstage + 2 * TILE_B;

        #pragma unroll
        for (int ks = 0; ks < 2; ks++) {
            const uint32_t aOff = ((uint32_t)(ks * 2 + aHalf) ^ xa) << 4;
            const uint32_t bOff = ((uint32_t)(ks * 2 + bHalf) ^ xb) << 4;
            uint32_t bh[4][2], bl[4][2];
            #pragma unroll
            for (int np = 0; np < 2; np++) {
                const uint32_t off = bRowBase + np * (16 * ROWB) + bOff;
                ldsm_x4(bh[np*2][0], bh[np*2][1], bh[np*2+1][0], bh[np*2+1][1], bTile + off);
                ldsm_x4(bl[np*2][0], bl[np*2][1], bl[np*2+1][0], bl[np*2+1][1],
                        bTile + TILE_B + off);
            }
            #pragma unroll
            for (int mt = 0; mt < 4; mt++) {
                uint32_t ah[4], al[4];
                const uint32_t off = aRowBase + mt * (16 * ROWB) + aOff;
                ldsm_x4(ah[0], ah[1], ah[2], ah[3], aTile + off);
                ldsm_x4(al[0], al[1], al[2], al[3], aTile + TILE_B + off);
                #pragma unroll
                for (int nt = 0; nt < 4; nt++) {
                    float* c = acc[mt][nt];
                    mma16816(c[0], c[1], c[2], c[3],
                             ah[0], ah[1], ah[2], ah[3], bh[nt][0], bh[nt][1]);
                    mma16816(c[0], c[1], c[2], c[3],
                             ah[0], ah[1], ah[2], ah[3], bl[nt][0], bl[nt][1]);
                    mma16816(c[0], c[1], c[2], c[3],
                             al[0], al[1], al[2], al[3], bh[nt][0], bh[nt][1]);
                }
            }
        }
        // prefetch after compute; writes stage (kc+2)%3, readers are on kc%3
        if (kc + 2 < NUMK) prefetch(kc + 2);
        asm volatile("cp.async.commit_group;" ::: "memory");
    }

    if (mode == 0) {
        const int rbase = m0 + mw * 64 + (lane >> 2);
        const int cbase = n0 + nw * 32 + ((lane & 3) << 1);
        #pragma unroll
        for (int mt = 0; mt < 4; mt++) {
            #pragma unroll
            for (int nt = 0; nt < 4; nt++) {
                float* c = acc[mt][nt];
                float* p0 = Cm + (size_t)(rbase + mt * 16) * Ndim + cbase + nt * 8;
                float* p1 = p0 + (size_t)8 * Ndim;
                *reinterpret_cast<float2*>(p0) = make_float2(c[0], c[1]);
                *reinterpret_cast<float2*>(p1) = make_float2(c[2], c[3]);
            }
        }
        return;
    }

    // ---- fused QKV epilogue: stage fp32 tile in smem [128][132] ----
    float* sm = reinterpret_cast<float*>(smem_raw);
    __syncthreads();
    const int rloc = mw * 64 + (lane >> 2);
    const int cloc = nw * 32 + ((lane & 3) << 1);
    #pragma unroll
    for (int mt = 0; mt < 4; mt++) {
        #pragma unroll
        for (int nt = 0; nt < 4; nt++) {
            float* c = acc[mt][nt];
            float* p0 = sm + (size_t)(rloc + mt * 16) * 132 + cloc + nt * 8;
            *reinterpret_cast<float2*>(p0)           = make_float2(c[0], c[1]);
            *reinterpret_cast<float2*>(p0 + 8 * 132) = make_float2(c[2], c[3]);
        }
    }
    __syncthreads();

    const int ct = blockIdx.x;
    const int b = m0 >> 11;
    const int t_base = m0 & (TT - 1);

    if (ct < 16) {
        const bool isQ = (ct < 8);
        const float qs = isQ ? 0.125f : 1.0f;
        __nv_bfloat16* dh = isQ ? qh : kh;
        __nv_bfloat16* dl = isQ ? ql : kl;
        const int hbase = (isQ ? ct : (ct - 8)) * 2;
        #pragma unroll
        for (int i = 0; i < 16; i++) {
            const int idx = i * 256 + tid;
            const int dp = (idx & 15) * 2;
            const int hs = (idx >> 4) & 1;
            const int r  = idx >> 5;
            const int t  = t_base + r;
            const float c0 = gcos[t * 32 + dp],  c1 = gcos[t * 32 + dp + 1];
            const float s0 = gsin[t * 32 + dp],  s1 = gsin[t * 32 + dp + 1];
            const float* row = sm + (size_t)r * 132 + hs * 64;
            const float x1 = row[dp],      x1b = row[dp + 1];
            const float x2 = row[dp + 32], x2b = row[dp + 33];
            const float o0 = (x1 * c0 - x2 * s0) * qs;
            const float o1 = (x1b * c1 - x2b * s1) * qs;
            const float o2 = (x2 * c0 + x1 * s0) * qs;
            const float o3 = (x2b * c1 + x1b * s1) * qs;
            const size_t base = (((size_t)b * HH + hbase + hs) * TT + t) * 64;
            store_hl(dh, dl, base + dp, o0, o1);
            store_hl(dh, dl, base + dp + 32, o2, o3);
        }
    } else {
        const int hbase = (ct - 16) * 2;
        #pragma unroll
        for (int i = 0; i < 32; i++) {
            const int idx = i * 256 + tid;
            const int c  = idx >> 6;
            const int t2 = idx & 63;
            const int hs = c >> 6;
            const int d  = c & 63;
            const float a  = sm[(size_t)(2 * t2) * 132 + c];
            const float bv = sm[(size_t)(2 * t2 + 1) * 132 + c];
            const int t = t_base + 2 * t2;
            store_hl(vth, vtl,
                     (((size_t)b * HH + hbase + hs) * 64 + d) * TT + t, a, bv);
        }
    }
}

// ---------------- fp32 -> bf16 hi/lo split ---------------------------------
__global__ void split_kernel(const float4* __restrict__ in,
                             uint2* __restrict__ hi, uint2* __restrict__ lo, int n4)
{
    int i = blockIdx.x * blockDim.x + threadIdx.x;
    if (i >= n4) return;
    float4 v = in[i];
    float vv[4] = { v.x, v.y, v.z, v.w };
    unsigned short h[4], l[4];
    #pragma unroll
    for (int k = 0; k < 4; k++) {
        __nv_bfloat16 hb = __float2bfloat16(vv[k]);
        __nv_bfloat16 lb = __float2bfloat16(vv[k] - __bfloat162float(hb));
        h[k] = __bfloat16_as_ushort(hb);
        l[k] = __bfloat16_as_ushort(lb);
    }
    uint2 ho, lo_;
    ho.x = (uint32_t)h[0] | ((uint32_t)h[1] << 16);
    ho.y = (uint32_t)h[2] | ((uint32_t)h[3] << 16);
    lo_.x = (uint32_t)l[0] | ((uint32_t)l[1] << 16);
    lo_.y = (uint32_t)l[2] | ((uint32_t)l[3] << 16);
    hi[i] = ho;
    lo[i] = lo_;
}

// -------- combined W transpose-split + RoPE table, ONE launch --------------
// grid (128, 33): y<32 -> weight transpose tiles; y==32 -> rope table slice.
__global__ void transpose_split_all(const float* __restrict__ Wq,
                                    const float* __restrict__ Wkv,
                                    const float* __restrict__ Wc,
                                    __nv_bfloat16* __restrict__ wh,
                                    __nv_bfloat16* __restrict__ wl,
                                    __nv_bfloat16* __restrict__ wch,
                                    __nv_bfloat16* __restrict__ wcl,
                                    float* __restrict__ gcos, float* __restrict__ gsin)
{
    const int tx = threadIdx.x, ty = threadIdx.y;   // 32 x 8
    if (blockIdx.y == 32) {
        // rope table: 128 blocks x 512 entries = 65536 = TT*32
        const int tid = ty * 32 + tx;
        #pragma unroll
        for (int e = 0; e < 2; e++) {
            int i = blockIdx.x * 512 + e * 256 + tid;
            int t = i >> 5;
            int d = i & 31;
            float inv = (float)exp(-((double)(2 * d) / 64.0) * log(10000.0));
            float ang = (float)t * inv;
            gcos[i] = cosf(ang);
            gsin[i] = sinf(ang);
        }
        return;
    }

    __shared__ float t[32][33];
    const int nx = blockIdx.x;
    const int k0 = blockIdx.y * 32;
    const float* W;
    __nv_bfloat16 *Th, *Tl;
    int N, n0;
    if (nx < 32)       { W = Wq;  N = CC;     n0 = nx * 32;        Th = wh;  Tl = wl; }
    else if (nx < 96)  { W = Wkv; N = 2 * CC; n0 = (nx - 32) * 32;
                         Th = wh + (size_t)CC * GK; Tl = wl + (size_t)CC * GK; }
    else               { W = Wc;  N = CC;     n0 = (nx - 96) * 32; Th = wch; Tl = wcl; }

    #pragma unroll
    for (int i = 0; i < 32; i += 8)
        t[ty + i][tx] = W[(size_t)(k0 + ty + i) * N + n0 + tx];
    __syncthreads();
    #pragma unroll
    for (int i = 0; i < 32; i += 8) {
        float v = t[tx][ty + i];
        __nv_bfloat16 hb = __float2bfloat16(v);
        size_t o = (size_t)(n0 + ty + i) * GK + k0 + tx;
        Th[o] = hb;
        Tl[o] = __float2bfloat16(v - __bfloat162float(hb));
    }
}

// ---------------- Flash attention on HMMA (bf16 hi/lo, fp32 accum) --------
// 3-stage KV pipeline, single barrier per KV tile.
#define FROWB 144
#define FQ_TILE (128 * FROWB)        // 18432
#define FKV_TILE (64 * FROWB)        // 9216
#define FSTAGE (4 * FKV_TILE)        // 36864
#define FSMEM (2 * FQ_TILE + 3 * FSTAGE)   // 147456

__global__ void __launch_bounds__(256, 1)
flash_mma_kernel(const __nv_bfloat16* __restrict__ qh, const __nv_bfloat16* __restrict__ ql,
                 const __nv_bfloat16* __restrict__ kh, const __nv_bfloat16* __restrict__ kl,
                 const __nv_bfloat16* __restrict__ vth, const __nv_bfloat16* __restrict__ vtl,
                 __nv_bfloat16* __restrict__ yh, __nv_bfloat16* __restrict__ yl)
{
    extern __shared__ char smem_raw[];
    const uint32_t sQ  = smem_u32(smem_raw);
    const uint32_t sKV = sQ + 2 * FQ_TILE;

    const int tid = threadIdx.x, lane = tid & 31, warp = tid >> 5;
    const int t0 = (gridDim.x - 1 - blockIdx.x) * 128;   // heavy-first
    const int h = blockIdx.y, b = blockIdx.z;
    const size_t bh = (size_t)b * HH + h;
    const int nkv = t0 / 64 + 2;

    #pragma unroll
    for (int i = 0; i < 8; i++) {
        int idx = i * 256 + tid;
        int arr = idx >> 10, r = (idx >> 3) & 127, j = idx & 7;
        const __nv_bfloat16* g = (arr ? ql : qh) + (bh * TT + t0 + r) * 64 + j * 8;
        cp_async16(sQ + arr * FQ_TILE + r * FROWB + j * 16, g);
    }
    auto pref_kv = [&](int n) {
        const uint32_t sb = sKV + (uint32_t)(n % 3) * FSTAGE;
        const int j0 = n * 64;
        #pragma unroll
        for (int i = 0; i < 8; i++) {
            int idx = i * 256 + tid;
            int arr = idx >> 9, r = (idx >> 3) & 63, j = idx & 7;
            const __nv_bfloat16* g;
            if (arr == 0)      g = kh  + (bh * TT + j0 + r) * 64 + j * 8;
            else if (arr == 1) g = kl  + (bh * TT + j0 + r) * 64 + j * 8;
            else if (arr == 2) g = vth + (bh * 64 + r) * TT + j0 + j * 8;
            else               g = vtl + (bh * 64 + r) * TT + j0 + j * 8;
            cp_async16(sb + arr * FKV_TILE + r * FROWB + j * 16, g);
        }
    };
    pref_kv(0);
    asm volatile("cp.async.commit_group;" ::: "memory");
    pref_kv(1);
    asm volatile("cp.async.commit_group;" ::: "memory");

    const int wrow = t0 + warp * 16;
    const int gr = lane >> 2;
    const int qk = (lane & 3) * 2;
    const int row0 = wrow + gr;
    const int row1 = row0 + 8;

    uint32_t qa_h[4][4], qa_l[4][4];
    float O[8][4];
    #pragma unroll
    for (int nt = 0; nt < 8; nt++)
        #pragma unroll
        for (int e = 0; e < 4; e++) O[nt][e] = 0.f;
    float mA = -1e30f, mB = -1e30f, lA = 0.f, lB = 0.f;

    const uint32_t bBaseOff = ((lane & 7) + ((lane >> 4) << 3)) * FROWB + (((lane >> 3) & 1) << 4);

    for (int n = 0; n < nkv; n++) {
        asm volatile("cp.async.wait_group 1;" ::: "memory");
        __syncthreads();   // single barrier; 3-stage overwrite safety

        if (n == 0) {
            const uint32_t qb = sQ + (warp * 16 + (lane & 15)) * FROWB + ((lane >> 4) << 4);
            #pragma unroll
            for (int ks = 0; ks < 4; ks++) {
                ldsm_x4(qa_h[ks][0], qa_h[ks][1], qa_h[ks][2], qa_h[ks][3], qb + ks * 32);
                ldsm_x4(qa_l[ks][0], qa_l[ks][1], qa_l[ks][2], qa_l[ks][3],
                        qb + FQ_TILE + ks * 32);
            }
        }

        const int j0 = n * 64;
        if (j0 <= wrow + 15) {
            const uint32_t sb = sKV + (uint32_t)(n % 3) * FSTAGE;
            float S[8][4];
            #pragma unroll
            for (int nt = 0; nt < 8; nt++)
                #pragma unroll
                for (int e = 0; e < 4; e++) S[nt][e] = 0.f;

            #pragma unroll
            for (int ks = 0; ks < 4; ks++) {
                uint32_t B0h[8], B1h[8], B0l[8], B1l[8];
                #pragma unroll
                for (int q2 = 0; q2 < 4; q2++) {
                    const uint32_t off = bBaseOff + q2 * (16 * FROWB) + ks * 32;
                    ldsm_x4(B0h[q2*2], B1h[q2*2], B0h[q2*2+1], B1h[q2*2+1], sb + off);
                    ldsm_x4(B0l[q2*2], B1l[q2*2], B0l[q2*2+1], B1l[q2*2+1],
                            sb + FKV_TILE + off);
                }
                #pragma unroll
                for (int nt = 0; nt < 8; nt++) {
                    float* c = S[nt];
                    mma16816(c[0], c[1], c[2], c[3],
                             qa_h[ks][0], qa_h[ks][1], qa_h[ks][2], qa_h[ks][3],
                             B0h[nt], B1h[nt]);
                    mma16816(c[0], c[1], c[2], c[3],
                             qa_h[ks][0], qa_h[ks][1], qa_h[ks][2], qa_h[ks][3],
                             B0l[nt], B1l[nt]);
                    mma16816(c[0], c[1], c[2], c[3],
                             qa_l[ks][0], qa_l[ks][1], qa_l[ks][2], qa_l[ks][3],
                             B0h[nt], B1h[nt]);
                }
            }

            if (j0 + 63 > wrow) {
                #pragma unroll
                for (int nt = 0; nt < 8; nt++) {
                    const int c0 = j0 + nt * 8 + qk;
                    if (c0 > row0)     S[nt][0] = -1e30f;
                    if (c0 + 1 > row0) S[nt][1] = -1e30f;
                    if (c0 > row1)     S[nt][2] = -1e30f;
                    if (c0 + 1 > row1) S[nt][3] = -1e30f;
                }
            }

            float tmA = -1e30f, tmB = -1e30f;
            #pragma unroll
            for (int nt = 0; nt < 8; nt++) {
                tmA = fmaxf(tmA, fmaxf(S[nt][0], S[nt][1]));
                tmB = fmaxf(tmB, fmaxf(S[nt][2], S[nt][3]));
            }
            tmA = fmaxf(tmA, __shfl_xor_sync(0xffffffffu, tmA, 1));
            tmA = fmaxf(tmA, __shfl_xor_sync(0xffffffffu, tmA, 2));
            tmB = fmaxf(tmB, __shfl_xor_sync(0xffffffffu, tmB, 1));
            tmB = fmaxf(tmB, __shfl_xor_sync(0xffffffffu, tmB, 2));
            const float mnA = fmaxf(mA, tmA), mnB = fmaxf(mB, tmB);
            const float aA = __expf(mA - mnA), aB = __expf(mB - mnB);
            float sumA = 0.f, sumB = 0.f;
            #pragma unroll
            for (int nt = 0; nt < 8; nt++) {
                S[nt][0] = __expf(S[nt][0] - mnA);
                S[nt][1] = __expf(S[nt][1] - mnA);
                S[nt][2] = __expf(S[nt][2] - mnB);
                S[nt][3] = __expf(S[nt][3] - mnB);
                sumA += S[nt][0] + S[nt][1];
                sumB += S[nt][2] + S[nt][3];
            }
            sumA += __shfl_xor_sync(0xffffffffu, sumA, 1);
            sumA += __shfl_xor_sync(0xffffffffu, sumA, 2);
            sumB += __shfl_xor_sync(0xffffffffu, sumB, 1);
            sumB += __shfl_xor_sync(0xffffffffu, sumB, 2);
            lA = lA * aA + sumA;
            lB = lB * aB + sumB;
            mA = mnA; mB = mnB;
            #pragma unroll
            for (int nt = 0; nt < 8; nt++) {
                O[nt][0] *= aA; O[nt][1] *= aA;
                O[nt][2] *= aB; O[nt][3] *= aB;
            }

            const uint32_t vb = sb + 2 * FKV_TILE;
            #pragma unroll
            for (int ks = 0; ks < 4; ks++) {
                const int n0t = 2 * ks, n1t = 2 * ks + 1;
                uint32_t pah[4], pal[4];
                {
                    __nv_bfloat162 h0 = __float22bfloat162_rn(make_float2(S[n0t][0], S[n0t][1]));
                    __nv_bfloat162 h1 = __float22bfloat162_rn(make_float2(S[n0t][2], S[n0t][3]));
                    __nv_bfloat162 h2 = __float22bfloat162_rn(make_float2(S[n1t][0], S[n1t][1]));
                    __nv_bfloat162 h3 = __float22bfloat162_rn(make_float2(S[n1t][2], S[n1t][3]));
                    pah[0] = *reinterpret_cast<uint32_t*>(&h0);
                    pah[1] = *reinterpret_cast<uint32_t*>(&h1);
                    pah[2] = *reinterpret_cast<uint32_t*>(&h2);
                    pah[3] = *reinterpret_cast<uint32_t*>(&h3);
                    pal[0] = pack_bf16(S[n0t][0] - __bfloat162float(h0.x),
                                       S[n0t][1] - __bfloat162float(h0.y));
                    pal[1] = pack_bf16(S[n0t][2] - __bfloat162float(h1.x),
                                       S[n0t][3] - __bfloat162float(h1.y));
                    pal[2] = pack_bf16(S[n1t][0] - __bfloat162float(h2.x),
                                       S[n1t][1] - __bfloat162float(h2.y));
                    pal[3] = pack_bf16(S[n1t][2] - __bfloat162float(h3.x),
                                       S[n1t][3] - __bfloat162float(h3.y));
                }
                uint32_t V0h[8], V1h[8], V0l[8], V1l[8];
                #pragma unroll
                for (int q2 = 0; q2 < 4; q2++) {
                    const uint32_t off = bBaseOff + q2 * (16 * FROWB) + ks * 32;
                    ldsm_x4(V0h[q2*2], V1h[q2*2], V0h[q2*2+1], V1h[q2*2+1], vb + off);
                    ldsm_x4(V0l[q2*2], V1l[q2*2], V0l[q2*2+1], V1l[q2*2+1],
                            vb + FKV_TILE + off);
                }
                #pragma unroll
                for (int nt = 0; nt < 8; nt++) {
                    float* c = O[nt];
                    mma16816(c[0], c[1], c[2], c[3],
                             pah[0], pah[1], pah[2], pah[3], V0h[nt], V1h[nt]);
                    mma16816(c[0], c[1], c[2], c[3],
                             pah[0], pah[1], pah[2], pah[3], V0l[nt], V1l[nt]);
                    mma16816(c[0], c[1], c[2], c[3],
                             pal[0], pal[1], pal[2], pal[3], V0h[nt], V1h[nt]);
                }
            }
        }
        if (n + 2 < nkv) pref_kv(n + 2);
        asm volatile("cp.async.commit_group;" ::: "memory");
    }

    const float iA = 1.f / lA, iB = 1.f / lB;
    #pragma unroll
    for (int nt = 0; nt < 8; nt++) {
        const size_t d0 = (size_t)h * 64 + nt * 8 + qk;
        store_hl(yh, yl, ((size_t)b * TT + row0) * CC + d0, O[nt][0] * iA, O[nt][1] * iA);
        store_hl(yh, yl, ((size_t)b * TT + row1) * CC + d0, O[nt][2] * iB, O[nt][3] * iB);
    }
}

// ---------------- launch ---------------------------------------------------
extern "C" void kernel_launch(void* const* d_in, const int* in_sizes, int n_in,
                              void* d_out, int out_size)
{
    const float* x   = (const float*)d_in[0];
    const float* Wq  = (const float*)d_in[1];
    const float* Wkv = (const float*)d_in[2];
    const float* Wc  = (const float*)d_in[3];
    float* out = (float*)d_out;

    float *gc, *gs;
    __nv_bfloat16 *xh, *xl, *yh, *yl, *wh, *wl, *wch, *wcl;
    __nv_bfloat16 *qh, *ql, *kh, *kl, *vth, *vtl;
    cudaGetSymbolAddress((void**)&gc, g_cos);
    cudaGetSymbolAddress((void**)&gs, g_sin);
    cudaGetSymbolAddress((void**)&xh, g_xh);
    cudaGetSymbolAddress((void**)&xl, g_xl);
    cudaGetSymbolAddress((void**)&yh, g_yh);
    cudaGetSymbolAddress((void**)&yl, g_yl);
    cudaGetSymbolAddress((void**)&wh, g_wh);
    cudaGetSymbolAddress((void**)&wl, g_wl);
    cudaGetSymbolAddress((void**)&wch, g_wch);
    cudaGetSymbolAddress((void**)&wcl, g_wcl);
    cudaGetSymbolAddress((void**)&qh, g_qh);
    cudaGetSymbolAddress((void**)&ql, g_ql);
    cudaGetSymbolAddress((void**)&kh, g_kh);
    cudaGetSymbolAddress((void**)&kl, g_kl);
    cudaGetSymbolAddress((void**)&vth, g_vth);
    cudaGetSymbolAddress((void**)&vtl, g_vtl);

    cudaFuncSetAttribute(gemm_kernel_mma, cudaFuncAttributeMaxDynamicSharedMemorySize, SMEM_DYN);
    cudaFuncSetAttribute(flash_mma_kernel, cudaFuncAttributeMaxDynamicSharedMemorySize, FSMEM);

    // #0: split x
    {
        int n4 = MM * GK / 4;
        split_kernel<<<(n4 + 255) / 256, 256>>>((const float4*)x, (uint2*)xh, (uint2*)xl, n4);
    }
    // #1: all weight transposes + rope table
    transpose_split_all<<<dim3(128, GK / 32 + 1), dim3(32, 8)>>>(
        Wq, Wkv, Wc, wh, wl, wch, wcl, gc, gs);

    // #2: fused QKV GEMM
    gemm_kernel_mma<<<dim3(3 * CC / 128, MM / 128), 256, SMEM_DYN>>>(
        xh, xl, wh, wl, nullptr, 3 * CC, 1, gc, gs, qh, ql, kh, kl, vth, vtl);

    // #3: attention (ncu target)
    flash_mma_kernel<<<dim3(TT / 128, HH, BB), 256, FSMEM>>>(qh, ql, kh, kl, vth, vtl, yh, yl);

    // #4: out = y @ Wc
    gemm_kernel_mma<<<dim3(CC / 128, MM / 128), 256, SMEM_DYN>>>(
        yh, yl, wch, wcl, out, CC, 0, nullptr, nullptr,
        nullptr, nullptr, nullptr, nullptr, nullptr, nullptr);
}